// round 3
// baseline (speedup 1.0000x reference)
#include <cuda_runtime.h>
#include <math.h>
#include <stdint.h>

#define BSZ 128
#define TT  512
#define HH  256
#define GG  768
#define VOC 29
#define EMBD 8
#define DECS 63
#define HALFK 128
#define LOGITS_SZ (BSZ*DECS*VOC)

// ---------------- device scratch ----------------
__device__ float  g_y0 [(size_t)BSZ*TT*2*HH];
__device__ float  g_y1 [(size_t)BSZ*TT*2*HH];
__device__ float  g_gi1[(size_t)2*BSZ*TT*GG];
__device__ float  g_enc[(size_t)BSZ*TT*HH];
__device__ float  g_h0 [2*BSZ*HH];
__device__ float  g_h1 [2*BSZ*HH];
__device__ float2 g_WhhP0 [2*HALFK*GG];
__device__ float2 g_WhhP1 [2*HALFK*GG];
__device__ float2 g_dWhhP [2*HALFK*GG];
__device__ float2 g_dWih1P[HALFK*GG];
__device__ float2 g_qWP   [HALFK*HH];
__device__ float  g_dWih0T[EMBD*GG];

__device__ __forceinline__ float sigf(float v){ return 1.0f/(1.0f+expf(-v)); }

// ---------------- weight packing ----------------
__global__ void prep_kernel(const float* __restrict__ eWhh0, const float* __restrict__ eWhh1,
                            const float* __restrict__ dWhh,  const float* __restrict__ dWih1,
                            const float* __restrict__ qW,    const float* __restrict__ dWih0)
{
    const int N0 = 2*HALFK*GG;           // 196608
    const int N1 = HALFK*GG;             // 98304
    const int N2 = HALFK*HH;             // 32768
    const int N3 = EMBD*GG;              // 6144
    const int TOT = N0*3 + N1 + N2 + N3;
    for (int i = blockIdx.x*blockDim.x + threadIdx.x; i < TOT; i += gridDim.x*blockDim.x){
        int idx = i;
        if (idx < N0){
            int d = idx / N1, q = idx % N1;
            int r = q % GG, kk = q / GG;
            const float* s = eWhh0 + (size_t)(d*GG + r)*HH;
            g_WhhP0[idx] = make_float2(s[2*kk], s[2*kk+1]);
            continue;
        }
        idx -= N0;
        if (idx < N0){
            int d = idx / N1, q = idx % N1;
            int r = q % GG, kk = q / GG;
            const float* s = eWhh1 + (size_t)(d*GG + r)*HH;
            g_WhhP1[idx] = make_float2(s[2*kk], s[2*kk+1]);
            continue;
        }
        idx -= N0;
        if (idx < N0){
            int d = idx / N1, q = idx % N1;
            int r = q % GG, kk = q / GG;
            const float* s = dWhh + (size_t)(d*GG + r)*HH;
            g_dWhhP[idx] = make_float2(s[2*kk], s[2*kk+1]);
            continue;
        }
        idx -= N0;
        if (idx < N1){
            int r = idx % GG, kk = idx / GG;
            const float* s = dWih1 + (size_t)r*HH;
            g_dWih1P[idx] = make_float2(s[2*kk], s[2*kk+1]);
            continue;
        }
        idx -= N1;
        if (idx < N2){
            int o = idx % HH, kk = idx / HH;
            const float* s = qW + (size_t)o*HH;
            g_qWP[idx] = make_float2(s[2*kk], s[2*kk+1]);
            continue;
        }
        idx -= N2;
        {
            int j3 = idx % GG, k = idx / GG;
            g_dWih0T[idx] = dWih0[(size_t)j3*EMBD + k];
        }
    }
}

// ---------------- encoder layer 0 ----------------
__global__ __launch_bounds__(256) void enc0_kernel(const float* __restrict__ x,
        const float* __restrict__ Wih, const float* __restrict__ bih, const float* __restrict__ bhh)
{
    const int dir = blockIdx.x >> 5;
    const int grp = blockIdx.x & 31;
    const int j   = threadIdx.x;
    const float2* __restrict__ WP = g_WhhP0 + (size_t)dir*HALFK*GG;

    float bi[3], bh[3], wiA[3], wiB[3];
#pragma unroll
    for (int g = 0; g < 3; g++){
        int row = dir*GG + g*HH + j;
        bi[g]  = bih[row];
        bh[g]  = bhh[row];
        wiA[g] = Wih[(size_t)row*2 + 0];
        wiB[g] = Wih[(size_t)row*2 + 1];
    }

    __shared__ __align__(16) float hs[4][HH];
#pragma unroll
    for (int r = 0; r < 4; r++) hs[r][j] = 0.0f;
    __syncthreads();

    const int b0 = grp*4;
    for (int s = 0; s < TT; s++){
        const int t = dir ? (TT-1-s) : s;
        float giR[4], giZ[4], giN[4], aR[4], aZ[4], aN[4];
#pragma unroll
        for (int r = 0; r < 4; r++){
            float x0 = x[((size_t)(b0+r)*TT + t)*2 + 0];
            float x1 = x[((size_t)(b0+r)*TT + t)*2 + 1];
            giR[r] = bi[0] + wiA[0]*x0 + wiB[0]*x1;
            giZ[r] = bi[1] + wiA[1]*x0 + wiB[1]*x1;
            giN[r] = bi[2] + wiA[2]*x0 + wiB[2]*x1;
            aR[r] = bh[0]; aZ[r] = bh[1]; aN[r] = bh[2];
        }
#pragma unroll 2
        for (int kk = 0; kk < HALFK; kk++){
            float2 w0 = WP[kk*GG + j];
            float2 w1 = WP[kk*GG + HH + j];
            float2 w2 = WP[kk*GG + 2*HH + j];
#pragma unroll
            for (int r = 0; r < 4; r++){
                float2 h2 = *(const float2*)&hs[r][2*kk];
                aR[r] += w0.x*h2.x + w0.y*h2.y;
                aZ[r] += w1.x*h2.x + w1.y*h2.y;
                aN[r] += w2.x*h2.x + w2.y*h2.y;
            }
        }
        float hn[4];
#pragma unroll
        for (int r = 0; r < 4; r++){
            float hold = hs[r][j];
            float rg = sigf(giR[r] + aR[r]);
            float zg = sigf(giZ[r] + aZ[r]);
            float ng = tanhf(giN[r] + rg*aN[r]);
            hn[r] = (1.0f - zg)*ng + zg*hold;
        }
        __syncthreads();
#pragma unroll
        for (int r = 0; r < 4; r++){
            hs[r][j] = hn[r];
            g_y0[((size_t)(b0+r)*TT + t)*(2*HH) + dir*HH + j] = hn[r];
        }
        __syncthreads();
    }
#pragma unroll
    for (int r = 0; r < 4; r++) g_h0[dir*BSZ*HH + (b0+r)*HH + j] = hs[r][j];
}

// ---------------- encoder layer 1 (gi precomputed) ----------------
__global__ __launch_bounds__(256) void enc1_kernel(const float* __restrict__ bhh)
{
    const int dir = blockIdx.x >> 5;
    const int grp = blockIdx.x & 31;
    const int j   = threadIdx.x;
    const float2* __restrict__ WP = g_WhhP1 + (size_t)dir*HALFK*GG;
    const float*  __restrict__ GI = g_gi1  + (size_t)dir*BSZ*TT*GG;

    float bh[3];
#pragma unroll
    for (int g = 0; g < 3; g++) bh[g] = bhh[dir*GG + g*HH + j];

    __shared__ __align__(16) float hs[4][HH];
#pragma unroll
    for (int r = 0; r < 4; r++) hs[r][j] = 0.0f;
    __syncthreads();

    const int b0 = grp*4;
    for (int s = 0; s < TT; s++){
        const int t = dir ? (TT-1-s) : s;
        float giR[4], giZ[4], giN[4], aR[4], aZ[4], aN[4];
#pragma unroll
        for (int r = 0; r < 4; r++){
            const float* gp = GI + ((size_t)(b0+r)*TT + t)*GG;
            giR[r] = gp[j];
            giZ[r] = gp[HH + j];
            giN[r] = gp[2*HH + j];
            aR[r] = bh[0]; aZ[r] = bh[1]; aN[r] = bh[2];
        }
#pragma unroll 2
        for (int kk = 0; kk < HALFK; kk++){
            float2 w0 = WP[kk*GG + j];
            float2 w1 = WP[kk*GG + HH + j];
            float2 w2 = WP[kk*GG + 2*HH + j];
#pragma unroll
            for (int r = 0; r < 4; r++){
                float2 h2 = *(const float2*)&hs[r][2*kk];
                aR[r] += w0.x*h2.x + w0.y*h2.y;
                aZ[r] += w1.x*h2.x + w1.y*h2.y;
                aN[r] += w2.x*h2.x + w2.y*h2.y;
            }
        }
        float hn[4];
#pragma unroll
        for (int r = 0; r < 4; r++){
            float hold = hs[r][j];
            float rg = sigf(giR[r] + aR[r]);
            float zg = sigf(giZ[r] + aZ[r]);
            float ng = tanhf(giN[r] + rg*aN[r]);
            hn[r] = (1.0f - zg)*ng + zg*hold;
        }
        __syncthreads();
#pragma unroll
        for (int r = 0; r < 4; r++){
            hs[r][j] = hn[r];
            g_y1[((size_t)(b0+r)*TT + t)*(2*HH) + dir*HH + j] = hn[r];
        }
        __syncthreads();
    }
#pragma unroll
    for (int r = 0; r < 4; r++) g_h1[dir*BSZ*HH + (b0+r)*HH + j] = hs[r][j];
}

// ---------------- tiled SGEMM: C[m][n] = sum_k A[m][k]*B[n][k] + bias[n] ----------------
#define GBM 128
#define GBN 64
#define GBK 16
__global__ __launch_bounds__(256) void gemm_bt(const float* __restrict__ A, const float* __restrict__ Bm,
        const float* __restrict__ bias, float* __restrict__ C, int M, int N, int K)
{
    __shared__ float As[GBK][GBM];
    __shared__ float Bs[GBK][GBN];
    const int bm  = blockIdx.x * GBM;
    const int bn  = blockIdx.y * GBN;
    const int tid = threadIdx.x;
    const int tx  = tid & 15;
    const int ty  = tid >> 4;
    float acc[8][4];
#pragma unroll
    for (int i = 0; i < 8; i++)
#pragma unroll
        for (int jx = 0; jx < 4; jx++) acc[i][jx] = 0.0f;

    for (int k0 = 0; k0 < K; k0 += GBK){
#pragma unroll
        for (int i = 0; i < 2; i++){
            int lin = tid + i*256;
            int ar = lin >> 2, ac = (lin & 3)*4;
            float4 v = *(const float4*)&A[(size_t)(bm+ar)*K + k0 + ac];
            As[ac+0][ar] = v.x; As[ac+1][ar] = v.y; As[ac+2][ar] = v.z; As[ac+3][ar] = v.w;
        }
        {
            int br = tid >> 2, bc = (tid & 3)*4;
            float4 v = *(const float4*)&Bm[(size_t)(bn+br)*K + k0 + bc];
            Bs[bc+0][br] = v.x; Bs[bc+1][br] = v.y; Bs[bc+2][br] = v.z; Bs[bc+3][br] = v.w;
        }
        __syncthreads();
#pragma unroll
        for (int k = 0; k < GBK; k++){
            float a[8], b[4];
#pragma unroll
            for (int i = 0; i < 8; i++) a[i] = As[k][ty*8 + i];
#pragma unroll
            for (int i = 0; i < 4; i++) b[i] = Bs[k][tx*4 + i];
#pragma unroll
            for (int i = 0; i < 8; i++)
#pragma unroll
                for (int jx = 0; jx < 4; jx++) acc[i][jx] += a[i]*b[jx];
        }
        __syncthreads();
    }
#pragma unroll
    for (int i = 0; i < 8; i++){
        int m = bm + ty*8 + i;
#pragma unroll
        for (int jx = 0; jx < 4; jx++){
            int n = bn + tx*4 + jx;
            C[(size_t)m*N + n] = acc[i][jx] + bias[n];
        }
    }
}

// ---------------- decoder: 64 blocks x 2 rows, 63 sequential steps ----------------
__global__ __launch_bounds__(256) void dec_kernel(
        const int*   __restrict__ tseq, const float* __restrict__ dbih, const float* __restrict__ dbhh,
        const float* __restrict__ qb,   const float* __restrict__ outb, const float* __restrict__ emb,
        const float* __restrict__ outW, float* __restrict__ out)
{
    const int j  = threadIdx.x;
    const int b0 = blockIdx.x * 2;
    const int warp = j >> 5, lane = j & 31;

    __shared__ __align__(16) float h0s[2][HH];
    __shared__ __align__(16) float h1s[2][HH];
    __shared__ float qs[2][HH];
    __shared__ float cx[2][HH];
    __shared__ float ws[2][TT];
    __shared__ float es[2][EMBD];
    __shared__ float ls[2][32];
    __shared__ float buf[256];
    __shared__ float mred[2], invs[2];
    __shared__ int   toks[2];

#pragma unroll
    for (int r = 0; r < 2; r++){
        h0s[r][j] = g_h0[(b0+r)*HH + j] + g_h0[BSZ*HH + (b0+r)*HH + j];
        h1s[r][j] = g_h1[(b0+r)*HH + j] + g_h1[BSZ*HH + (b0+r)*HH + j];
    }
    if (j < 2) toks[j] = tseq[(size_t)(b0+j)*64];
    __syncthreads();

    float bi0[3], bh0[3], bi1[3], bh1[3];
#pragma unroll
    for (int g = 0; g < 3; g++){
        bi0[g] = dbih[g*HH + j];        bh0[g] = dbhh[g*HH + j];
        bi1[g] = dbih[GG + g*HH + j];   bh1[g] = dbhh[GG + g*HH + j];
    }
    const float qbias = qb[j];

    for (int s = 0; s < DECS; s++){
        if (j < 2*EMBD){ int r = j >> 3, k = j & 7; es[r][k] = emb[(size_t)toks[r]*EMBD + k]; }
        __syncthreads();

        // ---- GRU cell 0 ----
        float giR[2], giZ[2], giN[2], aR[2], aZ[2], aN[2];
#pragma unroll
        for (int r = 0; r < 2; r++){
            giR[r] = bi0[0]; giZ[r] = bi0[1]; giN[r] = bi0[2];
            aR[r] = bh0[0];  aZ[r] = bh0[1];  aN[r] = bh0[2];
        }
#pragma unroll
        for (int k = 0; k < EMBD; k++){
            float w0 = g_dWih0T[k*GG + j];
            float w1 = g_dWih0T[k*GG + HH + j];
            float w2 = g_dWih0T[k*GG + 2*HH + j];
#pragma unroll
            for (int r = 0; r < 2; r++){
                float e = es[r][k];
                giR[r] += w0*e; giZ[r] += w1*e; giN[r] += w2*e;
            }
        }
#pragma unroll 2
        for (int kk = 0; kk < HALFK; kk++){
            float2 w0 = g_dWhhP[kk*GG + j];
            float2 w1 = g_dWhhP[kk*GG + HH + j];
            float2 w2 = g_dWhhP[kk*GG + 2*HH + j];
#pragma unroll
            for (int r = 0; r < 2; r++){
                float2 h2 = *(const float2*)&h0s[r][2*kk];
                aR[r] += w0.x*h2.x + w0.y*h2.y;
                aZ[r] += w1.x*h2.x + w1.y*h2.y;
                aN[r] += w2.x*h2.x + w2.y*h2.y;
            }
        }
        float h0n[2];
#pragma unroll
        for (int r = 0; r < 2; r++){
            float hold = h0s[r][j];
            float rg = sigf(giR[r] + aR[r]);
            float zg = sigf(giZ[r] + aZ[r]);
            float ng = tanhf(giN[r] + rg*aN[r]);
            h0n[r] = (1.0f - zg)*ng + zg*hold;
        }
        __syncthreads();
#pragma unroll
        for (int r = 0; r < 2; r++) h0s[r][j] = h0n[r];
        __syncthreads();

        // ---- GRU cell 1 (input = h0) ----
#pragma unroll
        for (int r = 0; r < 2; r++){
            giR[r] = bi1[0]; giZ[r] = bi1[1]; giN[r] = bi1[2];
            aR[r] = bh1[0];  aZ[r] = bh1[1];  aN[r] = bh1[2];
        }
#pragma unroll 2
        for (int kk = 0; kk < HALFK; kk++){
            float2 u0 = g_dWih1P[kk*GG + j];
            float2 u1 = g_dWih1P[kk*GG + HH + j];
            float2 u2 = g_dWih1P[kk*GG + 2*HH + j];
            float2 w0 = g_dWhhP[HALFK*GG + kk*GG + j];
            float2 w1 = g_dWhhP[HALFK*GG + kk*GG + HH + j];
            float2 w2 = g_dWhhP[HALFK*GG + kk*GG + 2*HH + j];
#pragma unroll
            for (int r = 0; r < 2; r++){
                float2 x2 = *(const float2*)&h0s[r][2*kk];
                float2 h2 = *(const float2*)&h1s[r][2*kk];
                giR[r] += u0.x*x2.x + u0.y*x2.y;
                giZ[r] += u1.x*x2.x + u1.y*x2.y;
                giN[r] += u2.x*x2.x + u2.y*x2.y;
                aR[r] += w0.x*h2.x + w0.y*h2.y;
                aZ[r] += w1.x*h2.x + w1.y*h2.y;
                aN[r] += w2.x*h2.x + w2.y*h2.y;
            }
        }
        float h1n[2];
#pragma unroll
        for (int r = 0; r < 2; r++){
            float hold = h1s[r][j];
            float rg = sigf(giR[r] + aR[r]);
            float zg = sigf(giZ[r] + aZ[r]);
            float ng = tanhf(giN[r] + rg*aN[r]);
            h1n[r] = (1.0f - zg)*ng + zg*hold;
        }
        __syncthreads();
#pragma unroll
        for (int r = 0; r < 2; r++) h1s[r][j] = h1n[r];
        __syncthreads();

        // ---- q = h1 @ qW^T + qb ----
        float q0 = qbias, q1 = qbias;
#pragma unroll 2
        for (int kk = 0; kk < HALFK; kk++){
            float2 w = g_qWP[kk*HH + j];
            float2 a = *(const float2*)&h1s[0][2*kk];
            float2 b = *(const float2*)&h1s[1][2*kk];
            q0 += w.x*a.x + w.y*a.y;
            q1 += w.x*b.x + w.y*b.y;
        }
        qs[0][j] = q0; qs[1][j] = q1;
        __syncthreads();

        // ---- scores: warp per t-stripe ----
        for (int tt = warp; tt < TT/2; tt += 8){
#pragma unroll
            for (int half = 0; half < 2; half++){
                int t = tt + half*(TT/2);
#pragma unroll
                for (int r = 0; r < 2; r++){
                    const float* ep = g_enc + ((size_t)(b0+r)*TT + t)*HH + lane*8;
                    float4 e0 = *(const float4*)(ep);
                    float4 e1 = *(const float4*)(ep+4);
                    const float* qp = &qs[r][lane*8];
                    float acc = e0.x*qp[0] + e0.y*qp[1] + e0.z*qp[2] + e0.w*qp[3]
                              + e1.x*qp[4] + e1.y*qp[5] + e1.z*qp[6] + e1.w*qp[7];
#pragma unroll
                    for (int o = 16; o > 0; o >>= 1) acc += __shfl_xor_sync(0xffffffffu, acc, o);
                    if (lane == 0) ws[r][t] = acc;
                }
            }
        }
        __syncthreads();

        // ---- softmax (per row) ----
#pragma unroll
        for (int r = 0; r < 2; r++){
            buf[j] = fmaxf(ws[r][j], ws[r][j+256]);
            __syncthreads();
            for (int o = 128; o > 0; o >>= 1){
                if (j < o) buf[j] = fmaxf(buf[j], buf[j+o]);
                __syncthreads();
            }
            if (j == 0) mred[r] = buf[0];
            __syncthreads();
            float m = mred[r];
            float e0 = expf(ws[r][j] - m), e1 = expf(ws[r][j+256] - m);
            ws[r][j] = e0; ws[r][j+256] = e1;
            buf[j] = e0 + e1;
            __syncthreads();
            for (int o = 128; o > 0; o >>= 1){
                if (j < o) buf[j] += buf[j+o];
                __syncthreads();
            }
            if (j == 0) invs[r] = 1.0f/buf[0];
            __syncthreads();
        }

        // ---- ctx ----
        {
            float c0 = 0.0f, c1 = 0.0f;
            const float* e0p = g_enc + (size_t)(b0+0)*TT*HH + j;
            const float* e1p = g_enc + (size_t)(b0+1)*TT*HH + j;
            for (int t = 0; t < TT; t++){
                c0 += ws[0][t]*e0p[(size_t)t*HH];
                c1 += ws[1][t]*e1p[(size_t)t*HH];
            }
            cx[0][j] = c0*invs[0] + h1s[0][j];
            cx[1][j] = c1*invs[1] + h1s[1][j];
        }
        __syncthreads();

        // ---- logits + write ----
        for (int v = warp; v < VOC; v += 8){
            const float* wp = outW + (size_t)v*HH + lane*8;
            float4 w0 = *(const float4*)(wp);
            float4 w1 = *(const float4*)(wp+4);
#pragma unroll
            for (int r = 0; r < 2; r++){
                const float* hp = &cx[r][lane*8];
                float acc = w0.x*hp[0] + w0.y*hp[1] + w0.z*hp[2] + w0.w*hp[3]
                          + w1.x*hp[4] + w1.y*hp[5] + w1.z*hp[6] + w1.w*hp[7];
#pragma unroll
                for (int o = 16; o > 0; o >>= 1) acc += __shfl_xor_sync(0xffffffffu, acc, o);
                if (lane == 0){
                    float lv = acc + outb[v];
                    ls[r][v] = lv;
                    out[((size_t)(b0+r)*DECS + s)*VOC + v] = lv;
                }
            }
        }
        __syncthreads();

        // ---- argmax feedback ----
        if (j < 2){
            float best = ls[j][0]; int bi = 0;
#pragma unroll
            for (int v = 1; v < VOC; v++){
                float lv = ls[j][v];
                if (lv > best){ best = lv; bi = v; }
            }
            toks[j] = bi;
        }
        __syncthreads();
    }

    // ---- final hidden ----
#pragma unroll
    for (int r = 0; r < 2; r++){
        out[LOGITS_SZ + (size_t)(b0+r)*HH + j]              = h0s[r][j];
        out[LOGITS_SZ + (size_t)BSZ*HH + (size_t)(b0+r)*HH + j] = h1s[r][j];
    }
}

// ---------------- launch ----------------
extern "C" void kernel_launch(void* const* d_in, const int* in_sizes, int n_in,
                              void* d_out, int out_size)
{
    const float* x      = (const float*)d_in[0];
    const int*   tseq   = (const int*)  d_in[1];
    const float* eWih0  = (const float*)d_in[2];
    const float* eWhh0  = (const float*)d_in[3];
    const float* ebih0  = (const float*)d_in[4];
    const float* ebhh0  = (const float*)d_in[5];
    const float* eWih1  = (const float*)d_in[6];
    const float* eWhh1  = (const float*)d_in[7];
    const float* ebih1  = (const float*)d_in[8];
    const float* ebhh1  = (const float*)d_in[9];
    const float* e2d_W  = (const float*)d_in[10];
    const float* e2d_b  = (const float*)d_in[11];
    const float* dWih0  = (const float*)d_in[12];
    const float* dWih1  = (const float*)d_in[13];
    const float* dWhh   = (const float*)d_in[14];
    const float* dbih   = (const float*)d_in[15];
    const float* dbhh   = (const float*)d_in[16];
    const float* q_W    = (const float*)d_in[17];
    const float* q_b    = (const float*)d_in[18];
    const float* out_W  = (const float*)d_in[19];
    const float* out_b  = (const float*)d_in[20];
    const float* emb    = (const float*)d_in[21];
    float* out = (float*)d_out;

    prep_kernel<<<148, 256>>>(eWhh0, eWhh1, dWhh, dWih1, q_W, dWih0);
    enc0_kernel<<<64, 256>>>(x, eWih0, ebih0, ebhh0);

    float* gy0 = nullptr; cudaGetSymbolAddress((void**)&gy0, g_y0);
    float* gy1 = nullptr; cudaGetSymbolAddress((void**)&gy1, g_y1);
    float* ggi = nullptr; cudaGetSymbolAddress((void**)&ggi, g_gi1);
    float* gen = nullptr; cudaGetSymbolAddress((void**)&gen, g_enc);

    dim3 gGI(BSZ*TT/GBM, GG/GBN);
    gemm_bt<<<gGI, 256>>>(gy0, eWih1,        ebih1,      ggi,                      BSZ*TT, GG, 2*HH);
    gemm_bt<<<gGI, 256>>>(gy0, eWih1+GG*2*HH, ebih1+GG,  ggi+(size_t)BSZ*TT*GG,   BSZ*TT, GG, 2*HH);

    enc1_kernel<<<64, 256>>>(ebhh1);

    dim3 gED(BSZ*TT/GBM, HH/GBN);
    gemm_bt<<<gED, 256>>>(gy1, e2d_W, e2d_b, gen, BSZ*TT, HH, 2*HH);

    dec_kernel<<<64, 256>>>(tseq, dbih, dbhh, q_b, out_b, emb, out_W, out);
}

// round 6
// speedup vs baseline: 1.1034x; 1.1034x over previous
#include <cuda_runtime.h>
#include <math.h>
#include <stdint.h>
#include <string.h>

#define BSZ 128
#define TT  512
#define HH  256
#define GG  768
#define VOC 29
#define EMBD 8
#define DECS 63
#define HALFK 128
#define LOGITS_SZ (BSZ*DECS*VOC)

// ---------------- packed fp32 FMA (Blackwell f32x2 pipe) ----------------
__device__ __forceinline__ float2 ffma2(float2 a, float2 b, float2 c){
    unsigned long long au, bu, cu, ru;
    memcpy(&au, &a, 8); memcpy(&bu, &b, 8); memcpy(&cu, &c, 8);
    asm("fma.rn.f32x2 %0, %1, %2, %3;" : "=l"(ru) : "l"(au), "l"(bu), "l"(cu));
    float2 r; memcpy(&r, &ru, 8);
    return r;
}

// ---------------- device scratch ----------------
__device__ float  g_y0 [(size_t)BSZ*TT*2*HH];
__device__ float  g_y1 [(size_t)BSZ*TT*2*HH];
__device__ float  g_gi1[(size_t)2*BSZ*TT*GG];
__device__ float  g_enc[(size_t)BSZ*TT*HH];
__device__ float  g_h0 [2*BSZ*HH];
__device__ float  g_h1 [2*BSZ*HH];
__device__ float2 g_WhhP0 [2*HALFK*GG];
__device__ float2 g_WhhP1 [2*HALFK*GG];
__device__ float2 g_dWhhP [2*HALFK*GG];
__device__ float2 g_dWih1P[HALFK*GG];
__device__ float2 g_qWP   [HALFK*HH];
__device__ float  g_dWih0T[EMBD*GG];

__device__ __forceinline__ float sigf(float v){ return 1.0f/(1.0f+expf(-v)); }

// ---------------- weight packing ----------------
__global__ void prep_kernel(const float* __restrict__ eWhh0, const float* __restrict__ eWhh1,
                            const float* __restrict__ dWhh,  const float* __restrict__ dWih1,
                            const float* __restrict__ qW,    const float* __restrict__ dWih0)
{
    const int N0 = 2*HALFK*GG;
    const int N1 = HALFK*GG;
    const int N2 = HALFK*HH;
    const int N3 = EMBD*GG;
    const int TOT = N0*3 + N1 + N2 + N3;
    for (int i = blockIdx.x*blockDim.x + threadIdx.x; i < TOT; i += gridDim.x*blockDim.x){
        int idx = i;
        if (idx < N0){
            int d = idx / N1, q = idx % N1;
            int r = q % GG, kk = q / GG;
            const float* s = eWhh0 + (size_t)(d*GG + r)*HH;
            g_WhhP0[idx] = make_float2(s[2*kk], s[2*kk+1]);
            continue;
        }
        idx -= N0;
        if (idx < N0){
            int d = idx / N1, q = idx % N1;
            int r = q % GG, kk = q / GG;
            const float* s = eWhh1 + (size_t)(d*GG + r)*HH;
            g_WhhP1[idx] = make_float2(s[2*kk], s[2*kk+1]);
            continue;
        }
        idx -= N0;
        if (idx < N0){
            int d = idx / N1, q = idx % N1;
            int r = q % GG, kk = q / GG;
            const float* s = dWhh + (size_t)(d*GG + r)*HH;
            g_dWhhP[idx] = make_float2(s[2*kk], s[2*kk+1]);
            continue;
        }
        idx -= N0;
        if (idx < N1){
            int r = idx % GG, kk = idx / GG;
            const float* s = dWih1 + (size_t)r*HH;
            g_dWih1P[idx] = make_float2(s[2*kk], s[2*kk+1]);
            continue;
        }
        idx -= N1;
        if (idx < N2){
            int o = idx % HH, kk = idx / HH;
            const float* s = qW + (size_t)o*HH;
            g_qWP[idx] = make_float2(s[2*kk], s[2*kk+1]);
            continue;
        }
        idx -= N2;
        {
            int j3 = idx % GG, k = idx / GG;
            g_dWih0T[idx] = dWih0[(size_t)j3*EMBD + k];
        }
    }
}

// ---------------- encoder layer 0 ----------------
__global__ __launch_bounds__(256) void enc0_kernel(const float* __restrict__ x,
        const float* __restrict__ Wih, const float* __restrict__ bih, const float* __restrict__ bhh)
{
    const int dir = blockIdx.x >> 5;
    const int grp = blockIdx.x & 31;
    const int j   = threadIdx.x;
    const float2* __restrict__ WP = g_WhhP0 + (size_t)dir*HALFK*GG;

    float bi[3], bh[3], wiA[3], wiB[3];
#pragma unroll
    for (int g = 0; g < 3; g++){
        int row = dir*GG + g*HH + j;
        bi[g]  = bih[row];
        bh[g]  = bhh[row];
        wiA[g] = Wih[(size_t)row*2 + 0];
        wiB[g] = Wih[(size_t)row*2 + 1];
    }

    __shared__ __align__(16) float hs[4][HH];
#pragma unroll
    for (int r = 0; r < 4; r++) hs[r][j] = 0.0f;
    __syncthreads();

    const int b0 = grp*4;
    for (int s = 0; s < TT; s++){
        const int t = dir ? (TT-1-s) : s;
        float giR[4], giZ[4], giN[4];
        float2 aR2[4], aZ2[4], aN2[4];
#pragma unroll
        for (int r = 0; r < 4; r++){
            float x0 = x[((size_t)(b0+r)*TT + t)*2 + 0];
            float x1 = x[((size_t)(b0+r)*TT + t)*2 + 1];
            giR[r] = bi[0] + wiA[0]*x0 + wiB[0]*x1;
            giZ[r] = bi[1] + wiA[1]*x0 + wiB[1]*x1;
            giN[r] = bi[2] + wiA[2]*x0 + wiB[2]*x1;
            aR2[r] = make_float2(0.f,0.f); aZ2[r] = make_float2(0.f,0.f); aN2[r] = make_float2(0.f,0.f);
        }
#pragma unroll 2
        for (int kk = 0; kk < HALFK; kk++){
            float2 w0 = WP[kk*GG + j];
            float2 w1 = WP[kk*GG + HH + j];
            float2 w2 = WP[kk*GG + 2*HH + j];
#pragma unroll
            for (int r = 0; r < 4; r++){
                float2 h2 = *(const float2*)&hs[r][2*kk];
                aR2[r] = ffma2(w0, h2, aR2[r]);
                aZ2[r] = ffma2(w1, h2, aZ2[r]);
                aN2[r] = ffma2(w2, h2, aN2[r]);
            }
        }
        float hn[4];
#pragma unroll
        for (int r = 0; r < 4; r++){
            float hold = hs[r][j];
            float rg = sigf(giR[r] + bh[0] + aR2[r].x + aR2[r].y);
            float zg = sigf(giZ[r] + bh[1] + aZ2[r].x + aZ2[r].y);
            float ng = tanhf(giN[r] + rg*(bh[2] + aN2[r].x + aN2[r].y));
            hn[r] = (1.0f - zg)*ng + zg*hold;
        }
        __syncthreads();
#pragma unroll
        for (int r = 0; r < 4; r++){
            hs[r][j] = hn[r];
            g_y0[((size_t)(b0+r)*TT + t)*(2*HH) + dir*HH + j] = hn[r];
        }
        __syncthreads();
    }
#pragma unroll
    for (int r = 0; r < 4; r++) g_h0[dir*BSZ*HH + (b0+r)*HH + j] = hs[r][j];
}

// ---------------- encoder layer 1 (gi precomputed) ----------------
__global__ __launch_bounds__(256) void enc1_kernel(const float* __restrict__ bhh)
{
    const int dir = blockIdx.x >> 5;
    const int grp = blockIdx.x & 31;
    const int j   = threadIdx.x;
    const float2* __restrict__ WP = g_WhhP1 + (size_t)dir*HALFK*GG;
    const float*  __restrict__ GI = g_gi1  + (size_t)dir*BSZ*TT*GG;

    float bh[3];
#pragma unroll
    for (int g = 0; g < 3; g++) bh[g] = bhh[dir*GG + g*HH + j];

    __shared__ __align__(16) float hs[4][HH];
#pragma unroll
    for (int r = 0; r < 4; r++) hs[r][j] = 0.0f;
    __syncthreads();

    const int b0 = grp*4;
    for (int s = 0; s < TT; s++){
        const int t = dir ? (TT-1-s) : s;
        float giR[4], giZ[4], giN[4];
        float2 aR2[4], aZ2[4], aN2[4];
#pragma unroll
        for (int r = 0; r < 4; r++){
            const float* gp = GI + ((size_t)(b0+r)*TT + t)*GG;
            giR[r] = gp[j];
            giZ[r] = gp[HH + j];
            giN[r] = gp[2*HH + j];
            aR2[r] = make_float2(0.f,0.f); aZ2[r] = make_float2(0.f,0.f); aN2[r] = make_float2(0.f,0.f);
        }
#pragma unroll 2
        for (int kk = 0; kk < HALFK; kk++){
            float2 w0 = WP[kk*GG + j];
            float2 w1 = WP[kk*GG + HH + j];
            float2 w2 = WP[kk*GG + 2*HH + j];
#pragma unroll
            for (int r = 0; r < 4; r++){
                float2 h2 = *(const float2*)&hs[r][2*kk];
                aR2[r] = ffma2(w0, h2, aR2[r]);
                aZ2[r] = ffma2(w1, h2, aZ2[r]);
                aN2[r] = ffma2(w2, h2, aN2[r]);
            }
        }
        float hn[4];
#pragma unroll
        for (int r = 0; r < 4; r++){
            float hold = hs[r][j];
            float rg = sigf(giR[r] + bh[0] + aR2[r].x + aR2[r].y);
            float zg = sigf(giZ[r] + bh[1] + aZ2[r].x + aZ2[r].y);
            float ng = tanhf(giN[r] + rg*(bh[2] + aN2[r].x + aN2[r].y));
            hn[r] = (1.0f - zg)*ng + zg*hold;
        }
        __syncthreads();
#pragma unroll
        for (int r = 0; r < 4; r++){
            hs[r][j] = hn[r];
            g_y1[((size_t)(b0+r)*TT + t)*(2*HH) + dir*HH + j] = hn[r];
        }
        __syncthreads();
    }
#pragma unroll
    for (int r = 0; r < 4; r++) g_h1[dir*BSZ*HH + (b0+r)*HH + j] = hs[r][j];
}

// ---------------- tiled SGEMM with f32x2: C[m][n] = sum_k A[m][k]*B[n][k] + bias[n] ----------------
#define GBM 128
#define GBN 64
#define GBK 16
__global__ __launch_bounds__(256) void gemm_bt(const float* __restrict__ A, const float* __restrict__ Bm,
        const float* __restrict__ bias, float* __restrict__ C, int M, int N, int K)
{
    __shared__ __align__(16) float  As [GBK][GBM];
    __shared__ __align__(16) float2 Bs2[GBK][GBN];      // duplicated (b,b)
    const int bm  = blockIdx.x * GBM;
    const int bn  = blockIdx.y * GBN;
    const int tid = threadIdx.x;
    const int tx  = tid & 15;
    const int ty  = tid >> 4;
    float2 acc2[4][4];
#pragma unroll
    for (int p = 0; p < 4; p++)
#pragma unroll
        for (int jx = 0; jx < 4; jx++) acc2[p][jx] = make_float2(0.f,0.f);

    for (int k0 = 0; k0 < K; k0 += GBK){
#pragma unroll
        for (int i = 0; i < 2; i++){
            int lin = tid + i*256;
            int ar = lin >> 2, ac = (lin & 3)*4;
            float4 v = *(const float4*)&A[(size_t)(bm+ar)*K + k0 + ac];
            As[ac+0][ar] = v.x; As[ac+1][ar] = v.y; As[ac+2][ar] = v.z; As[ac+3][ar] = v.w;
        }
        {
            int br = tid >> 2, bc = (tid & 3)*4;
            float4 v = *(const float4*)&Bm[(size_t)(bn+br)*K + k0 + bc];
            Bs2[bc+0][br] = make_float2(v.x, v.x);
            Bs2[bc+1][br] = make_float2(v.y, v.y);
            Bs2[bc+2][br] = make_float2(v.z, v.z);
            Bs2[bc+3][br] = make_float2(v.w, v.w);
        }
        __syncthreads();
#pragma unroll
        for (int k = 0; k < GBK; k++){
            float2 a2[4], b2[4];
#pragma unroll
            for (int p = 0; p < 4; p++) a2[p] = *(const float2*)&As[k][ty*8 + 2*p];
#pragma unroll
            for (int jx = 0; jx < 4; jx++) b2[jx] = Bs2[k][tx*4 + jx];
#pragma unroll
            for (int p = 0; p < 4; p++)
#pragma unroll
                for (int jx = 0; jx < 4; jx++) acc2[p][jx] = ffma2(a2[p], b2[jx], acc2[p][jx]);
        }
        __syncthreads();
    }
#pragma unroll
    for (int p = 0; p < 4; p++){
        int m0 = bm + ty*8 + 2*p;
#pragma unroll
        for (int jx = 0; jx < 4; jx++){
            int n = bn + tx*4 + jx;
            float bv = bias[n];
            C[(size_t)m0*N + n]     = acc2[p][jx].x + bv;
            C[(size_t)(m0+1)*N + n] = acc2[p][jx].y + bv;
        }
    }
}

// ---------------- decoder: 64 blocks x 2 rows, 63 sequential steps ----------------
__global__ __launch_bounds__(256) void dec_kernel(
        const int*   __restrict__ tseq, const float* __restrict__ dbih, const float* __restrict__ dbhh,
        const float* __restrict__ qb,   const float* __restrict__ outb, const float* __restrict__ emb,
        const float* __restrict__ outW, float* __restrict__ out)
{
    const int j  = threadIdx.x;
    const int b0 = blockIdx.x * 2;
    const int warp = j >> 5, lane = j & 31;

    __shared__ __align__(16) float h0s[2][HH];
    __shared__ __align__(16) float h1s[2][HH];
    __shared__ __align__(16) float qs[2][HH];
    __shared__ float cx[2][HH];
    __shared__ float ws[2][TT];
    __shared__ float es[2][EMBD];
    __shared__ float ls[2][32];
    __shared__ float buf[256];
    __shared__ float mred[2], invs[2];
    __shared__ int   toks[2];

#pragma unroll
    for (int r = 0; r < 2; r++){
        h0s[r][j] = g_h0[(b0+r)*HH + j] + g_h0[BSZ*HH + (b0+r)*HH + j];
        h1s[r][j] = g_h1[(b0+r)*HH + j] + g_h1[BSZ*HH + (b0+r)*HH + j];
    }
    if (j < 2) toks[j] = tseq[(size_t)(b0+j)*64];
    __syncthreads();

    float bi0[3], bh0[3], bi1[3], bh1[3];
#pragma unroll
    for (int g = 0; g < 3; g++){
        bi0[g] = dbih[g*HH + j];        bh0[g] = dbhh[g*HH + j];
        bi1[g] = dbih[GG + g*HH + j];   bh1[g] = dbhh[GG + g*HH + j];
    }
    const float qbias = qb[j];

    for (int s = 0; s < DECS; s++){
        if (j < 2*EMBD){ int r = j >> 3, k = j & 7; es[r][k] = emb[(size_t)toks[r]*EMBD + k]; }
        __syncthreads();

        // ---- GRU cell 0 ----
        float giR[2], giZ[2], giN[2];
        float2 aR2[2], aZ2[2], aN2[2];
#pragma unroll
        for (int r = 0; r < 2; r++){
            giR[r] = bi0[0]; giZ[r] = bi0[1]; giN[r] = bi0[2];
            aR2[r] = make_float2(0.f,0.f); aZ2[r] = make_float2(0.f,0.f); aN2[r] = make_float2(0.f,0.f);
        }
#pragma unroll
        for (int k = 0; k < EMBD; k++){
            float w0 = g_dWih0T[k*GG + j];
            float w1 = g_dWih0T[k*GG + HH + j];
            float w2 = g_dWih0T[k*GG + 2*HH + j];
#pragma unroll
            for (int r = 0; r < 2; r++){
                float e = es[r][k];
                giR[r] += w0*e; giZ[r] += w1*e; giN[r] += w2*e;
            }
        }
#pragma unroll 2
        for (int kk = 0; kk < HALFK; kk++){
            float2 w0 = g_dWhhP[kk*GG + j];
            float2 w1 = g_dWhhP[kk*GG + HH + j];
            float2 w2 = g_dWhhP[kk*GG + 2*HH + j];
#pragma unroll
            for (int r = 0; r < 2; r++){
                float2 h2 = *(const float2*)&h0s[r][2*kk];
                aR2[r] = ffma2(w0, h2, aR2[r]);
                aZ2[r] = ffma2(w1, h2, aZ2[r]);
                aN2[r] = ffma2(w2, h2, aN2[r]);
            }
        }
        float h0n[2];
#pragma unroll
        for (int r = 0; r < 2; r++){
            float hold = h0s[r][j];
            float rg = sigf(giR[r] + bh0[0] + aR2[r].x + aR2[r].y);
            float zg = sigf(giZ[r] + bh0[1] + aZ2[r].x + aZ2[r].y);
            float ng = tanhf(giN[r] + rg*(bh0[2] + aN2[r].x + aN2[r].y));
            h0n[r] = (1.0f - zg)*ng + zg*hold;
        }
        __syncthreads();
#pragma unroll
        for (int r = 0; r < 2; r++) h0s[r][j] = h0n[r];
        __syncthreads();

        // ---- GRU cell 1 (input = h0) ----
        float2 gR2[2], gZ2[2], gN2[2];
#pragma unroll
        for (int r = 0; r < 2; r++){
            gR2[r] = make_float2(0.f,0.f); gZ2[r] = make_float2(0.f,0.f); gN2[r] = make_float2(0.f,0.f);
            aR2[r] = make_float2(0.f,0.f); aZ2[r] = make_float2(0.f,0.f); aN2[r] = make_float2(0.f,0.f);
        }
#pragma unroll 2
        for (int kk = 0; kk < HALFK; kk++){
            float2 u0 = g_dWih1P[kk*GG + j];
            float2 u1 = g_dWih1P[kk*GG + HH + j];
            float2 u2 = g_dWih1P[kk*GG + 2*HH + j];
            float2 w0 = g_dWhhP[HALFK*GG + kk*GG + j];
            float2 w1 = g_dWhhP[HALFK*GG + kk*GG + HH + j];
            float2 w2 = g_dWhhP[HALFK*GG + kk*GG + 2*HH + j];
#pragma unroll
            for (int r = 0; r < 2; r++){
                float2 x2 = *(const float2*)&h0s[r][2*kk];
                float2 h2 = *(const float2*)&h1s[r][2*kk];
                gR2[r] = ffma2(u0, x2, gR2[r]);
                gZ2[r] = ffma2(u1, x2, gZ2[r]);
                gN2[r] = ffma2(u2, x2, gN2[r]);
                aR2[r] = ffma2(w0, h2, aR2[r]);
                aZ2[r] = ffma2(w1, h2, aZ2[r]);
                aN2[r] = ffma2(w2, h2, aN2[r]);
            }
        }
        float h1n[2];
#pragma unroll
        for (int r = 0; r < 2; r++){
            float hold = h1s[r][j];
            float rg = sigf(bi1[0] + gR2[r].x + gR2[r].y + bh1[0] + aR2[r].x + aR2[r].y);
            float zg = sigf(bi1[1] + gZ2[r].x + gZ2[r].y + bh1[1] + aZ2[r].x + aZ2[r].y);
            float ng = tanhf(bi1[2] + gN2[r].x + gN2[r].y + rg*(bh1[2] + aN2[r].x + aN2[r].y));
            h1n[r] = (1.0f - zg)*ng + zg*hold;
        }
        __syncthreads();
#pragma unroll
        for (int r = 0; r < 2; r++) h1s[r][j] = h1n[r];
        __syncthreads();

        // ---- q = h1 @ qW^T + qb ----
        {
            float2 q20 = make_float2(0.f,0.f), q21 = make_float2(0.f,0.f);
#pragma unroll 2
            for (int kk = 0; kk < HALFK; kk++){
                float2 w = g_qWP[kk*HH + j];
                float2 a = *(const float2*)&h1s[0][2*kk];
                float2 b = *(const float2*)&h1s[1][2*kk];
                q20 = ffma2(w, a, q20);
                q21 = ffma2(w, b, q21);
            }
            qs[0][j] = qbias + q20.x + q20.y;
            qs[1][j] = qbias + q21.x + q21.y;
        }
        __syncthreads();

        // ---- scores ----
        for (int tt = warp; tt < TT/2; tt += 8){
#pragma unroll
            for (int half = 0; half < 2; half++){
                int t = tt + half*(TT/2);
#pragma unroll
                for (int r = 0; r < 2; r++){
                    const float* ep = g_enc + ((size_t)(b0+r)*TT + t)*HH + lane*8;
                    float4 e0 = *(const float4*)(ep);
                    float4 e1 = *(const float4*)(ep+4);
                    const float* qp = &qs[r][lane*8];
                    float2 qa = *(const float2*)(qp);
                    float2 qb2 = *(const float2*)(qp+2);
                    float2 qc = *(const float2*)(qp+4);
                    float2 qd = *(const float2*)(qp+6);
                    float2 acc2 = make_float2(0.f,0.f);
                    acc2 = ffma2(make_float2(e0.x,e0.y), qa, acc2);
                    acc2 = ffma2(make_float2(e0.z,e0.w), qb2, acc2);
                    acc2 = ffma2(make_float2(e1.x,e1.y), qc, acc2);
                    acc2 = ffma2(make_float2(e1.z,e1.w), qd, acc2);
                    float acc = acc2.x + acc2.y;
#pragma unroll
                    for (int o = 16; o > 0; o >>= 1) acc += __shfl_xor_sync(0xffffffffu, acc, o);
                    if (lane == 0) ws[r][t] = acc;
                }
            }
        }
        __syncthreads();

        // ---- softmax (per row) ----
#pragma unroll
        for (int r = 0; r < 2; r++){
            buf[j] = fmaxf(ws[r][j], ws[r][j+256]);
            __syncthreads();
            for (int o = 128; o > 0; o >>= 1){
                if (j < o) buf[j] = fmaxf(buf[j], buf[j+o]);
                __syncthreads();
            }
            if (j == 0) mred[r] = buf[0];
            __syncthreads();
            float m = mred[r];
            float e0 = expf(ws[r][j] - m), e1 = expf(ws[r][j+256] - m);
            ws[r][j] = e0; ws[r][j+256] = e1;
            buf[j] = e0 + e1;
            __syncthreads();
            for (int o = 128; o > 0; o >>= 1){
                if (j < o) buf[j] += buf[j+o];
                __syncthreads();
            }
            if (j == 0) invs[r] = 1.0f/buf[0];
            __syncthreads();
        }

        // ---- ctx ----
        {
            float c0 = 0.0f, c1 = 0.0f;
            const float* e0p = g_enc + (size_t)(b0+0)*TT*HH + j;
            const float* e1p = g_enc + (size_t)(b0+1)*TT*HH + j;
            for (int t = 0; t < TT; t++){
                c0 += ws[0][t]*e0p[(size_t)t*HH];
                c1 += ws[1][t]*e1p[(size_t)t*HH];
            }
            cx[0][j] = c0*invs[0] + h1s[0][j];
            cx[1][j] = c1*invs[1] + h1s[1][j];
        }
        __syncthreads();

        // ---- logits + write ----
        for (int v = warp; v < VOC; v += 8){
            const float* wp = outW + (size_t)v*HH + lane*8;
            float4 w0 = *(const float4*)(wp);
            float4 w1 = *(const float4*)(wp+4);
#pragma unroll
            for (int r = 0; r < 2; r++){
                const float* hp = &cx[r][lane*8];
                float acc = w0.x*hp[0] + w0.y*hp[1] + w0.z*hp[2] + w0.w*hp[3]
                          + w1.x*hp[4] + w1.y*hp[5] + w1.z*hp[6] + w1.w*hp[7];
#pragma unroll
                for (int o = 16; o > 0; o >>= 1) acc += __shfl_xor_sync(0xffffffffu, acc, o);
                if (lane == 0){
                    float lv = acc + outb[v];
                    ls[r][v] = lv;
                    out[((size_t)(b0+r)*DECS + s)*VOC + v] = lv;
                }
            }
        }
        __syncthreads();

        // ---- argmax feedback ----
        if (j < 2){
            float best = ls[j][0]; int bi = 0;
#pragma unroll
            for (int v = 1; v < VOC; v++){
                float lv = ls[j][v];
                if (lv > best){ best = lv; bi = v; }
            }
            toks[j] = bi;
        }
        __syncthreads();
    }

    // ---- final hidden ----
#pragma unroll
    for (int r = 0; r < 2; r++){
        out[LOGITS_SZ + (size_t)(b0+r)*HH + j]              = h0s[r][j];
        out[LOGITS_SZ + (size_t)BSZ*HH + (size_t)(b0+r)*HH + j] = h1s[r][j];
    }
}

// ---------------- launch ----------------
extern "C" void kernel_launch(void* const* d_in, const int* in_sizes, int n_in,
                              void* d_out, int out_size)
{
    const float* x      = (const float*)d_in[0];
    const int*   tseq   = (const int*)  d_in[1];
    const float* eWih0  = (const float*)d_in[2];
    const float* eWhh0  = (const float*)d_in[3];
    const float* ebih0  = (const float*)d_in[4];
    const float* ebhh0  = (const float*)d_in[5];
    const float* eWih1  = (const float*)d_in[6];
    const float* eWhh1  = (const float*)d_in[7];
    const float* ebih1  = (const float*)d_in[8];
    const float* ebhh1  = (const float*)d_in[9];
    const float* e2d_W  = (const float*)d_in[10];
    const float* e2d_b  = (const float*)d_in[11];
    const float* dWih0  = (const float*)d_in[12];
    const float* dWih1  = (const float*)d_in[13];
    const float* dWhh   = (const float*)d_in[14];
    const float* dbih   = (const float*)d_in[15];
    const float* dbhh   = (const float*)d_in[16];
    const float* q_W    = (const float*)d_in[17];
    const float* q_b    = (const float*)d_in[18];
    const float* out_W  = (const float*)d_in[19];
    const float* out_b  = (const float*)d_in[20];
    const float* emb    = (const float*)d_in[21];
    float* out = (float*)d_out;

    prep_kernel<<<148, 256>>>(eWhh0, eWhh1, dWhh, dWih1, q_W, dWih0);
    enc0_kernel<<<64, 256>>>(x, eWih0, ebih0, ebhh0);

    float* gy0 = nullptr; cudaGetSymbolAddress((void**)&gy0, g_y0);
    float* gy1 = nullptr; cudaGetSymbolAddress((void**)&gy1, g_y1);
    float* ggi = nullptr; cudaGetSymbolAddress((void**)&ggi, g_gi1);
    float* gen = nullptr; cudaGetSymbolAddress((void**)&gen, g_enc);

    dim3 gGI(BSZ*TT/GBM, GG/GBN);
    gemm_bt<<<gGI, 256>>>(gy0, eWih1,         ebih1,     ggi,                    BSZ*TT, GG, 2*HH);
    gemm_bt<<<gGI, 256>>>(gy0, eWih1+GG*2*HH, ebih1+GG,  ggi+(size_t)BSZ*TT*GG,  BSZ*TT, GG, 2*HH);

    enc1_kernel<<<64, 256>>>(ebhh1);

    dim3 gED(BSZ*TT/GBM, HH/GBN);
    gemm_bt<<<gED, 256>>>(gy1, e2d_W, e2d_b, gen, BSZ*TT, HH, 2*HH);

    dec_kernel<<<64, 256>>>(tseq, dbih, dbhh, q_b, out_b, emb, out_W, out);
}

// round 11
// speedup vs baseline: 1.4839x; 1.3448x over previous
#include <cuda_runtime.h>
#include <math.h>
#include <stdint.h>
#include <string.h>

#define BSZ 128
#define TT  512
#define HH  256
#define GG  768
#define VOC 29
#define EMBD 8
#define DECS 63
#define KK4 64
#define LOGITS_SZ (BSZ*DECS*VOC)

// ---------------- packed fp32 FMA (Blackwell f32x2 pipe) ----------------
__device__ __forceinline__ float2 ffma2(float2 a, float2 b, float2 c){
    unsigned long long au, bu, cu, ru;
    memcpy(&au, &a, 8); memcpy(&bu, &b, 8); memcpy(&cu, &c, 8);
    asm("fma.rn.f32x2 %0, %1, %2, %3;" : "=l"(ru) : "l"(au), "l"(bu), "l"(cu));
    float2 r; memcpy(&r, &ru, 8);
    return r;
}

// ---------------- device scratch ----------------
__device__ float  g_y0 [(size_t)BSZ*TT*2*HH];
__device__ float  g_y1 [(size_t)BSZ*TT*2*HH];
__device__ float  g_gi1[(size_t)2*BSZ*TT*GG];
__device__ float  g_enc[(size_t)BSZ*TT*HH];
__device__ float  g_h0 [2*BSZ*HH];
__device__ float  g_h1 [2*BSZ*HH];
__device__ float4 g_WhhQ0 [2*KK4*GG];
__device__ float4 g_WhhQ1 [2*KK4*GG];
__device__ float4 g_dWhhQ [2*KK4*GG];
__device__ float4 g_dWih1Q[KK4*GG];
__device__ float4 g_qWQ   [KK4*HH];
__device__ float  g_dWih0T[EMBD*GG];

__device__ __forceinline__ float sigf(float v){ return 1.0f/(1.0f+expf(-v)); }

// ---------------- weight packing: [kk4][row] float4 (4 consecutive k) ----------------
__global__ void prep_kernel(const float* __restrict__ eWhh0, const float* __restrict__ eWhh1,
                            const float* __restrict__ dWhh,  const float* __restrict__ dWih1,
                            const float* __restrict__ qW,    const float* __restrict__ dWih0)
{
    const int NW = 2*KK4*GG;   // 98304
    const int NI = KK4*GG;     // 49152
    const int NQ = KK4*HH;     // 16384
    const int NT = EMBD*GG;    // 6144
    const int TOT = 3*NW + NI + NQ + NT;
    for (int i = blockIdx.x*blockDim.x + threadIdx.x; i < TOT; i += gridDim.x*blockDim.x){
        int idx = i;
        if (idx < NW){
            int d = idx/(KK4*GG), rem = idx%(KK4*GG);
            int kk = rem/GG, row = rem%GG;
            g_WhhQ0[idx] = *(const float4*)&eWhh0[(size_t)(d*GG+row)*HH + 4*kk];
            continue;
        }
        idx -= NW;
        if (idx < NW){
            int d = idx/(KK4*GG), rem = idx%(KK4*GG);
            int kk = rem/GG, row = rem%GG;
            g_WhhQ1[idx] = *(const float4*)&eWhh1[(size_t)(d*GG+row)*HH + 4*kk];
            continue;
        }
        idx -= NW;
        if (idx < NW){
            int d = idx/(KK4*GG), rem = idx%(KK4*GG);
            int kk = rem/GG, row = rem%GG;
            g_dWhhQ[idx] = *(const float4*)&dWhh[(size_t)(d*GG+row)*HH + 4*kk];
            continue;
        }
        idx -= NW;
        if (idx < NI){
            int kk = idx/GG, row = idx%GG;
            g_dWih1Q[idx] = *(const float4*)&dWih1[(size_t)row*HH + 4*kk];
            continue;
        }
        idx -= NI;
        if (idx < NQ){
            int kk = idx/HH, o = idx%HH;
            g_qWQ[idx] = *(const float4*)&qW[(size_t)o*HH + 4*kk];
            continue;
        }
        idx -= NQ;
        {
            int k = idx/GG, j3 = idx%GG;
            g_dWih0T[idx] = dWih0[(size_t)j3*EMBD + k];
        }
    }
}

// ---------------- encoder layer 0 ----------------
__global__ __launch_bounds__(256) void enc0_kernel(const float* __restrict__ x,
        const float* __restrict__ Wih, const float* __restrict__ bih, const float* __restrict__ bhh)
{
    const int dir = blockIdx.x >> 5;
    const int grp = blockIdx.x & 31;
    const int j   = threadIdx.x;
    const float4* __restrict__ WQ = g_WhhQ0 + (size_t)dir*KK4*GG;

    float bi[3], bh[3], wiA[3], wiB[3];
#pragma unroll
    for (int g = 0; g < 3; g++){
        int row = dir*GG + g*HH + j;
        bi[g]  = bih[row];
        bh[g]  = bhh[row];
        wiA[g] = Wih[(size_t)row*2 + 0];
        wiB[g] = Wih[(size_t)row*2 + 1];
    }

    __shared__ __align__(16) float hs[4][HH];
#pragma unroll
    for (int r = 0; r < 4; r++) hs[r][j] = 0.0f;
    __syncthreads();

    const int b0 = grp*4;
    for (int s = 0; s < TT; s++){
        const int t = dir ? (TT-1-s) : s;
        float giR[4], giZ[4], giN[4];
        float2 aR2[4], aZ2[4], aN2[4];
#pragma unroll
        for (int r = 0; r < 4; r++){
            float x0 = x[((size_t)(b0+r)*TT + t)*2 + 0];
            float x1 = x[((size_t)(b0+r)*TT + t)*2 + 1];
            giR[r] = bi[0] + wiA[0]*x0 + wiB[0]*x1;
            giZ[r] = bi[1] + wiA[1]*x0 + wiB[1]*x1;
            giN[r] = bi[2] + wiA[2]*x0 + wiB[2]*x1;
            aR2[r] = make_float2(0.f,0.f); aZ2[r] = make_float2(0.f,0.f); aN2[r] = make_float2(0.f,0.f);
        }
#pragma unroll 4
        for (int kk = 0; kk < KK4; kk++){
            float4 w0 = WQ[kk*GG + j];
            float4 w1 = WQ[kk*GG + HH + j];
            float4 w2 = WQ[kk*GG + 2*HH + j];
#pragma unroll
            for (int r = 0; r < 4; r++){
                float4 h4 = *(const float4*)&hs[r][4*kk];
                aR2[r] = ffma2(make_float2(w0.x,w0.y), make_float2(h4.x,h4.y), aR2[r]);
                aR2[r] = ffma2(make_float2(w0.z,w0.w), make_float2(h4.z,h4.w), aR2[r]);
                aZ2[r] = ffma2(make_float2(w1.x,w1.y), make_float2(h4.x,h4.y), aZ2[r]);
                aZ2[r] = ffma2(make_float2(w1.z,w1.w), make_float2(h4.z,h4.w), aZ2[r]);
                aN2[r] = ffma2(make_float2(w2.x,w2.y), make_float2(h4.x,h4.y), aN2[r]);
                aN2[r] = ffma2(make_float2(w2.z,w2.w), make_float2(h4.z,h4.w), aN2[r]);
            }
        }
        float hn[4];
#pragma unroll
        for (int r = 0; r < 4; r++){
            float hold = hs[r][j];
            float rg = sigf(giR[r] + bh[0] + aR2[r].x + aR2[r].y);
            float zg = sigf(giZ[r] + bh[1] + aZ2[r].x + aZ2[r].y);
            float ng = tanhf(giN[r] + rg*(bh[2] + aN2[r].x + aN2[r].y));
            hn[r] = (1.0f - zg)*ng + zg*hold;
        }
        __syncthreads();
#pragma unroll
        for (int r = 0; r < 4; r++){
            hs[r][j] = hn[r];
            g_y0[((size_t)(b0+r)*TT + t)*(2*HH) + dir*HH + j] = hn[r];
        }
        __syncthreads();
    }
#pragma unroll
    for (int r = 0; r < 4; r++) g_h0[dir*BSZ*HH + (b0+r)*HH + j] = hs[r][j];
}

// ---------------- encoder layer 1 (gi precomputed) ----------------
__global__ __launch_bounds__(256) void enc1_kernel(const float* __restrict__ bhh)
{
    const int dir = blockIdx.x >> 5;
    const int grp = blockIdx.x & 31;
    const int j   = threadIdx.x;
    const float4* __restrict__ WQ = g_WhhQ1 + (size_t)dir*KK4*GG;
    const float*  __restrict__ GI = g_gi1  + (size_t)dir*BSZ*TT*GG;

    float bh[3];
#pragma unroll
    for (int g = 0; g < 3; g++) bh[g] = bhh[dir*GG + g*HH + j];

    __shared__ __align__(16) float hs[4][HH];
#pragma unroll
    for (int r = 0; r < 4; r++) hs[r][j] = 0.0f;
    __syncthreads();

    const int b0 = grp*4;
    for (int s = 0; s < TT; s++){
        const int t = dir ? (TT-1-s) : s;
        float giR[4], giZ[4], giN[4];
        float2 aR2[4], aZ2[4], aN2[4];
#pragma unroll
        for (int r = 0; r < 4; r++){
            const float* gp = GI + ((size_t)(b0+r)*TT + t)*GG;
            giR[r] = gp[j];
            giZ[r] = gp[HH + j];
            giN[r] = gp[2*HH + j];
            aR2[r] = make_float2(0.f,0.f); aZ2[r] = make_float2(0.f,0.f); aN2[r] = make_float2(0.f,0.f);
        }
#pragma unroll 4
        for (int kk = 0; kk < KK4; kk++){
            float4 w0 = WQ[kk*GG + j];
            float4 w1 = WQ[kk*GG + HH + j];
            float4 w2 = WQ[kk*GG + 2*HH + j];
#pragma unroll
            for (int r = 0; r < 4; r++){
                float4 h4 = *(const float4*)&hs[r][4*kk];
                aR2[r] = ffma2(make_float2(w0.x,w0.y), make_float2(h4.x,h4.y), aR2[r]);
                aR2[r] = ffma2(make_float2(w0.z,w0.w), make_float2(h4.z,h4.w), aR2[r]);
                aZ2[r] = ffma2(make_float2(w1.x,w1.y), make_float2(h4.x,h4.y), aZ2[r]);
                aZ2[r] = ffma2(make_float2(w1.z,w1.w), make_float2(h4.z,h4.w), aZ2[r]);
                aN2[r] = ffma2(make_float2(w2.x,w2.y), make_float2(h4.x,h4.y), aN2[r]);
                aN2[r] = ffma2(make_float2(w2.z,w2.w), make_float2(h4.z,h4.w), aN2[r]);
            }
        }
        float hn[4];
#pragma unroll
        for (int r = 0; r < 4; r++){
            float hold = hs[r][j];
            float rg = sigf(giR[r] + bh[0] + aR2[r].x + aR2[r].y);
            float zg = sigf(giZ[r] + bh[1] + aZ2[r].x + aZ2[r].y);
            float ng = tanhf(giN[r] + rg*(bh[2] + aN2[r].x + aN2[r].y));
            hn[r] = (1.0f - zg)*ng + zg*hold;
        }
        __syncthreads();
#pragma unroll
        for (int r = 0; r < 4; r++){
            hs[r][j] = hn[r];
            g_y1[((size_t)(b0+r)*TT + t)*(2*HH) + dir*HH + j] = hn[r];
        }
        __syncthreads();
    }
#pragma unroll
    for (int r = 0; r < 4; r++) g_h1[dir*BSZ*HH + (b0+r)*HH + j] = hs[r][j];
}

// ---------------- tiled SGEMM (f32x2, 8x8 microtile): C = A@B^T + bias ----------------
#define BM 128
#define BN 128
#define BK 16
__global__ __launch_bounds__(256,2) void gemm_bt(const float* __restrict__ A, const float* __restrict__ Bm,
        const float* __restrict__ bias, float* __restrict__ C, int M, int N, int K)
{
    __shared__ __align__(16) float  As[BK][BM];   // 8KB
    __shared__ __align__(16) float2 Bs[BK][BN];   // 16KB duplicated (b,b)
    const int bm  = blockIdx.x * BM;
    const int bn  = blockIdx.y * BN;
    const int tid = threadIdx.x;
    const int lr  = tid >> 2;        // 0..63
    const int lc  = (tid & 3) * 4;   // 0,4,8,12
    const int ty  = tid >> 4;        // m group
    const int tx  = tid & 15;        // n group

    float2 acc[4][8];
#pragma unroll
    for (int p = 0; p < 4; p++)
#pragma unroll
        for (int q = 0; q < 8; q++) acc[p][q] = make_float2(0.f,0.f);

    for (int k0 = 0; k0 < K; k0 += BK){
#pragma unroll
        for (int i = 0; i < 2; i++){
            int r = lr + i*64;
            float4 av = *(const float4*)&A[(size_t)(bm+r)*K + k0 + lc];
            As[lc+0][r] = av.x; As[lc+1][r] = av.y; As[lc+2][r] = av.z; As[lc+3][r] = av.w;
            float4 bv = *(const float4*)&Bm[(size_t)(bn+r)*K + k0 + lc];
            Bs[lc+0][r] = make_float2(bv.x,bv.x);
            Bs[lc+1][r] = make_float2(bv.y,bv.y);
            Bs[lc+2][r] = make_float2(bv.z,bv.z);
            Bs[lc+3][r] = make_float2(bv.w,bv.w);
        }
        __syncthreads();
#pragma unroll
        for (int k = 0; k < BK; k++){
            float2 a2[4], b2[8];
            float4 t0 = *(const float4*)&As[k][ty*8];
            float4 t1 = *(const float4*)&As[k][ty*8 + 4];
            a2[0] = make_float2(t0.x,t0.y); a2[1] = make_float2(t0.z,t0.w);
            a2[2] = make_float2(t1.x,t1.y); a2[3] = make_float2(t1.z,t1.w);
#pragma unroll
            for (int q = 0; q < 4; q++){
                float4 bb = *(const float4*)&Bs[k][tx*8 + q*2];
                b2[q*2+0] = make_float2(bb.x,bb.y);
                b2[q*2+1] = make_float2(bb.z,bb.w);
            }
#pragma unroll
            for (int p = 0; p < 4; p++)
#pragma unroll
                for (int q = 0; q < 8; q++) acc[p][q] = ffma2(a2[p], b2[q], acc[p][q]);
        }
        __syncthreads();
    }
#pragma unroll
    for (int p = 0; p < 4; p++){
        int m0 = bm + ty*8 + 2*p;
#pragma unroll
        for (int q = 0; q < 8; q++){
            int n = bn + tx*8 + q;
            float bv = bias[n];
            C[(size_t)m0*N + n]     = acc[p][q].x + bv;
            C[(size_t)(m0+1)*N + n] = acc[p][q].y + bv;
        }
    }
}

// ---------------- decoder ----------------
__global__ __launch_bounds__(256) void dec_kernel(
        const int*   __restrict__ tseq, const float* __restrict__ dbih, const float* __restrict__ dbhh,
        const float* __restrict__ qb,   const float* __restrict__ outb, const float* __restrict__ emb,
        const float* __restrict__ outW, float* __restrict__ out)
{
    const int j  = threadIdx.x;
    const int b0 = blockIdx.x * 2;
    const int warp = j >> 5, lane = j & 31;

    __shared__ __align__(16) float h0s[2][HH];
    __shared__ __align__(16) float h1s[2][HH];
    __shared__ __align__(16) float qs[2][HH];
    __shared__ float cx[2][HH];
    __shared__ float ws[2][TT];
    __shared__ float es[2][EMBD];
    __shared__ float ls[2][32];
    __shared__ float buf[256];
    __shared__ float mred[2], invs[2];
    __shared__ int   toks[2];

#pragma unroll
    for (int r = 0; r < 2; r++){
        h0s[r][j] = g_h0[(b0+r)*HH + j] + g_h0[BSZ*HH + (b0+r)*HH + j];
        h1s[r][j] = g_h1[(b0+r)*HH + j] + g_h1[BSZ*HH + (b0+r)*HH + j];
    }
    if (j < 2) toks[j] = tseq[(size_t)(b0+j)*64];
    __syncthreads();

    float bi0[3], bh0[3], bi1[3], bh1[3];
#pragma unroll
    for (int g = 0; g < 3; g++){
        bi0[g] = dbih[g*HH + j];        bh0[g] = dbhh[g*HH + j];
        bi1[g] = dbih[GG + g*HH + j];   bh1[g] = dbhh[GG + g*HH + j];
    }
    const float qbias = qb[j];

    for (int s = 0; s < DECS; s++){
        if (j < 2*EMBD){ int r = j >> 3, k = j & 7; es[r][k] = emb[(size_t)toks[r]*EMBD + k]; }
        __syncthreads();

        // ---- GRU cell 0 ----
        float giR[2], giZ[2], giN[2];
        float2 aR2[2], aZ2[2], aN2[2];
#pragma unroll
        for (int r = 0; r < 2; r++){
            giR[r] = bi0[0]; giZ[r] = bi0[1]; giN[r] = bi0[2];
            aR2[r] = make_float2(0.f,0.f); aZ2[r] = make_float2(0.f,0.f); aN2[r] = make_float2(0.f,0.f);
        }
#pragma unroll
        for (int k = 0; k < EMBD; k++){
            float w0 = g_dWih0T[k*GG + j];
            float w1 = g_dWih0T[k*GG + HH + j];
            float w2 = g_dWih0T[k*GG + 2*HH + j];
#pragma unroll
            for (int r = 0; r < 2; r++){
                float e = es[r][k];
                giR[r] += w0*e; giZ[r] += w1*e; giN[r] += w2*e;
            }
        }
#pragma unroll 4
        for (int kk = 0; kk < KK4; kk++){
            float4 w0 = g_dWhhQ[kk*GG + j];
            float4 w1 = g_dWhhQ[kk*GG + HH + j];
            float4 w2 = g_dWhhQ[kk*GG + 2*HH + j];
#pragma unroll
            for (int r = 0; r < 2; r++){
                float4 h4 = *(const float4*)&h0s[r][4*kk];
                aR2[r] = ffma2(make_float2(w0.x,w0.y), make_float2(h4.x,h4.y), aR2[r]);
                aR2[r] = ffma2(make_float2(w0.z,w0.w), make_float2(h4.z,h4.w), aR2[r]);
                aZ2[r] = ffma2(make_float2(w1.x,w1.y), make_float2(h4.x,h4.y), aZ2[r]);
                aZ2[r] = ffma2(make_float2(w1.z,w1.w), make_float2(h4.z,h4.w), aZ2[r]);
                aN2[r] = ffma2(make_float2(w2.x,w2.y), make_float2(h4.x,h4.y), aN2[r]);
                aN2[r] = ffma2(make_float2(w2.z,w2.w), make_float2(h4.z,h4.w), aN2[r]);
            }
        }
        float h0n[2];
#pragma unroll
        for (int r = 0; r < 2; r++){
            float hold = h0s[r][j];
            float rg = sigf(giR[r] + bh0[0] + aR2[r].x + aR2[r].y);
            float zg = sigf(giZ[r] + bh0[1] + aZ2[r].x + aZ2[r].y);
            float ng = tanhf(giN[r] + rg*(bh0[2] + aN2[r].x + aN2[r].y));
            h0n[r] = (1.0f - zg)*ng + zg*hold;
        }
        __syncthreads();
#pragma unroll
        for (int r = 0; r < 2; r++) h0s[r][j] = h0n[r];
        __syncthreads();

        // ---- GRU cell 1 (input = h0) ----
        float2 gR2[2], gZ2[2], gN2[2];
#pragma unroll
        for (int r = 0; r < 2; r++){
            gR2[r] = make_float2(0.f,0.f); gZ2[r] = make_float2(0.f,0.f); gN2[r] = make_float2(0.f,0.f);
            aR2[r] = make_float2(0.f,0.f); aZ2[r] = make_float2(0.f,0.f); aN2[r] = make_float2(0.f,0.f);
        }
#pragma unroll 2
        for (int kk = 0; kk < KK4; kk++){
            float4 u0 = g_dWih1Q[kk*GG + j];
            float4 u1 = g_dWih1Q[kk*GG + HH + j];
            float4 u2 = g_dWih1Q[kk*GG + 2*HH + j];
            float4 w0 = g_dWhhQ[KK4*GG + kk*GG + j];
            float4 w1 = g_dWhhQ[KK4*GG + kk*GG + HH + j];
            float4 w2 = g_dWhhQ[KK4*GG + kk*GG + 2*HH + j];
#pragma unroll
            for (int r = 0; r < 2; r++){
                float4 x4 = *(const float4*)&h0s[r][4*kk];
                float4 h4 = *(const float4*)&h1s[r][4*kk];
                gR2[r] = ffma2(make_float2(u0.x,u0.y), make_float2(x4.x,x4.y), gR2[r]);
                gR2[r] = ffma2(make_float2(u0.z,u0.w), make_float2(x4.z,x4.w), gR2[r]);
                gZ2[r] = ffma2(make_float2(u1.x,u1.y), make_float2(x4.x,x4.y), gZ2[r]);
                gZ2[r] = ffma2(make_float2(u1.z,u1.w), make_float2(x4.z,x4.w), gZ2[r]);
                gN2[r] = ffma2(make_float2(u2.x,u2.y), make_float2(x4.x,x4.y), gN2[r]);
                gN2[r] = ffma2(make_float2(u2.z,u2.w), make_float2(x4.z,x4.w), gN2[r]);
                aR2[r] = ffma2(make_float2(w0.x,w0.y), make_float2(h4.x,h4.y), aR2[r]);
                aR2[r] = ffma2(make_float2(w0.z,w0.w), make_float2(h4.z,h4.w), aR2[r]);
                aZ2[r] = ffma2(make_float2(w1.x,w1.y), make_float2(h4.x,h4.y), aZ2[r]);
                aZ2[r] = ffma2(make_float2(w1.z,w1.w), make_float2(h4.z,h4.w), aZ2[r]);
                aN2[r] = ffma2(make_float2(w2.x,w2.y), make_float2(h4.x,h4.y), aN2[r]);
                aN2[r] = ffma2(make_float2(w2.z,w2.w), make_float2(h4.z,h4.w), aN2[r]);
            }
        }
        float h1n[2];
#pragma unroll
        for (int r = 0; r < 2; r++){
            float hold = h1s[r][j];
            float rg = sigf(bi1[0] + gR2[r].x + gR2[r].y + bh1[0] + aR2[r].x + aR2[r].y);
            float zg = sigf(bi1[1] + gZ2[r].x + gZ2[r].y + bh1[1] + aZ2[r].x + aZ2[r].y);
            float ng = tanhf(bi1[2] + gN2[r].x + gN2[r].y + rg*(bh1[2] + aN2[r].x + aN2[r].y));
            h1n[r] = (1.0f - zg)*ng + zg*hold;
        }
        __syncthreads();
#pragma unroll
        for (int r = 0; r < 2; r++) h1s[r][j] = h1n[r];
        __syncthreads();

        // ---- q = h1 @ qW^T + qb ----
        {
            float2 q20 = make_float2(0.f,0.f), q21 = make_float2(0.f,0.f);
#pragma unroll 4
            for (int kk = 0; kk < KK4; kk++){
                float4 w = g_qWQ[kk*HH + j];
                float4 a = *(const float4*)&h1s[0][4*kk];
                float4 b = *(const float4*)&h1s[1][4*kk];
                q20 = ffma2(make_float2(w.x,w.y), make_float2(a.x,a.y), q20);
                q20 = ffma2(make_float2(w.z,w.w), make_float2(a.z,a.w), q20);
                q21 = ffma2(make_float2(w.x,w.y), make_float2(b.x,b.y), q21);
                q21 = ffma2(make_float2(w.z,w.w), make_float2(b.z,b.w), q21);
            }
            qs[0][j] = qbias + q20.x + q20.y;
            qs[1][j] = qbias + q21.x + q21.y;
        }
        __syncthreads();

        // ---- scores ----
        for (int tt = warp; tt < TT/2; tt += 8){
#pragma unroll
            for (int half = 0; half < 2; half++){
                int t = tt + half*(TT/2);
#pragma unroll
                for (int r = 0; r < 2; r++){
                    const float* ep = g_enc + ((size_t)(b0+r)*TT + t)*HH + lane*8;
                    float4 e0 = *(const float4*)(ep);
                    float4 e1 = *(const float4*)(ep+4);
                    const float* qp = &qs[r][lane*8];
                    float2 qa = *(const float2*)(qp);
                    float2 qb2 = *(const float2*)(qp+2);
                    float2 qc = *(const float2*)(qp+4);
                    float2 qd = *(const float2*)(qp+6);
                    float2 acc2 = make_float2(0.f,0.f);
                    acc2 = ffma2(make_float2(e0.x,e0.y), qa, acc2);
                    acc2 = ffma2(make_float2(e0.z,e0.w), qb2, acc2);
                    acc2 = ffma2(make_float2(e1.x,e1.y), qc, acc2);
                    acc2 = ffma2(make_float2(e1.z,e1.w), qd, acc2);
                    float acc = acc2.x + acc2.y;
#pragma unroll
                    for (int o = 16; o > 0; o >>= 1) acc += __shfl_xor_sync(0xffffffffu, acc, o);
                    if (lane == 0) ws[r][t] = acc;
                }
            }
        }
        __syncthreads();

        // ---- softmax (per row) ----
#pragma unroll
        for (int r = 0; r < 2; r++){
            buf[j] = fmaxf(ws[r][j], ws[r][j+256]);
            __syncthreads();
            for (int o = 128; o > 0; o >>= 1){
                if (j < o) buf[j] = fmaxf(buf[j], buf[j+o]);
                __syncthreads();
            }
            if (j == 0) mred[r] = buf[0];
            __syncthreads();
            float m = mred[r];
            float e0 = expf(ws[r][j] - m), e1 = expf(ws[r][j+256] - m);
            ws[r][j] = e0; ws[r][j+256] = e1;
            buf[j] = e0 + e1;
            __syncthreads();
            for (int o = 128; o > 0; o >>= 1){
                if (j < o) buf[j] += buf[j+o];
                __syncthreads();
            }
            if (j == 0) invs[r] = 1.0f/buf[0];
            __syncthreads();
        }

        // ---- ctx ----
        {
            float c0 = 0.0f, c1 = 0.0f;
            const float* e0p = g_enc + (size_t)(b0+0)*TT*HH + j;
            const float* e1p = g_enc + (size_t)(b0+1)*TT*HH + j;
            for (int t = 0; t < TT; t++){
                c0 += ws[0][t]*e0p[(size_t)t*HH];
                c1 += ws[1][t]*e1p[(size_t)t*HH];
            }
            cx[0][j] = c0*invs[0] + h1s[0][j];
            cx[1][j] = c1*invs[1] + h1s[1][j];
        }
        __syncthreads();

        // ---- logits + write ----
        for (int v = warp; v < VOC; v += 8){
            const float* wp = outW + (size_t)v*HH + lane*8;
            float4 w0 = *(const float4*)(wp);
            float4 w1 = *(const float4*)(wp+4);
#pragma unroll
            for (int r = 0; r < 2; r++){
                const float* hp = &cx[r][lane*8];
                float acc = w0.x*hp[0] + w0.y*hp[1] + w0.z*hp[2] + w0.w*hp[3]
                          + w1.x*hp[4] + w1.y*hp[5] + w1.z*hp[6] + w1.w*hp[7];
#pragma unroll
                for (int o = 16; o > 0; o >>= 1) acc += __shfl_xor_sync(0xffffffffu, acc, o);
                if (lane == 0){
                    float lv = acc + outb[v];
                    ls[r][v] = lv;
                    out[((size_t)(b0+r)*DECS + s)*VOC + v] = lv;
                }
            }
        }
        __syncthreads();

        // ---- argmax feedback ----
        if (j < 2){
            float best = ls[j][0]; int bi = 0;
#pragma unroll
            for (int v = 1; v < VOC; v++){
                float lv = ls[j][v];
                if (lv > best){ best = lv; bi = v; }
            }
            toks[j] = bi;
        }
        __syncthreads();
    }

    // ---- final hidden ----
#pragma unroll
    for (int r = 0; r < 2; r++){
        out[LOGITS_SZ + (size_t)(b0+r)*HH + j]              = h0s[r][j];
        out[LOGITS_SZ + (size_t)BSZ*HH + (size_t)(b0+r)*HH + j] = h1s[r][j];
    }
}

// ---------------- launch ----------------
extern "C" void kernel_launch(void* const* d_in, const int* in_sizes, int n_in,
                              void* d_out, int out_size)
{
    const float* x      = (const float*)d_in[0];
    const int*   tseq   = (const int*)  d_in[1];
    const float* eWih0  = (const float*)d_in[2];
    const float* eWhh0  = (const float*)d_in[3];
    const float* ebih0  = (const float*)d_in[4];
    const float* ebhh0  = (const float*)d_in[5];
    const float* eWih1  = (const float*)d_in[6];
    const float* eWhh1  = (const float*)d_in[7];
    const float* ebih1  = (const float*)d_in[8];
    const float* ebhh1  = (const float*)d_in[9];
    const float* e2d_W  = (const float*)d_in[10];
    const float* e2d_b  = (const float*)d_in[11];
    const float* dWih0  = (const float*)d_in[12];
    const float* dWih1  = (const float*)d_in[13];
    const float* dWhh   = (const float*)d_in[14];
    const float* dbih   = (const float*)d_in[15];
    const float* dbhh   = (const float*)d_in[16];
    const float* q_W    = (const float*)d_in[17];
    const float* q_b    = (const float*)d_in[18];
    const float* out_W  = (const float*)d_in[19];
    const float* out_b  = (const float*)d_in[20];
    const float* emb    = (const float*)d_in[21];
    float* out = (float*)d_out;

    prep_kernel<<<148, 256>>>(eWhh0, eWhh1, dWhh, dWih1, q_W, dWih0);
    enc0_kernel<<<64, 256>>>(x, eWih0, ebih0, ebhh0);

    float* gy0 = nullptr; cudaGetSymbolAddress((void**)&gy0, g_y0);
    float* gy1 = nullptr; cudaGetSymbolAddress((void**)&gy1, g_y1);
    float* ggi = nullptr; cudaGetSymbolAddress((void**)&ggi, g_gi1);
    float* gen = nullptr; cudaGetSymbolAddress((void**)&gen, g_enc);

    dim3 gGI(BSZ*TT/BM, GG/BN);
    gemm_bt<<<gGI, 256>>>(gy0, eWih1,         ebih1,     ggi,                    BSZ*TT, GG, 2*HH);
    gemm_bt<<<gGI, 256>>>(gy0, eWih1+GG*2*HH, ebih1+GG,  ggi+(size_t)BSZ*TT*GG,  BSZ*TT, GG, 2*HH);

    enc1_kernel<<<64, 256>>>(ebhh1);

    dim3 gED(BSZ*TT/BM, HH/BN);
    gemm_bt<<<gED, 256>>>(gy1, e2d_W, e2d_b, gen, BSZ*TT, HH, 2*HH);

    dec_kernel<<<64, 256>>>(tseq, dbih, dbhh, q_b, out_b, emb, out_W, out);
}

// round 14
// speedup vs baseline: 1.7584x; 1.1850x over previous
#include <cuda_runtime.h>
#include <math.h>
#include <stdint.h>
#include <string.h>

#define BSZ 128
#define TT  512
#define HH  256
#define GG  768
#define VOC 29
#define EMBD 8
#define DECS 63
#define KK4 64
#define LOGITS_SZ (BSZ*DECS*VOC)

// encoder cluster kernel smem layout (floats)
#define SM_WS    0                    // 192*64 float4 = 49152 floats
#define SM_HS    49152                // 2*8*256 = 4096
#define SM_PA    (SM_HS+4096)         // 192*9 = 1728
#define SM_WIH   (SM_PA+1728)         // 192*2 = 384
#define SM_BIS   (SM_WIH+384)         // 192
#define SM_BHS   (SM_BIS+192)         // 192
#define SM_XS    (SM_BHS+192)         // 16
#define SM_TOTF  (SM_XS+16)
#define SMEM_ENC (SM_TOTF*4)          // 223,040 bytes

// ---------------- packed fp32 FMA (Blackwell f32x2 pipe) ----------------
__device__ __forceinline__ float2 ffma2(float2 a, float2 b, float2 c){
    unsigned long long au, bu, cu, ru;
    memcpy(&au, &a, 8); memcpy(&bu, &b, 8); memcpy(&cu, &c, 8);
    asm("fma.rn.f32x2 %0, %1, %2, %3;" : "=l"(ru) : "l"(au), "l"(bu), "l"(cu));
    float2 r; memcpy(&r, &ru, 8);
    return r;
}

__device__ __forceinline__ uint32_t smem_u32(const void* p){
    uint32_t a;
    asm("{ .reg .u64 t; cvta.to.shared.u64 t, %1; cvt.u32.u64 %0, t; }" : "=r"(a) : "l"(p));
    return a;
}
__device__ __forceinline__ void st_cluster_f32(uint32_t laddr, uint32_t peer, float v){
    uint32_t r;
    asm volatile("mapa.shared::cluster.u32 %0, %1, %2;" : "=r"(r) : "r"(laddr), "r"(peer));
    asm volatile("st.shared::cluster.f32 [%0], %1;" :: "r"(r), "f"(v) : "memory");
}
#define CLUSTER_SYNC() do { \
    asm volatile("barrier.cluster.arrive.aligned;" ::: "memory"); \
    asm volatile("barrier.cluster.wait.aligned;" ::: "memory"); } while(0)

// ---------------- device scratch ----------------
__device__ float  g_y0 [(size_t)BSZ*TT*2*HH];
__device__ float  g_y1 [(size_t)BSZ*TT*2*HH];
__device__ float  g_gi1[(size_t)2*BSZ*TT*GG];
__device__ float  g_enc[(size_t)BSZ*TT*HH];
__device__ float  g_h0 [2*BSZ*HH];
__device__ float  g_h1 [2*BSZ*HH];
__device__ float4 g_dWhhQ [2*KK4*GG];
__device__ float4 g_dWih1Q[KK4*GG];
__device__ float4 g_qWQ   [KK4*HH];
__device__ float  g_dWih0T[EMBD*GG];

__device__ __forceinline__ float sigf(float v){ return 1.0f/(1.0f+expf(-v)); }

// ---------------- weight packing (decoder only) ----------------
__global__ void prep_kernel(const float* __restrict__ dWhh,  const float* __restrict__ dWih1,
                            const float* __restrict__ qW,    const float* __restrict__ dWih0)
{
    const int NW = 2*KK4*GG;   // 98304
    const int NI = KK4*GG;     // 49152
    const int NQ = KK4*HH;     // 16384
    const int NT = EMBD*GG;    // 6144
    const int TOT = NW + NI + NQ + NT;
    for (int i = blockIdx.x*blockDim.x + threadIdx.x; i < TOT; i += gridDim.x*blockDim.x){
        int idx = i;
        if (idx < NW){
            int d = idx/(KK4*GG), rem = idx%(KK4*GG);
            int kk = rem/GG, row = rem%GG;
            g_dWhhQ[idx] = *(const float4*)&dWhh[(size_t)(d*GG+row)*HH + 4*kk];
            continue;
        }
        idx -= NW;
        if (idx < NI){
            int kk = idx/GG, row = idx%GG;
            g_dWih1Q[idx] = *(const float4*)&dWih1[(size_t)row*HH + 4*kk];
            continue;
        }
        idx -= NI;
        if (idx < NQ){
            int kk = idx/HH, o = idx%HH;
            g_qWQ[idx] = *(const float4*)&qW[(size_t)o*HH + 4*kk];
            continue;
        }
        idx -= NQ;
        {
            int k = idx/GG, j3 = idx%GG;
            g_dWih0T[idx] = dWih0[(size_t)j3*EMBD + k];
        }
    }
}

// ---------------- clustered encoder layer (weights resident in cluster smem) ----------------
// grid = 128 CTAs (32 clusters of 4), 192 threads.
// cluster = (dir, batch-group of 8 rows). CTA rank owns feature slice [rank*64, rank*64+64).
template<int LAYER>
__global__ __cluster_dims__(4,1,1) __launch_bounds__(192,1)
void enc_cluster_kernel(const float* __restrict__ x,   const float* __restrict__ Wih,
                        const float* __restrict__ Whh, const float* __restrict__ bih,
                        const float* __restrict__ bhh, const float* __restrict__ gi_g,
                        float* __restrict__ y_out,     float* __restrict__ h_out)
{
    extern __shared__ float sm[];
    float* Ws   = sm + SM_WS;
    float* hs   = sm + SM_HS;
    float* pa   = sm + SM_PA;
    float* wihs = sm + SM_WIH;
    float* bis  = sm + SM_BIS;
    float* bhs  = sm + SM_BHS;
    float* xs   = sm + SM_XS;

    const int t = threadIdx.x;
    uint32_t rank; asm("mov.u32 %0, %%cluster_ctarank;" : "=r"(rank));
    const int cid = blockIdx.x >> 2;   // 0..31
    const int dir = cid >> 4;          // 0/1
    const int grp = cid & 15;          // 0..15
    const int b0  = grp*8;
    const int g   = t >> 6;            // gate 0..2
    const int jj  = t & 63;
    const int grow = g*HH + (int)rank*64 + jj;     // row in [0,768)

    // per-direction gi base (THE R12 BUG: this offset was missing)
    const float* __restrict__ GI = (LAYER == 1) ? (gi_g + (size_t)dir*BSZ*TT*GG) : gi_g;

    // load Whh slice into smem: Ws4[kk][srow], srow = t
    const float* Wsrc = Whh + (size_t)dir*GG*HH;
    for (int i = t; i < 192*64; i += 192){
        int srow = i >> 6, kk = i & 63;
        int gr = (srow>>6)*HH + (int)rank*64 + (srow&63);
        float4 v = *(const float4*)&Wsrc[(size_t)gr*HH + 4*kk];
        *(float4*)&Ws[(size_t)(kk*192 + srow)*4] = v;
    }
    // biases (+ Wih for layer 0)
    bhs[t] = bhh[dir*GG + grow];
    if (LAYER == 0){
        bis[t] = bih[dir*GG + grow];
        wihs[t*2+0] = Wih[(size_t)(dir*GG + grow)*2 + 0];
        wihs[t*2+1] = Wih[(size_t)(dir*GG + grow)*2 + 1];
    }
    // zero h buffer 0
    for (int i = t; i < 8*HH; i += 192) hs[i] = 0.0f;
    __syncthreads();
    CLUSTER_SYNC();

    const uint32_t hs_base = smem_u32(hs);
    int cur = 0;
    for (int s = 0; s < TT; s++){
        const int tt_ = dir ? (TT-1-s) : s;

        // prefetch step inputs
        float gipre[3][3];
        if (LAYER == 0){
            if (t < 16){ int r = t>>1, c2 = t&1; xs[t] = x[((size_t)(b0+r)*TT + tt_)*2 + c2]; }
        } else {
#pragma unroll
            for (int a = 0; a < 3; a++){
                int task = t + a*192;
                if (task < 512){
                    int j2 = task & 63, r2 = task >> 6;
                    const float* gp = GI + ((size_t)(b0+r2)*TT + tt_)*GG + (int)rank*64 + j2;
                    gipre[a][0] = gp[0]; gipre[a][1] = gp[HH]; gipre[a][2] = gp[2*HH];
                }
            }
        }

        // matmul: partial a[grow][r] for 8 batch rows, weights from smem
        float2 acc[8];
#pragma unroll
        for (int r = 0; r < 8; r++) acc[r] = make_float2(0.f,0.f);
        const float* hb = hs + cur*8*HH;
#pragma unroll 4
        for (int kk = 0; kk < 64; kk++){
            float4 w = *(const float4*)&Ws[(size_t)(kk*192 + t)*4];
#pragma unroll
            for (int r = 0; r < 8; r++){
                float4 h4 = *(const float4*)&hb[r*HH + 4*kk];
                acc[r] = ffma2(make_float2(w.x,w.y), make_float2(h4.x,h4.y), acc[r]);
                acc[r] = ffma2(make_float2(w.z,w.w), make_float2(h4.z,h4.w), acc[r]);
            }
        }
#pragma unroll
        for (int r = 0; r < 8; r++) pa[t*9 + r] = acc[r].x + acc[r].y;
        __syncthreads();

        // combine gates + activation + broadcast h_new shard to all 4 CTAs
        float* hnxt = hs + (cur^1)*8*HH;
        const uint32_t hnxt_u = hs_base + (uint32_t)((cur^1)*8*HH)*4u;
#pragma unroll
        for (int a = 0; a < 3; a++){
            int task = t + a*192;
            if (task < 512){
                int j2 = task & 63, r2 = task >> 6;
                float aRr = pa[(j2      )*9 + r2];
                float aZz = pa[(64 + j2 )*9 + r2];
                float aNn = pa[(128 + j2)*9 + r2];
                float giR, giZ, giN;
                if (LAYER == 0){
                    float x0 = xs[r2*2], x1 = xs[r2*2+1];
                    giR = bis[j2]      + wihs[(j2      )*2]*x0 + wihs[(j2      )*2+1]*x1;
                    giZ = bis[64+j2]   + wihs[(64+j2   )*2]*x0 + wihs[(64+j2   )*2+1]*x1;
                    giN = bis[128+j2]  + wihs[(128+j2  )*2]*x0 + wihs[(128+j2  )*2+1]*x1;
                } else {
                    giR = gipre[a][0]; giZ = gipre[a][1]; giN = gipre[a][2];
                }
                float rg = sigf(giR + bhs[j2]      + aRr);
                float zg = sigf(giZ + bhs[64+j2]   + aZz);
                float ng = tanhf(giN + rg*(bhs[128+j2] + aNn));
                int off = r2*HH + (int)rank*64 + j2;
                float hold = hb[off];
                float hn = (1.0f - zg)*ng + zg*hold;
                hnxt[off] = hn;
                uint32_t laddr = hnxt_u + (uint32_t)off*4u;
#pragma unroll
                for (uint32_t p = 0; p < 4; p++){
                    if (p != rank) st_cluster_f32(laddr, p, hn);
                }
                y_out[((size_t)(b0+r2)*TT + tt_)*(2*HH) + dir*HH + (int)rank*64 + j2] = hn;
            }
        }
        CLUSTER_SYNC();
        cur ^= 1;
    }

    // final hidden: each CTA writes its own shard
    const float* hf = hs + cur*8*HH;
#pragma unroll
    for (int a = 0; a < 3; a++){
        int task = t + a*192;
        if (task < 512){
            int j2 = task & 63, r2 = task >> 6;
            h_out[dir*BSZ*HH + (b0+r2)*HH + (int)rank*64 + j2] = hf[r2*HH + (int)rank*64 + j2];
        }
    }
}

// ---------------- tiled SGEMM (f32x2, 8x8 microtile): C = A@B^T + bias ----------------
#define BM 128
#define BN 128
#define BK 16
__global__ __launch_bounds__(256,2) void gemm_bt(const float* __restrict__ A, const float* __restrict__ Bm,
        const float* __restrict__ bias, float* __restrict__ C, int M, int N, int K)
{
    __shared__ __align__(16) float  As[BK][BM];
    __shared__ __align__(16) float2 Bs[BK][BN];
    const int bm  = blockIdx.x * BM;
    const int bn  = blockIdx.y * BN;
    const int tid = threadIdx.x;
    const int lr  = tid >> 2;
    const int lc  = (tid & 3) * 4;
    const int ty  = tid >> 4;
    const int tx  = tid & 15;

    float2 acc[4][8];
#pragma unroll
    for (int p = 0; p < 4; p++)
#pragma unroll
        for (int q = 0; q < 8; q++) acc[p][q] = make_float2(0.f,0.f);

    for (int k0 = 0; k0 < K; k0 += BK){
#pragma unroll
        for (int i = 0; i < 2; i++){
            int r = lr + i*64;
            float4 av = *(const float4*)&A[(size_t)(bm+r)*K + k0 + lc];
            As[lc+0][r] = av.x; As[lc+1][r] = av.y; As[lc+2][r] = av.z; As[lc+3][r] = av.w;
            float4 bv = *(const float4*)&Bm[(size_t)(bn+r)*K + k0 + lc];
            Bs[lc+0][r] = make_float2(bv.x,bv.x);
            Bs[lc+1][r] = make_float2(bv.y,bv.y);
            Bs[lc+2][r] = make_float2(bv.z,bv.z);
            Bs[lc+3][r] = make_float2(bv.w,bv.w);
        }
        __syncthreads();
#pragma unroll
        for (int k = 0; k < BK; k++){
            float2 a2[4], b2[8];
            float4 t0 = *(const float4*)&As[k][ty*8];
            float4 t1 = *(const float4*)&As[k][ty*8 + 4];
            a2[0] = make_float2(t0.x,t0.y); a2[1] = make_float2(t0.z,t0.w);
            a2[2] = make_float2(t1.x,t1.y); a2[3] = make_float2(t1.z,t1.w);
#pragma unroll
            for (int q = 0; q < 4; q++){
                float4 bb = *(const float4*)&Bs[k][tx*8 + q*2];
                b2[q*2+0] = make_float2(bb.x,bb.y);
                b2[q*2+1] = make_float2(bb.z,bb.w);
            }
#pragma unroll
            for (int p = 0; p < 4; p++)
#pragma unroll
                for (int q = 0; q < 8; q++) acc[p][q] = ffma2(a2[p], b2[q], acc[p][q]);
        }
        __syncthreads();
    }
#pragma unroll
    for (int p = 0; p < 4; p++){
        int m0 = bm + ty*8 + 2*p;
#pragma unroll
        for (int q = 0; q < 8; q++){
            int n = bn + tx*8 + q;
            float bv = bias[n];
            C[(size_t)m0*N + n]     = acc[p][q].x + bv;
            C[(size_t)(m0+1)*N + n] = acc[p][q].y + bv;
        }
    }
}

// ---------------- decoder ----------------
__global__ __launch_bounds__(256) void dec_kernel(
        const int*   __restrict__ tseq, const float* __restrict__ dbih, const float* __restrict__ dbhh,
        const float* __restrict__ qb,   const float* __restrict__ outb, const float* __restrict__ emb,
        const float* __restrict__ outW, float* __restrict__ out)
{
    const int j  = threadIdx.x;
    const int b0 = blockIdx.x * 2;
    const int warp = j >> 5, lane = j & 31;

    __shared__ __align__(16) float h0s[2][HH];
    __shared__ __align__(16) float h1s[2][HH];
    __shared__ __align__(16) float qs[2][HH];
    __shared__ float cx[2][HH];
    __shared__ float ws[2][TT];
    __shared__ float es[2][EMBD];
    __shared__ float ls[2][32];
    __shared__ float buf[256];
    __shared__ float mred[2], invs[2];
    __shared__ int   toks[2];

#pragma unroll
    for (int r = 0; r < 2; r++){
        h0s[r][j] = g_h0[(b0+r)*HH + j] + g_h0[BSZ*HH + (b0+r)*HH + j];
        h1s[r][j] = g_h1[(b0+r)*HH + j] + g_h1[BSZ*HH + (b0+r)*HH + j];
    }
    if (j < 2) toks[j] = tseq[(size_t)(b0+j)*64];
    __syncthreads();

    float bi0[3], bh0[3], bi1[3], bh1[3];
#pragma unroll
    for (int g = 0; g < 3; g++){
        bi0[g] = dbih[g*HH + j];        bh0[g] = dbhh[g*HH + j];
        bi1[g] = dbih[GG + g*HH + j];   bh1[g] = dbhh[GG + g*HH + j];
    }
    const float qbias = qb[j];

    for (int s = 0; s < DECS; s++){
        if (j < 2*EMBD){ int r = j >> 3, k = j & 7; es[r][k] = emb[(size_t)toks[r]*EMBD + k]; }
        __syncthreads();

        // ---- GRU cell 0 ----
        float giR[2], giZ[2], giN[2];
        float2 aR2[2], aZ2[2], aN2[2];
#pragma unroll
        for (int r = 0; r < 2; r++){
            giR[r] = bi0[0]; giZ[r] = bi0[1]; giN[r] = bi0[2];
            aR2[r] = make_float2(0.f,0.f); aZ2[r] = make_float2(0.f,0.f); aN2[r] = make_float2(0.f,0.f);
        }
#pragma unroll
        for (int k = 0; k < EMBD; k++){
            float w0 = g_dWih0T[k*GG + j];
            float w1 = g_dWih0T[k*GG + HH + j];
            float w2 = g_dWih0T[k*GG + 2*HH + j];
#pragma unroll
            for (int r = 0; r < 2; r++){
                float e = es[r][k];
                giR[r] += w0*e; giZ[r] += w1*e; giN[r] += w2*e;
            }
        }
#pragma unroll 4
        for (int kk = 0; kk < KK4; kk++){
            float4 w0 = g_dWhhQ[kk*GG + j];
            float4 w1 = g_dWhhQ[kk*GG + HH + j];
            float4 w2 = g_dWhhQ[kk*GG + 2*HH + j];
#pragma unroll
            for (int r = 0; r < 2; r++){
                float4 h4 = *(const float4*)&h0s[r][4*kk];
                aR2[r] = ffma2(make_float2(w0.x,w0.y), make_float2(h4.x,h4.y), aR2[r]);
                aR2[r] = ffma2(make_float2(w0.z,w0.w), make_float2(h4.z,h4.w), aR2[r]);
                aZ2[r] = ffma2(make_float2(w1.x,w1.y), make_float2(h4.x,h4.y), aZ2[r]);
                aZ2[r] = ffma2(make_float2(w1.z,w1.w), make_float2(h4.z,h4.w), aZ2[r]);
                aN2[r] = ffma2(make_float2(w2.x,w2.y), make_float2(h4.x,h4.y), aN2[r]);
                aN2[r] = ffma2(make_float2(w2.z,w2.w), make_float2(h4.z,h4.w), aN2[r]);
            }
        }
        float h0n[2];
#pragma unroll
        for (int r = 0; r < 2; r++){
            float hold = h0s[r][j];
            float rg = sigf(giR[r] + bh0[0] + aR2[r].x + aR2[r].y);
            float zg = sigf(giZ[r] + bh0[1] + aZ2[r].x + aZ2[r].y);
            float ng = tanhf(giN[r] + rg*(bh0[2] + aN2[r].x + aN2[r].y));
            h0n[r] = (1.0f - zg)*ng + zg*hold;
        }
        __syncthreads();
#pragma unroll
        for (int r = 0; r < 2; r++) h0s[r][j] = h0n[r];
        __syncthreads();

        // ---- GRU cell 1 (input = h0) ----
        float2 gR2[2], gZ2[2], gN2[2];
#pragma unroll
        for (int r = 0; r < 2; r++){
            gR2[r] = make_float2(0.f,0.f); gZ2[r] = make_float2(0.f,0.f); gN2[r] = make_float2(0.f,0.f);
            aR2[r] = make_float2(0.f,0.f); aZ2[r] = make_float2(0.f,0.f); aN2[r] = make_float2(0.f,0.f);
        }
#pragma unroll 2
        for (int kk = 0; kk < KK4; kk++){
            float4 u0 = g_dWih1Q[kk*GG + j];
            float4 u1 = g_dWih1Q[kk*GG + HH + j];
            float4 u2 = g_dWih1Q[kk*GG + 2*HH + j];
            float4 w0 = g_dWhhQ[KK4*GG + kk*GG + j];
            float4 w1 = g_dWhhQ[KK4*GG + kk*GG + HH + j];
            float4 w2 = g_dWhhQ[KK4*GG + kk*GG + 2*HH + j];
#pragma unroll
            for (int r = 0; r < 2; r++){
                float4 x4 = *(const float4*)&h0s[r][4*kk];
                float4 h4 = *(const float4*)&h1s[r][4*kk];
                gR2[r] = ffma2(make_float2(u0.x,u0.y), make_float2(x4.x,x4.y), gR2[r]);
                gR2[r] = ffma2(make_float2(u0.z,u0.w), make_float2(x4.z,x4.w), gR2[r]);
                gZ2[r] = ffma2(make_float2(u1.x,u1.y), make_float2(x4.x,x4.y), gZ2[r]);
                gZ2[r] = ffma2(make_float2(u1.z,u1.w), make_float2(x4.z,x4.w), gZ2[r]);
                gN2[r] = ffma2(make_float2(u2.x,u2.y), make_float2(x4.x,x4.y), gN2[r]);
                gN2[r] = ffma2(make_float2(u2.z,u2.w), make_float2(x4.z,x4.w), gN2[r]);
                aR2[r] = ffma2(make_float2(w0.x,w0.y), make_float2(h4.x,h4.y), aR2[r]);
                aR2[r] = ffma2(make_float2(w0.z,w0.w), make_float2(h4.z,h4.w), aR2[r]);
                aZ2[r] = ffma2(make_float2(w1.x,w1.y), make_float2(h4.x,h4.y), aZ2[r]);
                aZ2[r] = ffma2(make_float2(w1.z,w1.w), make_float2(h4.z,h4.w), aZ2[r]);
                aN2[r] = ffma2(make_float2(w2.x,w2.y), make_float2(h4.x,h4.y), aN2[r]);
                aN2[r] = ffma2(make_float2(w2.z,w2.w), make_float2(h4.z,h4.w), aN2[r]);
            }
        }
        float h1n[2];
#pragma unroll
        for (int r = 0; r < 2; r++){
            float hold = h1s[r][j];
            float rg = sigf(bi1[0] + gR2[r].x + gR2[r].y + bh1[0] + aR2[r].x + aR2[r].y);
            float zg = sigf(bi1[1] + gZ2[r].x + gZ2[r].y + bh1[1] + aZ2[r].x + aZ2[r].y);
            float ng = tanhf(bi1[2] + gN2[r].x + gN2[r].y + rg*(bh1[2] + aN2[r].x + aN2[r].y));
            h1n[r] = (1.0f - zg)*ng + zg*hold;
        }
        __syncthreads();
#pragma unroll
        for (int r = 0; r < 2; r++) h1s[r][j] = h1n[r];
        __syncthreads();

        // ---- q = h1 @ qW^T + qb ----
        {
            float2 q20 = make_float2(0.f,0.f), q21 = make_float2(0.f,0.f);
#pragma unroll 4
            for (int kk = 0; kk < KK4; kk++){
                float4 w = g_qWQ[kk*HH + j];
                float4 a = *(const float4*)&h1s[0][4*kk];
                float4 b = *(const float4*)&h1s[1][4*kk];
                q20 = ffma2(make_float2(w.x,w.y), make_float2(a.x,a.y), q20);
                q20 = ffma2(make_float2(w.z,w.w), make_float2(a.z,a.w), q20);
                q21 = ffma2(make_float2(w.x,w.y), make_float2(b.x,b.y), q21);
                q21 = ffma2(make_float2(w.z,w.w), make_float2(b.z,b.w), q21);
            }
            qs[0][j] = qbias + q20.x + q20.y;
            qs[1][j] = qbias + q21.x + q21.y;
        }
        __syncthreads();

        // ---- scores ----
        for (int tt = warp; tt < TT/2; tt += 8){
#pragma unroll
            for (int half = 0; half < 2; half++){
                int t = tt + half*(TT/2);
#pragma unroll
                for (int r = 0; r < 2; r++){
                    const float* ep = g_enc + ((size_t)(b0+r)*TT + t)*HH + lane*8;
                    float4 e0 = *(const float4*)(ep);
                    float4 e1 = *(const float4*)(ep+4);
                    const float* qp = &qs[r][lane*8];
                    float2 qa = *(const float2*)(qp);
                    float2 qb2 = *(const float2*)(qp+2);
                    float2 qc = *(const float2*)(qp+4);
                    float2 qd = *(const float2*)(qp+6);
                    float2 acc2 = make_float2(0.f,0.f);
                    acc2 = ffma2(make_float2(e0.x,e0.y), qa, acc2);
                    acc2 = ffma2(make_float2(e0.z,e0.w), qb2, acc2);
                    acc2 = ffma2(make_float2(e1.x,e1.y), qc, acc2);
                    acc2 = ffma2(make_float2(e1.z,e1.w), qd, acc2);
                    float acc = acc2.x + acc2.y;
#pragma unroll
                    for (int o = 16; o > 0; o >>= 1) acc += __shfl_xor_sync(0xffffffffu, acc, o);
                    if (lane == 0) ws[r][t] = acc;
                }
            }
        }
        __syncthreads();

        // ---- softmax (per row) ----
#pragma unroll
        for (int r = 0; r < 2; r++){
            buf[j] = fmaxf(ws[r][j], ws[r][j+256]);
            __syncthreads();
            for (int o = 128; o > 0; o >>= 1){
                if (j < o) buf[j] = fmaxf(buf[j], buf[j+o]);
                __syncthreads();
            }
            if (j == 0) mred[r] = buf[0];
            __syncthreads();
            float m = mred[r];
            float e0 = expf(ws[r][j] - m), e1 = expf(ws[r][j+256] - m);
            ws[r][j] = e0; ws[r][j+256] = e1;
            buf[j] = e0 + e1;
            __syncthreads();
            for (int o = 128; o > 0; o >>= 1){
                if (j < o) buf[j] += buf[j+o];
                __syncthreads();
            }
            if (j == 0) invs[r] = 1.0f/buf[0];
            __syncthreads();
        }

        // ---- ctx (4 partial accumulators to break serial chain) ----
        {
            float c0a=0.f,c0b=0.f,c0c=0.f,c0d=0.f;
            float c1a=0.f,c1b=0.f,c1c=0.f,c1d=0.f;
            const float* e0p = g_enc + (size_t)(b0+0)*TT*HH + j;
            const float* e1p = g_enc + (size_t)(b0+1)*TT*HH + j;
#pragma unroll 4
            for (int t = 0; t < TT; t += 4){
                c0a += ws[0][t  ]*e0p[(size_t)(t  )*HH];
                c0b += ws[0][t+1]*e0p[(size_t)(t+1)*HH];
                c0c += ws[0][t+2]*e0p[(size_t)(t+2)*HH];
                c0d += ws[0][t+3]*e0p[(size_t)(t+3)*HH];
                c1a += ws[1][t  ]*e1p[(size_t)(t  )*HH];
                c1b += ws[1][t+1]*e1p[(size_t)(t+1)*HH];
                c1c += ws[1][t+2]*e1p[(size_t)(t+2)*HH];
                c1d += ws[1][t+3]*e1p[(size_t)(t+3)*HH];
            }
            cx[0][j] = ((c0a+c0b)+(c0c+c0d))*invs[0] + h1s[0][j];
            cx[1][j] = ((c1a+c1b)+(c1c+c1d))*invs[1] + h1s[1][j];
        }
        __syncthreads();

        // ---- logits + write ----
        for (int v = warp; v < VOC; v += 8){
            const float* wp = outW + (size_t)v*HH + lane*8;
            float4 w0 = *(const float4*)(wp);
            float4 w1 = *(const float4*)(wp+4);
#pragma unroll
            for (int r = 0; r < 2; r++){
                const float* hp = &cx[r][lane*8];
                float acc = w0.x*hp[0] + w0.y*hp[1] + w0.z*hp[2] + w0.w*hp[3]
                          + w1.x*hp[4] + w1.y*hp[5] + w1.z*hp[6] + w1.w*hp[7];
#pragma unroll
                for (int o = 16; o > 0; o >>= 1) acc += __shfl_xor_sync(0xffffffffu, acc, o);
                if (lane == 0){
                    float lv = acc + outb[v];
                    ls[r][v] = lv;
                    out[((size_t)(b0+r)*DECS + s)*VOC + v] = lv;
                }
            }
        }
        __syncthreads();

        // ---- argmax feedback ----
        if (j < 2){
            float best = ls[j][0]; int bi = 0;
#pragma unroll
            for (int v = 1; v < VOC; v++){
                float lv = ls[j][v];
                if (lv > best){ best = lv; bi = v; }
            }
            toks[j] = bi;
        }
        __syncthreads();
    }

    // ---- final hidden ----
#pragma unroll
    for (int r = 0; r < 2; r++){
        out[LOGITS_SZ + (size_t)(b0+r)*HH + j]              = h0s[r][j];
        out[LOGITS_SZ + (size_t)BSZ*HH + (size_t)(b0+r)*HH + j] = h1s[r][j];
    }
}

// ---------------- launch ----------------
extern "C" void kernel_launch(void* const* d_in, const int* in_sizes, int n_in,
                              void* d_out, int out_size)
{
    const float* x      = (const float*)d_in[0];
    const int*   tseq   = (const int*)  d_in[1];
    const float* eWih0  = (const float*)d_in[2];
    const float* eWhh0  = (const float*)d_in[3];
    const float* ebih0  = (const float*)d_in[4];
    const float* ebhh0  = (const float*)d_in[5];
    const float* eWih1  = (const float*)d_in[6];
    const float* eWhh1  = (const float*)d_in[7];
    const float* ebih1  = (const float*)d_in[8];
    const float* ebhh1  = (const float*)d_in[9];
    const float* e2d_W  = (const float*)d_in[10];
    const float* e2d_b  = (const float*)d_in[11];
    const float* dWih0  = (const float*)d_in[12];
    const float* dWih1  = (const float*)d_in[13];
    const float* dWhh   = (const float*)d_in[14];
    const float* dbih   = (const float*)d_in[15];
    const float* dbhh   = (const float*)d_in[16];
    const float* q_W    = (const float*)d_in[17];
    const float* q_b    = (const float*)d_in[18];
    const float* out_W  = (const float*)d_in[19];
    const float* out_b  = (const float*)d_in[20];
    const float* emb    = (const float*)d_in[21];
    float* out = (float*)d_out;

    static int smem_set = 0;
    if (!smem_set){
        cudaFuncSetAttribute(enc_cluster_kernel<0>, cudaFuncAttributeMaxDynamicSharedMemorySize, SMEM_ENC);
        cudaFuncSetAttribute(enc_cluster_kernel<1>, cudaFuncAttributeMaxDynamicSharedMemorySize, SMEM_ENC);
        smem_set = 1;
    }

    float* gy0 = nullptr; cudaGetSymbolAddress((void**)&gy0, g_y0);
    float* gy1 = nullptr; cudaGetSymbolAddress((void**)&gy1, g_y1);
    float* ggi = nullptr; cudaGetSymbolAddress((void**)&ggi, g_gi1);
    float* gen = nullptr; cudaGetSymbolAddress((void**)&gen, g_enc);
    float* gh0 = nullptr; cudaGetSymbolAddress((void**)&gh0, g_h0);
    float* gh1 = nullptr; cudaGetSymbolAddress((void**)&gh1, g_h1);

    prep_kernel<<<148, 256>>>(dWhh, dWih1, q_W, dWih0);

    enc_cluster_kernel<0><<<128, 192, SMEM_ENC>>>(x, eWih0, eWhh0, ebih0, ebhh0, nullptr, gy0, gh0);

    dim3 gGI(BSZ*TT/BM, GG/BN);
    gemm_bt<<<gGI, 256>>>(gy0, eWih1,         ebih1,     ggi,                    BSZ*TT, GG, 2*HH);
    gemm_bt<<<gGI, 256>>>(gy0, eWih1+GG*2*HH, ebih1+GG,  ggi+(size_t)BSZ*TT*GG,  BSZ*TT, GG, 2*HH);

    enc_cluster_kernel<1><<<128, 192, SMEM_ENC>>>(nullptr, nullptr, eWhh1, ebih1, ebhh1, ggi, gy1, gh1);

    dim3 gED(BSZ*TT/BM, HH/BN);
    gemm_bt<<<gED, 256>>>(gy1, e2d_W, e2d_b, gen, BSZ*TT, HH, 2*HH);

    dec_kernel<<<64, 256>>>(tseq, dbih, dbhh, q_b, out_b, emb, out_W, out);
}

// round 15
// speedup vs baseline: 1.8586x; 1.0570x over previous
#include <cuda_runtime.h>
#include <math.h>
#include <stdint.h>
#include <string.h>

#define BSZ 128
#define TT  512
#define HH  256
#define GG  768
#define VOC 29
#define EMBD 8
#define DECS 63
#define KK4 64
#define LOGITS_SZ (BSZ*DECS*VOC)

// encoder cluster kernel smem layout (floats)
#define SM_WS    0                    // 192*64 float4 = 49152 floats
#define SM_HS    49152                // 2*8*256 = 4096
#define SM_PA    (SM_HS+4096)         // 192*9 = 1728
#define SM_WIH   (SM_PA+1728)         // 192*2 = 384
#define SM_BIS   (SM_WIH+384)         // 192
#define SM_BHS   (SM_BIS+192)         // 192
#define SM_XS    (SM_BHS+192)         // 16
#define SM_TOTF  (SM_XS+16)
#define SMEM_ENC (SM_TOTF*4)          // 223,040 bytes

// ---------------- packed fp32 FMA (Blackwell f32x2 pipe) ----------------
__device__ __forceinline__ float2 ffma2(float2 a, float2 b, float2 c){
    unsigned long long au, bu, cu, ru;
    memcpy(&au, &a, 8); memcpy(&bu, &b, 8); memcpy(&cu, &c, 8);
    asm("fma.rn.f32x2 %0, %1, %2, %3;" : "=l"(ru) : "l"(au), "l"(bu), "l"(cu));
    float2 r; memcpy(&r, &ru, 8);
    return r;
}

__device__ __forceinline__ uint32_t smem_u32(const void* p){
    uint32_t a;
    asm("{ .reg .u64 t; cvta.to.shared.u64 t, %1; cvt.u32.u64 %0, t; }" : "=r"(a) : "l"(p));
    return a;
}
__device__ __forceinline__ void st_cluster_f32(uint32_t laddr, uint32_t peer, float v){
    uint32_t r;
    asm volatile("mapa.shared::cluster.u32 %0, %1, %2;" : "=r"(r) : "r"(laddr), "r"(peer));
    asm volatile("st.shared::cluster.f32 [%0], %1;" :: "r"(r), "f"(v) : "memory");
}
#define CLUSTER_SYNC() do { \
    asm volatile("barrier.cluster.arrive.aligned;" ::: "memory"); \
    asm volatile("barrier.cluster.wait.aligned;" ::: "memory"); } while(0)

// ---------------- device scratch ----------------
__device__ float  g_y0 [(size_t)BSZ*TT*2*HH];
__device__ float  g_y1 [(size_t)BSZ*TT*2*HH];
__device__ float  g_gi1[(size_t)2*BSZ*TT*GG];
__device__ float  g_enc[(size_t)BSZ*TT*HH];
__device__ float  g_h0 [2*BSZ*HH];
__device__ float  g_h1 [2*BSZ*HH];
__device__ float4 g_dWhhQ [2*KK4*GG];
__device__ float4 g_dWih1Q[KK4*GG];
__device__ float4 g_qWQ   [KK4*HH];
__device__ float  g_dWih0T[EMBD*GG];

__device__ __forceinline__ float sigf(float v){ return 1.0f/(1.0f+expf(-v)); }

// ---------------- weight packing (decoder only) ----------------
__global__ void prep_kernel(const float* __restrict__ dWhh,  const float* __restrict__ dWih1,
                            const float* __restrict__ qW,    const float* __restrict__ dWih0)
{
    const int NW = 2*KK4*GG;   // 98304
    const int NI = KK4*GG;     // 49152
    const int NQ = KK4*HH;     // 16384
    const int NT = EMBD*GG;    // 6144
    const int TOT = NW + NI + NQ + NT;
    for (int i = blockIdx.x*blockDim.x + threadIdx.x; i < TOT; i += gridDim.x*blockDim.x){
        int idx = i;
        if (idx < NW){
            int d = idx/(KK4*GG), rem = idx%(KK4*GG);
            int kk = rem/GG, row = rem%GG;
            g_dWhhQ[idx] = *(const float4*)&dWhh[(size_t)(d*GG+row)*HH + 4*kk];
            continue;
        }
        idx -= NW;
        if (idx < NI){
            int kk = idx/GG, row = idx%GG;
            g_dWih1Q[idx] = *(const float4*)&dWih1[(size_t)row*HH + 4*kk];
            continue;
        }
        idx -= NI;
        if (idx < NQ){
            int kk = idx/HH, o = idx%HH;
            g_qWQ[idx] = *(const float4*)&qW[(size_t)o*HH + 4*kk];
            continue;
        }
        idx -= NQ;
        {
            int k = idx/GG, j3 = idx%GG;
            g_dWih0T[idx] = dWih0[(size_t)j3*EMBD + k];
        }
    }
}

// ---------------- clustered encoder layer (weights resident in cluster smem) ----------------
template<int LAYER>
__global__ __cluster_dims__(4,1,1) __launch_bounds__(192,1)
void enc_cluster_kernel(const float* __restrict__ x,   const float* __restrict__ Wih,
                        const float* __restrict__ Whh, const float* __restrict__ bih,
                        const float* __restrict__ bhh, const float* __restrict__ gi_g,
                        float* __restrict__ y_out,     float* __restrict__ h_out)
{
    extern __shared__ float sm[];
    float* Ws   = sm + SM_WS;
    float* hs   = sm + SM_HS;
    float* pa   = sm + SM_PA;
    float* wihs = sm + SM_WIH;
    float* bis  = sm + SM_BIS;
    float* bhs  = sm + SM_BHS;
    float* xs   = sm + SM_XS;

    const int t = threadIdx.x;
    uint32_t rank; asm("mov.u32 %0, %%cluster_ctarank;" : "=r"(rank));
    const int cid = blockIdx.x >> 2;   // 0..31
    const int dir = cid >> 4;          // 0/1
    const int grp = cid & 15;          // 0..15
    const int b0  = grp*8;
    const int g   = t >> 6;            // gate 0..2
    const int jj  = t & 63;
    const int grow = g*HH + (int)rank*64 + jj;     // row in [0,768)

    // per-direction gi base
    const float* __restrict__ GI = (LAYER == 1) ? (gi_g + (size_t)dir*BSZ*TT*GG) : gi_g;

    // load Whh slice into smem: Ws4[kk][srow], srow = t
    const float* Wsrc = Whh + (size_t)dir*GG*HH;
    for (int i = t; i < 192*64; i += 192){
        int srow = i >> 6, kk = i & 63;
        int gr = (srow>>6)*HH + (int)rank*64 + (srow&63);
        float4 v = *(const float4*)&Wsrc[(size_t)gr*HH + 4*kk];
        *(float4*)&Ws[(size_t)(kk*192 + srow)*4] = v;
    }
    // biases (+ Wih for layer 0)
    bhs[t] = bhh[dir*GG + grow];
    if (LAYER == 0){
        bis[t] = bih[dir*GG + grow];
        wihs[t*2+0] = Wih[(size_t)(dir*GG + grow)*2 + 0];
        wihs[t*2+1] = Wih[(size_t)(dir*GG + grow)*2 + 1];
    }
    // zero h buffer 0
    for (int i = t; i < 8*HH; i += 192) hs[i] = 0.0f;
    __syncthreads();
    CLUSTER_SYNC();

    const uint32_t hs_base = smem_u32(hs);
    int cur = 0;
    for (int s = 0; s < TT; s++){
        const int tt_ = dir ? (TT-1-s) : s;

        // prefetch step inputs
        float gipre[3][3];
        if (LAYER == 0){
            if (t < 16){ int r = t>>1, c2 = t&1; xs[t] = x[((size_t)(b0+r)*TT + tt_)*2 + c2]; }
        } else {
#pragma unroll
            for (int a = 0; a < 3; a++){
                int task = t + a*192;
                if (task < 512){
                    int j2 = task & 63, r2 = task >> 6;
                    const float* gp = GI + ((size_t)(b0+r2)*TT + tt_)*GG + (int)rank*64 + j2;
                    gipre[a][0] = gp[0]; gipre[a][1] = gp[HH]; gipre[a][2] = gp[2*HH];
                }
            }
        }

        // matmul: partial a[grow][r] for 8 batch rows, weights from smem
        float2 acc[8];
#pragma unroll
        for (int r = 0; r < 8; r++) acc[r] = make_float2(0.f,0.f);
        const float* hb = hs + cur*8*HH;
#pragma unroll 4
        for (int kk = 0; kk < 64; kk++){
            float4 w = *(const float4*)&Ws[(size_t)(kk*192 + t)*4];
#pragma unroll
            for (int r = 0; r < 8; r++){
                float4 h4 = *(const float4*)&hb[r*HH + 4*kk];
                acc[r] = ffma2(make_float2(w.x,w.y), make_float2(h4.x,h4.y), acc[r]);
                acc[r] = ffma2(make_float2(w.z,w.w), make_float2(h4.z,h4.w), acc[r]);
            }
        }
#pragma unroll
        for (int r = 0; r < 8; r++) pa[t*9 + r] = acc[r].x + acc[r].y;
        __syncthreads();

        // combine gates + activation + broadcast h_new shard to all 4 CTAs
        float* hnxt = hs + (cur^1)*8*HH;
        const uint32_t hnxt_u = hs_base + (uint32_t)((cur^1)*8*HH)*4u;
#pragma unroll
        for (int a = 0; a < 3; a++){
            int task = t + a*192;
            if (task < 512){
                int j2 = task & 63, r2 = task >> 6;
                float aRr = pa[(j2      )*9 + r2];
                float aZz = pa[(64 + j2 )*9 + r2];
                float aNn = pa[(128 + j2)*9 + r2];
                float giR, giZ, giN;
                if (LAYER == 0){
                    float x0 = xs[r2*2], x1 = xs[r2*2+1];
                    giR = bis[j2]      + wihs[(j2      )*2]*x0 + wihs[(j2      )*2+1]*x1;
                    giZ = bis[64+j2]   + wihs[(64+j2   )*2]*x0 + wihs[(64+j2   )*2+1]*x1;
                    giN = bis[128+j2]  + wihs[(128+j2  )*2]*x0 + wihs[(128+j2  )*2+1]*x1;
                } else {
                    giR = gipre[a][0]; giZ = gipre[a][1]; giN = gipre[a][2];
                }
                float rg = sigf(giR + bhs[j2]      + aRr);
                float zg = sigf(giZ + bhs[64+j2]   + aZz);
                float ng = tanhf(giN + rg*(bhs[128+j2] + aNn));
                int off = r2*HH + (int)rank*64 + j2;
                float hold = hb[off];
                float hn = (1.0f - zg)*ng + zg*hold;
                hnxt[off] = hn;
                uint32_t laddr = hnxt_u + (uint32_t)off*4u;
#pragma unroll
                for (uint32_t p = 0; p < 4; p++){
                    if (p != rank) st_cluster_f32(laddr, p, hn);
                }
                y_out[((size_t)(b0+r2)*TT + tt_)*(2*HH) + dir*HH + (int)rank*64 + j2] = hn;
            }
        }
        CLUSTER_SYNC();
        cur ^= 1;
    }

    // final hidden: each CTA writes its own shard
    const float* hf = hs + cur*8*HH;
#pragma unroll
    for (int a = 0; a < 3; a++){
        int task = t + a*192;
        if (task < 512){
            int j2 = task & 63, r2 = task >> 6;
            h_out[dir*BSZ*HH + (b0+r2)*HH + (int)rank*64 + j2] = hf[r2*HH + (int)rank*64 + j2];
        }
    }
}

// ---------------- double-buffered tiled SGEMM (f32x2): C = A@B^T + bias ----------------
#define BM 128
#define BN 128
#define BK 16
__global__ __launch_bounds__(256,2) void gemm_bt(const float* __restrict__ A, const float* __restrict__ Bm,
        const float* __restrict__ bias, float* __restrict__ C, int M, int N, int K)
{
    __shared__ __align__(16) float  As[2][BK][BM];   // 16KB
    __shared__ __align__(16) float2 Bs[2][BK][BN];   // 32KB duplicated (b,b)
    const int bm  = blockIdx.x * BM;
    const int bn  = blockIdx.y * BN;
    const int tid = threadIdx.x;
    const int lr  = tid >> 2;        // 0..63
    const int lc  = (tid & 3) * 4;   // 0,4,8,12
    const int ty  = tid >> 4;
    const int tx  = tid & 15;

    float2 acc[4][8];
#pragma unroll
    for (int p = 0; p < 4; p++)
#pragma unroll
        for (int q = 0; q < 8; q++) acc[p][q] = make_float2(0.f,0.f);

    // prologue: tile 0 -> buffer 0
#pragma unroll
    for (int i = 0; i < 2; i++){
        int r = lr + i*64;
        float4 av = *(const float4*)&A[(size_t)(bm+r)*K + lc];
        As[0][lc+0][r] = av.x; As[0][lc+1][r] = av.y; As[0][lc+2][r] = av.z; As[0][lc+3][r] = av.w;
        float4 bv = *(const float4*)&Bm[(size_t)(bn+r)*K + lc];
        Bs[0][lc+0][r] = make_float2(bv.x,bv.x);
        Bs[0][lc+1][r] = make_float2(bv.y,bv.y);
        Bs[0][lc+2][r] = make_float2(bv.z,bv.z);
        Bs[0][lc+3][r] = make_float2(bv.w,bv.w);
    }
    __syncthreads();

    const int NTILE = K / BK;
    for (int kt = 0; kt < NTILE; kt++){
        const int cur = kt & 1, nxt = cur ^ 1;

        // issue next tile's global loads first (overlap with compute)
        float4 avn[2], bvn[2];
        const bool has_next = (kt + 1 < NTILE);
        if (has_next){
            int k0 = (kt + 1) * BK;
#pragma unroll
            for (int i = 0; i < 2; i++){
                int r = lr + i*64;
                avn[i] = *(const float4*)&A[(size_t)(bm+r)*K + k0 + lc];
                bvn[i] = *(const float4*)&Bm[(size_t)(bn+r)*K + k0 + lc];
            }
        }

        // compute over current buffer
#pragma unroll
        for (int k = 0; k < BK; k++){
            float2 a2[4], b2[8];
            float4 t0 = *(const float4*)&As[cur][k][ty*8];
            float4 t1 = *(const float4*)&As[cur][k][ty*8 + 4];
            a2[0] = make_float2(t0.x,t0.y); a2[1] = make_float2(t0.z,t0.w);
            a2[2] = make_float2(t1.x,t1.y); a2[3] = make_float2(t1.z,t1.w);
#pragma unroll
            for (int q = 0; q < 4; q++){
                float4 bb = *(const float4*)&Bs[cur][k][tx*8 + q*2];
                b2[q*2+0] = make_float2(bb.x,bb.y);
                b2[q*2+1] = make_float2(bb.z,bb.w);
            }
#pragma unroll
            for (int p = 0; p < 4; p++)
#pragma unroll
                for (int q = 0; q < 8; q++) acc[p][q] = ffma2(a2[p], b2[q], acc[p][q]);
        }

        // stash next tile into the alternate buffer
        if (has_next){
#pragma unroll
            for (int i = 0; i < 2; i++){
                int r = lr + i*64;
                As[nxt][lc+0][r] = avn[i].x; As[nxt][lc+1][r] = avn[i].y;
                As[nxt][lc+2][r] = avn[i].z; As[nxt][lc+3][r] = avn[i].w;
                Bs[nxt][lc+0][r] = make_float2(bvn[i].x,bvn[i].x);
                Bs[nxt][lc+1][r] = make_float2(bvn[i].y,bvn[i].y);
                Bs[nxt][lc+2][r] = make_float2(bvn[i].z,bvn[i].z);
                Bs[nxt][lc+3][r] = make_float2(bvn[i].w,bvn[i].w);
            }
        }
        __syncthreads();
    }

#pragma unroll
    for (int p = 0; p < 4; p++){
        int m0 = bm + ty*8 + 2*p;
#pragma unroll
        for (int q = 0; q < 8; q++){
            int n = bn + tx*8 + q;
            float bv = bias[n];
            C[(size_t)m0*N + n]     = acc[p][q].x + bv;
            C[(size_t)(m0+1)*N + n] = acc[p][q].y + bv;
        }
    }
}

// ---------------- decoder ----------------
__global__ __launch_bounds__(256) void dec_kernel(
        const int*   __restrict__ tseq, const float* __restrict__ dbih, const float* __restrict__ dbhh,
        const float* __restrict__ qb,   const float* __restrict__ outb, const float* __restrict__ emb,
        const float* __restrict__ outW, float* __restrict__ out)
{
    const int j  = threadIdx.x;
    const int b0 = blockIdx.x * 2;
    const int warp = j >> 5, lane = j & 31;

    __shared__ __align__(16) float h0s[2][HH];
    __shared__ __align__(16) float h1s[2][HH];
    __shared__ __align__(16) float qs[2][HH];
    __shared__ float cx[2][HH];
    __shared__ float ws[2][TT];
    __shared__ float es[2][EMBD];
    __shared__ float ls[2][32];
    __shared__ float buf[256];
    __shared__ float mred[2], invs[2];
    __shared__ int   toks[2];

#pragma unroll
    for (int r = 0; r < 2; r++){
        h0s[r][j] = g_h0[(b0+r)*HH + j] + g_h0[BSZ*HH + (b0+r)*HH + j];
        h1s[r][j] = g_h1[(b0+r)*HH + j] + g_h1[BSZ*HH + (b0+r)*HH + j];
    }
    if (j < 2) toks[j] = tseq[(size_t)(b0+j)*64];
    __syncthreads();

    float bi0[3], bh0[3], bi1[3], bh1[3];
#pragma unroll
    for (int g = 0; g < 3; g++){
        bi0[g] = dbih[g*HH + j];        bh0[g] = dbhh[g*HH + j];
        bi1[g] = dbih[GG + g*HH + j];   bh1[g] = dbhh[GG + g*HH + j];
    }
    const float qbias = qb[j];

    for (int s = 0; s < DECS; s++){
        if (j < 2*EMBD){ int r = j >> 3, k = j & 7; es[r][k] = emb[(size_t)toks[r]*EMBD + k]; }
        __syncthreads();

        // ---- GRU cell 0 ----
        float giR[2], giZ[2], giN[2];
        float2 aR2[2], aZ2[2], aN2[2];
#pragma unroll
        for (int r = 0; r < 2; r++){
            giR[r] = bi0[0]; giZ[r] = bi0[1]; giN[r] = bi0[2];
            aR2[r] = make_float2(0.f,0.f); aZ2[r] = make_float2(0.f,0.f); aN2[r] = make_float2(0.f,0.f);
        }
#pragma unroll
        for (int k = 0; k < EMBD; k++){
            float w0 = g_dWih0T[k*GG + j];
            float w1 = g_dWih0T[k*GG + HH + j];
            float w2 = g_dWih0T[k*GG + 2*HH + j];
#pragma unroll
            for (int r = 0; r < 2; r++){
                float e = es[r][k];
                giR[r] += w0*e; giZ[r] += w1*e; giN[r] += w2*e;
            }
        }
#pragma unroll 4
        for (int kk = 0; kk < KK4; kk++){
            float4 w0 = g_dWhhQ[kk*GG + j];
            float4 w1 = g_dWhhQ[kk*GG + HH + j];
            float4 w2 = g_dWhhQ[kk*GG + 2*HH + j];
#pragma unroll
            for (int r = 0; r < 2; r++){
                float4 h4 = *(const float4*)&h0s[r][4*kk];
                aR2[r] = ffma2(make_float2(w0.x,w0.y), make_float2(h4.x,h4.y), aR2[r]);
                aR2[r] = ffma2(make_float2(w0.z,w0.w), make_float2(h4.z,h4.w), aR2[r]);
                aZ2[r] = ffma2(make_float2(w1.x,w1.y), make_float2(h4.x,h4.y), aZ2[r]);
                aZ2[r] = ffma2(make_float2(w1.z,w1.w), make_float2(h4.z,h4.w), aZ2[r]);
                aN2[r] = ffma2(make_float2(w2.x,w2.y), make_float2(h4.x,h4.y), aN2[r]);
                aN2[r] = ffma2(make_float2(w2.z,w2.w), make_float2(h4.z,h4.w), aN2[r]);
            }
        }
        float h0n[2];
#pragma unroll
        for (int r = 0; r < 2; r++){
            float hold = h0s[r][j];
            float rg = sigf(giR[r] + bh0[0] + aR2[r].x + aR2[r].y);
            float zg = sigf(giZ[r] + bh0[1] + aZ2[r].x + aZ2[r].y);
            float ng = tanhf(giN[r] + rg*(bh0[2] + aN2[r].x + aN2[r].y));
            h0n[r] = (1.0f - zg)*ng + zg*hold;
        }
        __syncthreads();
#pragma unroll
        for (int r = 0; r < 2; r++) h0s[r][j] = h0n[r];
        __syncthreads();

        // ---- GRU cell 1 (input = h0) ----
        float2 gR2[2], gZ2[2], gN2[2];
#pragma unroll
        for (int r = 0; r < 2; r++){
            gR2[r] = make_float2(0.f,0.f); gZ2[r] = make_float2(0.f,0.f); gN2[r] = make_float2(0.f,0.f);
            aR2[r] = make_float2(0.f,0.f); aZ2[r] = make_float2(0.f,0.f); aN2[r] = make_float2(0.f,0.f);
        }
#pragma unroll 2
        for (int kk = 0; kk < KK4; kk++){
            float4 u0 = g_dWih1Q[kk*GG + j];
            float4 u1 = g_dWih1Q[kk*GG + HH + j];
            float4 u2 = g_dWih1Q[kk*GG + 2*HH + j];
            float4 w0 = g_dWhhQ[KK4*GG + kk*GG + j];
            float4 w1 = g_dWhhQ[KK4*GG + kk*GG + HH + j];
            float4 w2 = g_dWhhQ[KK4*GG + kk*GG + 2*HH + j];
#pragma unroll
            for (int r = 0; r < 2; r++){
                float4 x4 = *(const float4*)&h0s[r][4*kk];
                float4 h4 = *(const float4*)&h1s[r][4*kk];
                gR2[r] = ffma2(make_float2(u0.x,u0.y), make_float2(x4.x,x4.y), gR2[r]);
                gR2[r] = ffma2(make_float2(u0.z,u0.w), make_float2(x4.z,x4.w), gR2[r]);
                gZ2[r] = ffma2(make_float2(u1.x,u1.y), make_float2(x4.x,x4.y), gZ2[r]);
                gZ2[r] = ffma2(make_float2(u1.z,u1.w), make_float2(x4.z,x4.w), gZ2[r]);
                gN2[r] = ffma2(make_float2(u2.x,u2.y), make_float2(x4.x,x4.y), gN2[r]);
                gN2[r] = ffma2(make_float2(u2.z,u2.w), make_float2(x4.z,x4.w), gN2[r]);
                aR2[r] = ffma2(make_float2(w0.x,w0.y), make_float2(h4.x,h4.y), aR2[r]);
                aR2[r] = ffma2(make_float2(w0.z,w0.w), make_float2(h4.z,h4.w), aR2[r]);
                aZ2[r] = ffma2(make_float2(w1.x,w1.y), make_float2(h4.x,h4.y), aZ2[r]);
                aZ2[r] = ffma2(make_float2(w1.z,w1.w), make_float2(h4.z,h4.w), aZ2[r]);
                aN2[r] = ffma2(make_float2(w2.x,w2.y), make_float2(h4.x,h4.y), aN2[r]);
                aN2[r] = ffma2(make_float2(w2.z,w2.w), make_float2(h4.z,h4.w), aN2[r]);
            }
        }
        float h1n[2];
#pragma unroll
        for (int r = 0; r < 2; r++){
            float hold = h1s[r][j];
            float rg = sigf(bi1[0] + gR2[r].x + gR2[r].y + bh1[0] + aR2[r].x + aR2[r].y);
            float zg = sigf(bi1[1] + gZ2[r].x + gZ2[r].y + bh1[1] + aZ2[r].x + aZ2[r].y);
            float ng = tanhf(bi1[2] + gN2[r].x + gN2[r].y + rg*(bh1[2] + aN2[r].x + aN2[r].y));
            h1n[r] = (1.0f - zg)*ng + zg*hold;
        }
        __syncthreads();
#pragma unroll
        for (int r = 0; r < 2; r++) h1s[r][j] = h1n[r];
        __syncthreads();

        // ---- q = h1 @ qW^T + qb ----
        {
            float2 q20 = make_float2(0.f,0.f), q21 = make_float2(0.f,0.f);
#pragma unroll 4
            for (int kk = 0; kk < KK4; kk++){
                float4 w = g_qWQ[kk*HH + j];
                float4 a = *(const float4*)&h1s[0][4*kk];
                float4 b = *(const float4*)&h1s[1][4*kk];
                q20 = ffma2(make_float2(w.x,w.y), make_float2(a.x,a.y), q20);
                q20 = ffma2(make_float2(w.z,w.w), make_float2(a.z,a.w), q20);
                q21 = ffma2(make_float2(w.x,w.y), make_float2(b.x,b.y), q21);
                q21 = ffma2(make_float2(w.z,w.w), make_float2(b.z,b.w), q21);
            }
            qs[0][j] = qbias + q20.x + q20.y;
            qs[1][j] = qbias + q21.x + q21.y;
        }
        __syncthreads();

        // ---- scores ----
        for (int tt = warp; tt < TT/2; tt += 8){
#pragma unroll
            for (int half = 0; half < 2; half++){
                int t = tt + half*(TT/2);
#pragma unroll
                for (int r = 0; r < 2; r++){
                    const float* ep = g_enc + ((size_t)(b0+r)*TT + t)*HH + lane*8;
                    float4 e0 = *(const float4*)(ep);
                    float4 e1 = *(const float4*)(ep+4);
                    const float* qp = &qs[r][lane*8];
                    float2 qa = *(const float2*)(qp);
                    float2 qb2 = *(const float2*)(qp+2);
                    float2 qc = *(const float2*)(qp+4);
                    float2 qd = *(const float2*)(qp+6);
                    float2 acc2 = make_float2(0.f,0.f);
                    acc2 = ffma2(make_float2(e0.x,e0.y), qa, acc2);
                    acc2 = ffma2(make_float2(e0.z,e0.w), qb2, acc2);
                    acc2 = ffma2(make_float2(e1.x,e1.y), qc, acc2);
                    acc2 = ffma2(make_float2(e1.z,e1.w), qd, acc2);
                    float acc = acc2.x + acc2.y;
#pragma unroll
                    for (int o = 16; o > 0; o >>= 1) acc += __shfl_xor_sync(0xffffffffu, acc, o);
                    if (lane == 0) ws[r][t] = acc;
                }
            }
        }
        __syncthreads();

        // ---- softmax (per row) ----
#pragma unroll
        for (int r = 0; r < 2; r++){
            buf[j] = fmaxf(ws[r][j], ws[r][j+256]);
            __syncthreads();
            for (int o = 128; o > 0; o >>= 1){
                if (j < o) buf[j] = fmaxf(buf[j], buf[j+o]);
                __syncthreads();
            }
            if (j == 0) mred[r] = buf[0];
            __syncthreads();
            float m = mred[r];
            float e0 = expf(ws[r][j] - m), e1 = expf(ws[r][j+256] - m);
            ws[r][j] = e0; ws[r][j+256] = e1;
            buf[j] = e0 + e1;
            __syncthreads();
            for (int o = 128; o > 0; o >>= 1){
                if (j < o) buf[j] += buf[j+o];
                __syncthreads();
            }
            if (j == 0) invs[r] = 1.0f/buf[0];
            __syncthreads();
        }

        // ---- ctx (4 partial accumulators to break serial chain) ----
        {
            float c0a=0.f,c0b=0.f,c0c=0.f,c0d=0.f;
            float c1a=0.f,c1b=0.f,c1c=0.f,c1d=0.f;
            const float* e0p = g_enc + (size_t)(b0+0)*TT*HH + j;
            const float* e1p = g_enc + (size_t)(b0+1)*TT*HH + j;
#pragma unroll 4
            for (int t = 0; t < TT; t += 4){
                c0a += ws[0][t  ]*e0p[(size_t)(t  )*HH];
                c0b += ws[0][t+1]*e0p[(size_t)(t+1)*HH];
                c0c += ws[0][t+2]*e0p[(size_t)(t+2)*HH];
                c0d += ws[0][t+3]*e0p[(size_t)(t+3)*HH];
                c1a += ws[1][t  ]*e1p[(size_t)(t  )*HH];
                c1b += ws[1][t+1]*e1p[(size_t)(t+1)*HH];
                c1c += ws[1][t+2]*e1p[(size_t)(t+2)*HH];
                c1d += ws[1][t+3]*e1p[(size_t)(t+3)*HH];
            }
            cx[0][j] = ((c0a+c0b)+(c0c+c0d))*invs[0] + h1s[0][j];
            cx[1][j] = ((c1a+c1b)+(c1c+c1d))*invs[1] + h1s[1][j];
        }
        __syncthreads();

        // ---- logits + write ----
        for (int v = warp; v < VOC; v += 8){
            const float* wp = outW + (size_t)v*HH + lane*8;
            float4 w0 = *(const float4*)(wp);
            float4 w1 = *(const float4*)(wp+4);
#pragma unroll
            for (int r = 0; r < 2; r++){
                const float* hp = &cx[r][lane*8];
                float acc = w0.x*hp[0] + w0.y*hp[1] + w0.z*hp[2] + w0.w*hp[3]
                          + w1.x*hp[4] + w1.y*hp[5] + w1.z*hp[6] + w1.w*hp[7];
#pragma unroll
                for (int o = 16; o > 0; o >>= 1) acc += __shfl_xor_sync(0xffffffffu, acc, o);
                if (lane == 0){
                    float lv = acc + outb[v];
                    ls[r][v] = lv;
                    out[((size_t)(b0+r)*DECS + s)*VOC + v] = lv;
                }
            }
        }
        __syncthreads();

        // ---- argmax feedback ----
        if (j < 2){
            float best = ls[j][0]; int bi = 0;
#pragma unroll
            for (int v = 1; v < VOC; v++){
                float lv = ls[j][v];
                if (lv > best){ best = lv; bi = v; }
            }
            toks[j] = bi;
        }
        __syncthreads();
    }

    // ---- final hidden ----
#pragma unroll
    for (int r = 0; r < 2; r++){
        out[LOGITS_SZ + (size_t)(b0+r)*HH + j]              = h0s[r][j];
        out[LOGITS_SZ + (size_t)BSZ*HH + (size_t)(b0+r)*HH + j] = h1s[r][j];
    }
}

// ---------------- launch ----------------
extern "C" void kernel_launch(void* const* d_in, const int* in_sizes, int n_in,
                              void* d_out, int out_size)
{
    const float* x      = (const float*)d_in[0];
    const int*   tseq   = (const int*)  d_in[1];
    const float* eWih0  = (const float*)d_in[2];
    const float* eWhh0  = (const float*)d_in[3];
    const float* ebih0  = (const float*)d_in[4];
    const float* ebhh0  = (const float*)d_in[5];
    const float* eWih1  = (const float*)d_in[6];
    const float* eWhh1  = (const float*)d_in[7];
    const float* ebih1  = (const float*)d_in[8];
    const float* ebhh1  = (const float*)d_in[9];
    const float* e2d_W  = (const float*)d_in[10];
    const float* e2d_b  = (const float*)d_in[11];
    const float* dWih0  = (const float*)d_in[12];
    const float* dWih1  = (const float*)d_in[13];
    const float* dWhh   = (const float*)d_in[14];
    const float* dbih   = (const float*)d_in[15];
    const float* dbhh   = (const float*)d_in[16];
    const float* q_W    = (const float*)d_in[17];
    const float* q_b    = (const float*)d_in[18];
    const float* out_W  = (const float*)d_in[19];
    const float* out_b  = (const float*)d_in[20];
    const float* emb    = (const float*)d_in[21];
    float* out = (float*)d_out;

    static int smem_set = 0;
    if (!smem_set){
        cudaFuncSetAttribute(enc_cluster_kernel<0>, cudaFuncAttributeMaxDynamicSharedMemorySize, SMEM_ENC);
        cudaFuncSetAttribute(enc_cluster_kernel<1>, cudaFuncAttributeMaxDynamicSharedMemorySize, SMEM_ENC);
        smem_set = 1;
    }

    float* gy0 = nullptr; cudaGetSymbolAddress((void**)&gy0, g_y0);
    float* gy1 = nullptr; cudaGetSymbolAddress((void**)&gy1, g_y1);
    float* ggi = nullptr; cudaGetSymbolAddress((void**)&ggi, g_gi1);
    float* gen = nullptr; cudaGetSymbolAddress((void**)&gen, g_enc);
    float* gh0 = nullptr; cudaGetSymbolAddress((void**)&gh0, g_h0);
    float* gh1 = nullptr; cudaGetSymbolAddress((void**)&gh1, g_h1);

    prep_kernel<<<148, 256>>>(dWhh, dWih1, q_W, dWih0);

    enc_cluster_kernel<0><<<128, 192, SMEM_ENC>>>(x, eWih0, eWhh0, ebih0, ebhh0, nullptr, gy0, gh0);

    dim3 gGI(BSZ*TT/BM, GG/BN);
    gemm_bt<<<gGI, 256>>>(gy0, eWih1,         ebih1,     ggi,                    BSZ*TT, GG, 2*HH);
    gemm_bt<<<gGI, 256>>>(gy0, eWih1+GG*2*HH, ebih1+GG,  ggi+(size_t)BSZ*TT*GG,  BSZ*TT, GG, 2*HH);

    enc_cluster_kernel<1><<<128, 192, SMEM_ENC>>>(nullptr, nullptr, eWhh1, ebih1, ebhh1, ggi, gy1, gh1);

    dim3 gED(BSZ*TT/BM, HH/BN);
    gemm_bt<<<gED, 256>>>(gy1, e2d_W, e2d_b, gen, BSZ*TT, HH, 2*HH);

    dec_kernel<<<64, 256>>>(tseq, dbih, dbhh, q_b, out_b, emb, out_W, out);
}

// round 16
// speedup vs baseline: 2.4591x; 1.3231x over previous
#include <cuda_runtime.h>
#include <math.h>
#include <stdint.h>
#include <string.h>

#define BSZ 128
#define TT  512
#define HH  256
#define GG  768
#define VOC 29
#define EMBD 8
#define DECS 63
#define KK4 64
#define LOGITS_SZ (BSZ*DECS*VOC)

// encoder cluster kernel smem layout (floats)
#define SM_WS    0                    // 192*64 float4 = 49152 floats
#define SM_HS    49152                // 2*8*256 = 4096
#define SM_PA    (SM_HS+4096)         // 192*9 = 1728
#define SM_WIH   (SM_PA+1728)         // 192*2 = 384
#define SM_BIS   (SM_WIH+384)         // 192
#define SM_BHS   (SM_BIS+192)         // 192
#define SM_XS    (SM_BHS+192)         // 16
#define SM_TOTF  (SM_XS+16)
#define SMEM_ENC (SM_TOTF*4)          // 223,040 bytes

// ---------------- packed fp32 FMA (Blackwell f32x2 pipe) ----------------
__device__ __forceinline__ float2 ffma2(float2 a, float2 b, float2 c){
    unsigned long long au, bu, cu, ru;
    memcpy(&au, &a, 8); memcpy(&bu, &b, 8); memcpy(&cu, &c, 8);
    asm("fma.rn.f32x2 %0, %1, %2, %3;" : "=l"(ru) : "l"(au), "l"(bu), "l"(cu));
    float2 r; memcpy(&r, &ru, 8);
    return r;
}

__device__ __forceinline__ uint32_t smem_u32(const void* p){
    uint32_t a;
    asm("{ .reg .u64 t; cvta.to.shared.u64 t, %1; cvt.u32.u64 %0, t; }" : "=r"(a) : "l"(p));
    return a;
}
__device__ __forceinline__ void st_cluster_f32(uint32_t laddr, uint32_t peer, float v){
    uint32_t r;
    asm volatile("mapa.shared::cluster.u32 %0, %1, %2;" : "=r"(r) : "r"(laddr), "r"(peer));
    asm volatile("st.shared::cluster.f32 [%0], %1;" :: "r"(r), "f"(v) : "memory");
}
#define CLUSTER_SYNC() do { \
    asm volatile("barrier.cluster.arrive.aligned;" ::: "memory"); \
    asm volatile("barrier.cluster.wait.aligned;" ::: "memory"); } while(0)

// ---------------- device scratch ----------------
__device__ float  g_y0 [(size_t)BSZ*TT*2*HH];
__device__ float  g_y1 [(size_t)BSZ*TT*2*HH];
__device__ float  g_gi1[(size_t)2*BSZ*TT*GG];
__device__ float  g_enc[(size_t)BSZ*TT*HH];
__device__ float  g_h0 [2*BSZ*HH];
__device__ float  g_h1 [2*BSZ*HH];
__device__ float4 g_dWhhQ [2*KK4*GG];
__device__ float4 g_dWih1Q[KK4*GG];
__device__ float4 g_qWQ   [KK4*HH];
__device__ float  g_dWih0T[EMBD*GG];

__device__ __forceinline__ float sigf(float v){ return 1.0f/(1.0f+expf(-v)); }

// ---------------- weight packing (decoder only) ----------------
__global__ void prep_kernel(const float* __restrict__ dWhh,  const float* __restrict__ dWih1,
                            const float* __restrict__ qW,    const float* __restrict__ dWih0)
{
    const int NW = 2*KK4*GG;   // 98304
    const int NI = KK4*GG;     // 49152
    const int NQ = KK4*HH;     // 16384
    const int NT = EMBD*GG;    // 6144
    const int TOT = NW + NI + NQ + NT;
    for (int i = blockIdx.x*blockDim.x + threadIdx.x; i < TOT; i += gridDim.x*blockDim.x){
        int idx = i;
        if (idx < NW){
            int d = idx/(KK4*GG), rem = idx%(KK4*GG);
            int kk = rem/GG, row = rem%GG;
            g_dWhhQ[idx] = *(const float4*)&dWhh[(size_t)(d*GG+row)*HH + 4*kk];
            continue;
        }
        idx -= NW;
        if (idx < NI){
            int kk = idx/GG, row = idx%GG;
            g_dWih1Q[idx] = *(const float4*)&dWih1[(size_t)row*HH + 4*kk];
            continue;
        }
        idx -= NI;
        if (idx < NQ){
            int kk = idx/HH, o = idx%HH;
            g_qWQ[idx] = *(const float4*)&qW[(size_t)o*HH + 4*kk];
            continue;
        }
        idx -= NQ;
        {
            int k = idx/GG, j3 = idx%GG;
            g_dWih0T[idx] = dWih0[(size_t)j3*EMBD + k];
        }
    }
}

// ---------------- clustered encoder layer (weights resident in cluster smem) ----------------
template<int LAYER>
__global__ __cluster_dims__(4,1,1) __launch_bounds__(192,1)
void enc_cluster_kernel(const float* __restrict__ x,   const float* __restrict__ Wih,
                        const float* __restrict__ Whh, const float* __restrict__ bih,
                        const float* __restrict__ bhh, const float* __restrict__ gi_g,
                        float* __restrict__ y_out,     float* __restrict__ h_out)
{
    extern __shared__ float sm[];
    float* Ws   = sm + SM_WS;
    float* hs   = sm + SM_HS;
    float* pa   = sm + SM_PA;
    float* wihs = sm + SM_WIH;
    float* bis  = sm + SM_BIS;
    float* bhs  = sm + SM_BHS;
    float* xs   = sm + SM_XS;

    const int t = threadIdx.x;
    uint32_t rank; asm("mov.u32 %0, %%cluster_ctarank;" : "=r"(rank));
    const int cid = blockIdx.x >> 2;   // 0..31
    const int dir = cid >> 4;          // 0/1
    const int grp = cid & 15;          // 0..15
    const int b0  = grp*8;
    const int g   = t >> 6;            // gate 0..2
    const int jj  = t & 63;
    const int grow = g*HH + (int)rank*64 + jj;     // row in [0,768)

    // per-direction gi base
    const float* __restrict__ GI = (LAYER == 1) ? (gi_g + (size_t)dir*BSZ*TT*GG) : gi_g;

    // load Whh slice into smem: Ws4[kk][srow], srow = t
    const float* Wsrc = Whh + (size_t)dir*GG*HH;
    for (int i = t; i < 192*64; i += 192){
        int srow = i >> 6, kk = i & 63;
        int gr = (srow>>6)*HH + (int)rank*64 + (srow&63);
        float4 v = *(const float4*)&Wsrc[(size_t)gr*HH + 4*kk];
        *(float4*)&Ws[(size_t)(kk*192 + srow)*4] = v;
    }
    // biases (+ Wih for layer 0)
    bhs[t] = bhh[dir*GG + grow];
    if (LAYER == 0){
        bis[t] = bih[dir*GG + grow];
        wihs[t*2+0] = Wih[(size_t)(dir*GG + grow)*2 + 0];
        wihs[t*2+1] = Wih[(size_t)(dir*GG + grow)*2 + 1];
    }
    // zero h buffer 0
    for (int i = t; i < 8*HH; i += 192) hs[i] = 0.0f;
    __syncthreads();
    CLUSTER_SYNC();

    const uint32_t hs_base = smem_u32(hs);
    int cur = 0;
    for (int s = 0; s < TT; s++){
        const int tt_ = dir ? (TT-1-s) : s;

        // prefetch step inputs
        float gipre[3][3];
        if (LAYER == 0){
            if (t < 16){ int r = t>>1, c2 = t&1; xs[t] = x[((size_t)(b0+r)*TT + tt_)*2 + c2]; }
        } else {
#pragma unroll
            for (int a = 0; a < 3; a++){
                int task = t + a*192;
                if (task < 512){
                    int j2 = task & 63, r2 = task >> 6;
                    const float* gp = GI + ((size_t)(b0+r2)*TT + tt_)*GG + (int)rank*64 + j2;
                    gipre[a][0] = gp[0]; gipre[a][1] = gp[HH]; gipre[a][2] = gp[2*HH];
                }
            }
        }

        // matmul: partial a[grow][r] for 8 batch rows, weights from smem
        float2 acc[8];
#pragma unroll
        for (int r = 0; r < 8; r++) acc[r] = make_float2(0.f,0.f);
        const float* hb = hs + cur*8*HH;
#pragma unroll 4
        for (int kk = 0; kk < 64; kk++){
            float4 w = *(const float4*)&Ws[(size_t)(kk*192 + t)*4];
#pragma unroll
            for (int r = 0; r < 8; r++){
                float4 h4 = *(const float4*)&hb[r*HH + 4*kk];
                acc[r] = ffma2(make_float2(w.x,w.y), make_float2(h4.x,h4.y), acc[r]);
                acc[r] = ffma2(make_float2(w.z,w.w), make_float2(h4.z,h4.w), acc[r]);
            }
        }
#pragma unroll
        for (int r = 0; r < 8; r++) pa[t*9 + r] = acc[r].x + acc[r].y;
        __syncthreads();

        // combine gates + activation + broadcast h_new shard to all 4 CTAs
        float* hnxt = hs + (cur^1)*8*HH;
        const uint32_t hnxt_u = hs_base + (uint32_t)((cur^1)*8*HH)*4u;
#pragma unroll
        for (int a = 0; a < 3; a++){
            int task = t + a*192;
            if (task < 512){
                int j2 = task & 63, r2 = task >> 6;
                float aRr = pa[(j2      )*9 + r2];
                float aZz = pa[(64 + j2 )*9 + r2];
                float aNn = pa[(128 + j2)*9 + r2];
                float giR, giZ, giN;
                if (LAYER == 0){
                    float x0 = xs[r2*2], x1 = xs[r2*2+1];
                    giR = bis[j2]      + wihs[(j2      )*2]*x0 + wihs[(j2      )*2+1]*x1;
                    giZ = bis[64+j2]   + wihs[(64+j2   )*2]*x0 + wihs[(64+j2   )*2+1]*x1;
                    giN = bis[128+j2]  + wihs[(128+j2  )*2]*x0 + wihs[(128+j2  )*2+1]*x1;
                } else {
                    giR = gipre[a][0]; giZ = gipre[a][1]; giN = gipre[a][2];
                }
                float rg = sigf(giR + bhs[j2]      + aRr);
                float zg = sigf(giZ + bhs[64+j2]   + aZz);
                float ng = tanhf(giN + rg*(bhs[128+j2] + aNn));
                int off = r2*HH + (int)rank*64 + j2;
                float hold = hb[off];
                float hn = (1.0f - zg)*ng + zg*hold;
                hnxt[off] = hn;
                uint32_t laddr = hnxt_u + (uint32_t)off*4u;
#pragma unroll
                for (uint32_t p = 0; p < 4; p++){
                    if (p != rank) st_cluster_f32(laddr, p, hn);
                }
                y_out[((size_t)(b0+r2)*TT + tt_)*(2*HH) + dir*HH + (int)rank*64 + j2] = hn;
            }
        }
        CLUSTER_SYNC();
        cur ^= 1;
    }

    // final hidden: each CTA writes its own shard
    const float* hf = hs + cur*8*HH;
#pragma unroll
    for (int a = 0; a < 3; a++){
        int task = t + a*192;
        if (task < 512){
            int j2 = task & 63, r2 = task >> 6;
            h_out[dir*BSZ*HH + (b0+r2)*HH + (int)rank*64 + j2] = hf[r2*HH + (int)rank*64 + j2];
        }
    }
}

// ---------------- double-buffered tiled SGEMM (f32x2, strided microtile): C = A@B^T + bias ----------------
// m-pairs: mp = ty + p*16 (rows 2mp, 2mp+1); n-cols: n = tx + q*16.
// All smem fragment loads are 8B with lane-contiguous addresses -> 1 wavefront each.
#define BM 128
#define BN 128
#define BK 16
__global__ __launch_bounds__(256,2) void gemm_bt(const float* __restrict__ A, const float* __restrict__ Bm,
        const float* __restrict__ bias, float* __restrict__ C, int M, int N, int K)
{
    __shared__ __align__(16) float  As[2][BK][BM];   // 16KB  (As[k][m], m-major pairs)
    __shared__ __align__(16) float2 Bs[2][BK][BN];   // 32KB  duplicated (b,b)
    const int bm  = blockIdx.x * BM;
    const int bn  = blockIdx.y * BN;
    const int tid = threadIdx.x;
    const int lr  = tid >> 2;        // 0..63
    const int lc  = (tid & 3) * 4;   // 0,4,8,12
    const int ty  = tid >> 4;        // 0..15 (m group)
    const int tx  = tid & 15;        // 0..15 (n group)

    float2 acc[4][8];
#pragma unroll
    for (int p = 0; p < 4; p++)
#pragma unroll
        for (int q = 0; q < 8; q++) acc[p][q] = make_float2(0.f,0.f);

    // prologue: tile 0 -> buffer 0
#pragma unroll
    for (int i = 0; i < 2; i++){
        int r = lr + i*64;
        float4 av = *(const float4*)&A[(size_t)(bm+r)*K + lc];
        As[0][lc+0][r] = av.x; As[0][lc+1][r] = av.y; As[0][lc+2][r] = av.z; As[0][lc+3][r] = av.w;
        float4 bv = *(const float4*)&Bm[(size_t)(bn+r)*K + lc];
        Bs[0][lc+0][r] = make_float2(bv.x,bv.x);
        Bs[0][lc+1][r] = make_float2(bv.y,bv.y);
        Bs[0][lc+2][r] = make_float2(bv.z,bv.z);
        Bs[0][lc+3][r] = make_float2(bv.w,bv.w);
    }
    __syncthreads();

    const int NTILE = K / BK;
    for (int kt = 0; kt < NTILE; kt++){
        const int cur = kt & 1, nxt = cur ^ 1;

        // issue next tile's global loads first (overlap with compute)
        float4 avn[2], bvn[2];
        const bool has_next = (kt + 1 < NTILE);
        if (has_next){
            int k0 = (kt + 1) * BK;
#pragma unroll
            for (int i = 0; i < 2; i++){
                int r = lr + i*64;
                avn[i] = *(const float4*)&A[(size_t)(bm+r)*K + k0 + lc];
                bvn[i] = *(const float4*)&Bm[(size_t)(bn+r)*K + k0 + lc];
            }
        }

        // compute over current buffer — lane-contiguous 8B fragment loads
#pragma unroll
        for (int k = 0; k < BK; k++){
            float2 a2[4], b2[8];
#pragma unroll
            for (int p = 0; p < 4; p++)
                a2[p] = *(const float2*)&As[cur][k][2*(ty + p*16)];
#pragma unroll
            for (int q = 0; q < 8; q++)
                b2[q] = Bs[cur][k][q*16 + tx];
#pragma unroll
            for (int p = 0; p < 4; p++)
#pragma unroll
                for (int q = 0; q < 8; q++) acc[p][q] = ffma2(a2[p], b2[q], acc[p][q]);
        }

        // stash next tile into the alternate buffer
        if (has_next){
#pragma unroll
            for (int i = 0; i < 2; i++){
                int r = lr + i*64;
                As[nxt][lc+0][r] = avn[i].x; As[nxt][lc+1][r] = avn[i].y;
                As[nxt][lc+2][r] = avn[i].z; As[nxt][lc+3][r] = avn[i].w;
                Bs[nxt][lc+0][r] = make_float2(bvn[i].x,bvn[i].x);
                Bs[nxt][lc+1][r] = make_float2(bvn[i].y,bvn[i].y);
                Bs[nxt][lc+2][r] = make_float2(bvn[i].z,bvn[i].z);
                Bs[nxt][lc+3][r] = make_float2(bvn[i].w,bvn[i].w);
            }
        }
        __syncthreads();
    }

#pragma unroll
    for (int p = 0; p < 4; p++){
        int m0 = bm + 2*(ty + p*16);
#pragma unroll
        for (int q = 0; q < 8; q++){
            int n = bn + q*16 + tx;
            float bv = bias[n];
            C[(size_t)m0*N + n]     = acc[p][q].x + bv;
            C[(size_t)(m0+1)*N + n] = acc[p][q].y + bv;
        }
    }
}

// ---------------- decoder ----------------
__global__ __launch_bounds__(256) void dec_kernel(
        const int*   __restrict__ tseq, const float* __restrict__ dbih, const float* __restrict__ dbhh,
        const float* __restrict__ qb,   const float* __restrict__ outb, const float* __restrict__ emb,
        const float* __restrict__ outW, float* __restrict__ out)
{
    const int j  = threadIdx.x;
    const int b0 = blockIdx.x * 2;
    const int warp = j >> 5, lane = j & 31;

    __shared__ __align__(16) float h0s[2][HH];
    __shared__ __align__(16) float h1s[2][HH];
    __shared__ __align__(16) float qs[2][HH];
    __shared__ float cx[2][HH];
    __shared__ float ws[2][TT];
    __shared__ float es[2][EMBD];
    __shared__ float ls[2][32];
    __shared__ float buf[256];
    __shared__ float mred[2], invs[2];
    __shared__ int   toks[2];

#pragma unroll
    for (int r = 0; r < 2; r++){
        h0s[r][j] = g_h0[(b0+r)*HH + j] + g_h0[BSZ*HH + (b0+r)*HH + j];
        h1s[r][j] = g_h1[(b0+r)*HH + j] + g_h1[BSZ*HH + (b0+r)*HH + j];
    }
    if (j < 2) toks[j] = tseq[(size_t)(b0+j)*64];
    __syncthreads();

    float bi0[3], bh0[3], bi1[3], bh1[3];
#pragma unroll
    for (int g = 0; g < 3; g++){
        bi0[g] = dbih[g*HH + j];        bh0[g] = dbhh[g*HH + j];
        bi1[g] = dbih[GG + g*HH + j];   bh1[g] = dbhh[GG + g*HH + j];
    }
    const float qbias = qb[j];

    for (int s = 0; s < DECS; s++){
        if (j < 2*EMBD){ int r = j >> 3, k = j & 7; es[r][k] = emb[(size_t)toks[r]*EMBD + k]; }
        __syncthreads();

        // ---- GRU cell 0 ----
        float giR[2], giZ[2], giN[2];
        float2 aR2[2], aZ2[2], aN2[2];
#pragma unroll
        for (int r = 0; r < 2; r++){
            giR[r] = bi0[0]; giZ[r] = bi0[1]; giN[r] = bi0[2];
            aR2[r] = make_float2(0.f,0.f); aZ2[r] = make_float2(0.f,0.f); aN2[r] = make_float2(0.f,0.f);
        }
#pragma unroll
        for (int k = 0; k < EMBD; k++){
            float w0 = g_dWih0T[k*GG + j];
            float w1 = g_dWih0T[k*GG + HH + j];
            float w2 = g_dWih0T[k*GG + 2*HH + j];
#pragma unroll
            for (int r = 0; r < 2; r++){
                float e = es[r][k];
                giR[r] += w0*e; giZ[r] += w1*e; giN[r] += w2*e;
            }
        }
#pragma unroll 4
        for (int kk = 0; kk < KK4; kk++){
            float4 w0 = g_dWhhQ[kk*GG + j];
            float4 w1 = g_dWhhQ[kk*GG + HH + j];
            float4 w2 = g_dWhhQ[kk*GG + 2*HH + j];
#pragma unroll
            for (int r = 0; r < 2; r++){
                float4 h4 = *(const float4*)&h0s[r][4*kk];
                aR2[r] = ffma2(make_float2(w0.x,w0.y), make_float2(h4.x,h4.y), aR2[r]);
                aR2[r] = ffma2(make_float2(w0.z,w0.w), make_float2(h4.z,h4.w), aR2[r]);
                aZ2[r] = ffma2(make_float2(w1.x,w1.y), make_float2(h4.x,h4.y), aZ2[r]);
                aZ2[r] = ffma2(make_float2(w1.z,w1.w), make_float2(h4.z,h4.w), aZ2[r]);
                aN2[r] = ffma2(make_float2(w2.x,w2.y), make_float2(h4.x,h4.y), aN2[r]);
                aN2[r] = ffma2(make_float2(w2.z,w2.w), make_float2(h4.z,h4.w), aN2[r]);
            }
        }
        float h0n[2];
#pragma unroll
        for (int r = 0; r < 2; r++){
            float hold = h0s[r][j];
            float rg = sigf(giR[r] + bh0[0] + aR2[r].x + aR2[r].y);
            float zg = sigf(giZ[r] + bh0[1] + aZ2[r].x + aZ2[r].y);
            float ng = tanhf(giN[r] + rg*(bh0[2] + aN2[r].x + aN2[r].y));
            h0n[r] = (1.0f - zg)*ng + zg*hold;
        }
        __syncthreads();
#pragma unroll
        for (int r = 0; r < 2; r++) h0s[r][j] = h0n[r];
        __syncthreads();

        // ---- GRU cell 1 (input = h0) ----
        float2 gR2[2], gZ2[2], gN2[2];
#pragma unroll
        for (int r = 0; r < 2; r++){
            gR2[r] = make_float2(0.f,0.f); gZ2[r] = make_float2(0.f,0.f); gN2[r] = make_float2(0.f,0.f);
            aR2[r] = make_float2(0.f,0.f); aZ2[r] = make_float2(0.f,0.f); aN2[r] = make_float2(0.f,0.f);
        }
#pragma unroll 2
        for (int kk = 0; kk < KK4; kk++){
            float4 u0 = g_dWih1Q[kk*GG + j];
            float4 u1 = g_dWih1Q[kk*GG + HH + j];
            float4 u2 = g_dWih1Q[kk*GG + 2*HH + j];
            float4 w0 = g_dWhhQ[KK4*GG + kk*GG + j];
            float4 w1 = g_dWhhQ[KK4*GG + kk*GG + HH + j];
            float4 w2 = g_dWhhQ[KK4*GG + kk*GG + 2*HH + j];
#pragma unroll
            for (int r = 0; r < 2; r++){
                float4 x4 = *(const float4*)&h0s[r][4*kk];
                float4 h4 = *(const float4*)&h1s[r][4*kk];
                gR2[r] = ffma2(make_float2(u0.x,u0.y), make_float2(x4.x,x4.y), gR2[r]);
                gR2[r] = ffma2(make_float2(u0.z,u0.w), make_float2(x4.z,x4.w), gR2[r]);
                gZ2[r] = ffma2(make_float2(u1.x,u1.y), make_float2(x4.x,x4.y), gZ2[r]);
                gZ2[r] = ffma2(make_float2(u1.z,u1.w), make_float2(x4.z,x4.w), gZ2[r]);
                gN2[r] = ffma2(make_float2(u2.x,u2.y), make_float2(x4.x,x4.y), gN2[r]);
                gN2[r] = ffma2(make_float2(u2.z,u2.w), make_float2(x4.z,x4.w), gN2[r]);
                aR2[r] = ffma2(make_float2(w0.x,w0.y), make_float2(h4.x,h4.y), aR2[r]);
                aR2[r] = ffma2(make_float2(w0.z,w0.w), make_float2(h4.z,h4.w), aR2[r]);
                aZ2[r] = ffma2(make_float2(w1.x,w1.y), make_float2(h4.x,h4.y), aZ2[r]);
                aZ2[r] = ffma2(make_float2(w1.z,w1.w), make_float2(h4.z,h4.w), aZ2[r]);
                aN2[r] = ffma2(make_float2(w2.x,w2.y), make_float2(h4.x,h4.y), aN2[r]);
                aN2[r] = ffma2(make_float2(w2.z,w2.w), make_float2(h4.z,h4.w), aN2[r]);
            }
        }
        float h1n[2];
#pragma unroll
        for (int r = 0; r < 2; r++){
            float hold = h1s[r][j];
            float rg = sigf(bi1[0] + gR2[r].x + gR2[r].y + bh1[0] + aR2[r].x + aR2[r].y);
            float zg = sigf(bi1[1] + gZ2[r].x + gZ2[r].y + bh1[1] + aZ2[r].x + aZ2[r].y);
            float ng = tanhf(bi1[2] + gN2[r].x + gN2[r].y + rg*(bh1[2] + aN2[r].x + aN2[r].y));
            h1n[r] = (1.0f - zg)*ng + zg*hold;
        }
        __syncthreads();
#pragma unroll
        for (int r = 0; r < 2; r++) h1s[r][j] = h1n[r];
        __syncthreads();

        // ---- q = h1 @ qW^T + qb ----
        {
            float2 q20 = make_float2(0.f,0.f), q21 = make_float2(0.f,0.f);
#pragma unroll 4
            for (int kk = 0; kk < KK4; kk++){
                float4 w = g_qWQ[kk*HH + j];
                float4 a = *(const float4*)&h1s[0][4*kk];
                float4 b = *(const float4*)&h1s[1][4*kk];
                q20 = ffma2(make_float2(w.x,w.y), make_float2(a.x,a.y), q20);
                q20 = ffma2(make_float2(w.z,w.w), make_float2(a.z,a.w), q20);
                q21 = ffma2(make_float2(w.x,w.y), make_float2(b.x,b.y), q21);
                q21 = ffma2(make_float2(w.z,w.w), make_float2(b.z,b.w), q21);
            }
            qs[0][j] = qbias + q20.x + q20.y;
            qs[1][j] = qbias + q21.x + q21.y;
        }
        __syncthreads();

        // ---- scores ----
        for (int tt = warp; tt < TT/2; tt += 8){
#pragma unroll
            for (int half = 0; half < 2; half++){
                int t = tt + half*(TT/2);
#pragma unroll
                for (int r = 0; r < 2; r++){
                    const float* ep = g_enc + ((size_t)(b0+r)*TT + t)*HH + lane*8;
                    float4 e0 = *(const float4*)(ep);
                    float4 e1 = *(const float4*)(ep+4);
                    const float* qp = &qs[r][lane*8];
                    float2 qa = *(const float2*)(qp);
                    float2 qb2 = *(const float2*)(qp+2);
                    float2 qc = *(const float2*)(qp+4);
                    float2 qd = *(const float2*)(qp+6);
                    float2 acc2 = make_float2(0.f,0.f);
                    acc2 = ffma2(make_float2(e0.x,e0.y), qa, acc2);
                    acc2 = ffma2(make_float2(e0.z,e0.w), qb2, acc2);
                    acc2 = ffma2(make_float2(e1.x,e1.y), qc, acc2);
                    acc2 = ffma2(make_float2(e1.z,e1.w), qd, acc2);
                    float acc = acc2.x + acc2.y;
#pragma unroll
                    for (int o = 16; o > 0; o >>= 1) acc += __shfl_xor_sync(0xffffffffu, acc, o);
                    if (lane == 0) ws[r][t] = acc;
                }
            }
        }
        __syncthreads();

        // ---- softmax (per row) ----
#pragma unroll
        for (int r = 0; r < 2; r++){
            buf[j] = fmaxf(ws[r][j], ws[r][j+256]);
            __syncthreads();
            for (int o = 128; o > 0; o >>= 1){
                if (j < o) buf[j] = fmaxf(buf[j], buf[j+o]);
                __syncthreads();
            }
            if (j == 0) mred[r] = buf[0];
            __syncthreads();
            float m = mred[r];
            float e0 = expf(ws[r][j] - m), e1 = expf(ws[r][j+256] - m);
            ws[r][j] = e0; ws[r][j+256] = e1;
            buf[j] = e0 + e1;
            __syncthreads();
            for (int o = 128; o > 0; o >>= 1){
                if (j < o) buf[j] += buf[j+o];
                __syncthreads();
            }
            if (j == 0) invs[r] = 1.0f/buf[0];
            __syncthreads();
        }

        // ---- ctx (4 partial accumulators to break serial chain) ----
        {
            float c0a=0.f,c0b=0.f,c0c=0.f,c0d=0.f;
            float c1a=0.f,c1b=0.f,c1c=0.f,c1d=0.f;
            const float* e0p = g_enc + (size_t)(b0+0)*TT*HH + j;
            const float* e1p = g_enc + (size_t)(b0+1)*TT*HH + j;
#pragma unroll 4
            for (int t = 0; t < TT; t += 4){
                c0a += ws[0][t  ]*e0p[(size_t)(t  )*HH];
                c0b += ws[0][t+1]*e0p[(size_t)(t+1)*HH];
                c0c += ws[0][t+2]*e0p[(size_t)(t+2)*HH];
                c0d += ws[0][t+3]*e0p[(size_t)(t+3)*HH];
                c1a += ws[1][t  ]*e1p[(size_t)(t  )*HH];
                c1b += ws[1][t+1]*e1p[(size_t)(t+1)*HH];
                c1c += ws[1][t+2]*e1p[(size_t)(t+2)*HH];
                c1d += ws[1][t+3]*e1p[(size_t)(t+3)*HH];
            }
            cx[0][j] = ((c0a+c0b)+(c0c+c0d))*invs[0] + h1s[0][j];
            cx[1][j] = ((c1a+c1b)+(c1c+c1d))*invs[1] + h1s[1][j];
        }
        __syncthreads();

        // ---- logits + write ----
        for (int v = warp; v < VOC; v += 8){
            const float* wp = outW + (size_t)v*HH + lane*8;
            float4 w0 = *(const float4*)(wp);
            float4 w1 = *(const float4*)(wp+4);
#pragma unroll
            for (int r = 0; r < 2; r++){
                const float* hp = &cx[r][lane*8];
                float acc = w0.x*hp[0] + w0.y*hp[1] + w0.z*hp[2] + w0.w*hp[3]
                          + w1.x*hp[4] + w1.y*hp[5] + w1.z*hp[6] + w1.w*hp[7];
#pragma unroll
                for (int o = 16; o > 0; o >>= 1) acc += __shfl_xor_sync(0xffffffffu, acc, o);
                if (lane == 0){
                    float lv = acc + outb[v];
                    ls[r][v] = lv;
                    out[((size_t)(b0+r)*DECS + s)*VOC + v] = lv;
                }
            }
        }
        __syncthreads();

        // ---- argmax feedback ----
        if (j < 2){
            float best = ls[j][0]; int bi = 0;
#pragma unroll
            for (int v = 1; v < VOC; v++){
                float lv = ls[j][v];
                if (lv > best){ best = lv; bi = v; }
            }
            toks[j] = bi;
        }
        __syncthreads();
    }

    // ---- final hidden ----
#pragma unroll
    for (int r = 0; r < 2; r++){
        out[LOGITS_SZ + (size_t)(b0+r)*HH + j]              = h0s[r][j];
        out[LOGITS_SZ + (size_t)BSZ*HH + (size_t)(b0+r)*HH + j] = h1s[r][j];
    }
}

// ---------------- launch ----------------
extern "C" void kernel_launch(void* const* d_in, const int* in_sizes, int n_in,
                              void* d_out, int out_size)
{
    const float* x      = (const float*)d_in[0];
    const int*   tseq   = (const int*)  d_in[1];
    const float* eWih0  = (const float*)d_in[2];
    const float* eWhh0  = (const float*)d_in[3];
    const float* ebih0  = (const float*)d_in[4];
    const float* ebhh0  = (const float*)d_in[5];
    const float* eWih1  = (const float*)d_in[6];
    const float* eWhh1  = (const float*)d_in[7];
    const float* ebih1  = (const float*)d_in[8];
    const float* ebhh1  = (const float*)d_in[9];
    const float* e2d_W  = (const float*)d_in[10];
    const float* e2d_b  = (const float*)d_in[11];
    const float* dWih0  = (const float*)d_in[12];
    const float* dWih1  = (const float*)d_in[13];
    const float* dWhh   = (const float*)d_in[14];
    const float* dbih   = (const float*)d_in[15];
    const float* dbhh   = (const float*)d_in[16];
    const float* q_W    = (const float*)d_in[17];
    const float* q_b    = (const float*)d_in[18];
    const float* out_W  = (const float*)d_in[19];
    const float* out_b  = (const float*)d_in[20];
    const float* emb    = (const float*)d_in[21];
    float* out = (float*)d_out;

    static int smem_set = 0;
    if (!smem_set){
        cudaFuncSetAttribute(enc_cluster_kernel<0>, cudaFuncAttributeMaxDynamicSharedMemorySize, SMEM_ENC);
        cudaFuncSetAttribute(enc_cluster_kernel<1>, cudaFuncAttributeMaxDynamicSharedMemorySize, SMEM_ENC);
        smem_set = 1;
    }

    float* gy0 = nullptr; cudaGetSymbolAddress((void**)&gy0, g_y0);
    float* gy1 = nullptr; cudaGetSymbolAddress((void**)&gy1, g_y1);
    float* ggi = nullptr; cudaGetSymbolAddress((void**)&ggi, g_gi1);
    float* gen = nullptr; cudaGetSymbolAddress((void**)&gen, g_enc);
    float* gh0 = nullptr; cudaGetSymbolAddress((void**)&gh0, g_h0);
    float* gh1 = nullptr; cudaGetSymbolAddress((void**)&gh1, g_h1);

    prep_kernel<<<148, 256>>>(dWhh, dWih1, q_W, dWih0);

    enc_cluster_kernel<0><<<128, 192, SMEM_ENC>>>(x, eWih0, eWhh0, ebih0, ebhh0, nullptr, gy0, gh0);

    dim3 gGI(BSZ*TT/BM, GG/BN);
    gemm_bt<<<gGI, 256>>>(gy0, eWih1,         ebih1,     ggi,                    BSZ*TT, GG, 2*HH);
    gemm_bt<<<gGI, 256>>>(gy0, eWih1+GG*2*HH, ebih1+GG,  ggi+(size_t)BSZ*TT*GG,  BSZ*TT, GG, 2*HH);

    enc_cluster_kernel<1><<<128, 192, SMEM_ENC>>>(nullptr, nullptr, eWhh1, ebih1, ebhh1, ggi, gy1, gh1);

    dim3 gED(BSZ*TT/BM, HH/BN);
    gemm_bt<<<gED, 256>>>(gy1, e2d_W, e2d_b, gen, BSZ*TT, HH, 2*HH);

    dec_kernel<<<64, 256>>>(tseq, dbih, dbhh, q_b, out_b, emb, out_W, out);
}

// round 17
// speedup vs baseline: 2.5136x; 1.0222x over previous
#include <cuda_runtime.h>
#include <math.h>
#include <stdint.h>
#include <string.h>

#define BSZ 128
#define TT  512
#define HH  256
#define GG  768
#define VOC 29
#define EMBD 8
#define DECS 63
#define KK4 64
#define LOGITS_SZ (BSZ*DECS*VOC)

// encoder cluster kernel smem layout (floats)
#define SM_WS    0
#define SM_HS    49152
#define SM_PA    (SM_HS+4096)
#define SM_WIH   (SM_PA+1728)
#define SM_BIS   (SM_WIH+384)
#define SM_BHS   (SM_BIS+192)
#define SM_XS    (SM_BHS+192)
#define SM_TOTF  (SM_XS+16)
#define SMEM_ENC (SM_TOTF*4)

// ---------------- packed fp32 FMA ----------------
__device__ __forceinline__ float2 ffma2(float2 a, float2 b, float2 c){
    unsigned long long au, bu, cu, ru;
    memcpy(&au, &a, 8); memcpy(&bu, &b, 8); memcpy(&cu, &c, 8);
    asm("fma.rn.f32x2 %0, %1, %2, %3;" : "=l"(ru) : "l"(au), "l"(bu), "l"(cu));
    float2 r; memcpy(&r, &ru, 8);
    return r;
}

__device__ __forceinline__ uint32_t smem_u32(const void* p){
    uint32_t a;
    asm("{ .reg .u64 t; cvta.to.shared.u64 t, %1; cvt.u32.u64 %0, t; }" : "=r"(a) : "l"(p));
    return a;
}
__device__ __forceinline__ void st_cluster_f32(uint32_t laddr, uint32_t peer, float v){
    uint32_t r;
    asm volatile("mapa.shared::cluster.u32 %0, %1, %2;" : "=r"(r) : "r"(laddr), "r"(peer));
    asm volatile("st.shared::cluster.f32 [%0], %1;" :: "r"(r), "f"(v) : "memory");
}
#define CLUSTER_SYNC() do { \
    asm volatile("barrier.cluster.arrive.aligned;" ::: "memory"); \
    asm volatile("barrier.cluster.wait.aligned;" ::: "memory"); } while(0)

// ---------------- device scratch ----------------
__device__ float  g_y0 [(size_t)BSZ*TT*2*HH];
__device__ float  g_y1 [(size_t)BSZ*TT*2*HH];
__device__ float  g_gi1[(size_t)2*BSZ*TT*GG];
__device__ float  g_enc[(size_t)BSZ*TT*HH];
__device__ float  g_h0 [2*BSZ*HH];
__device__ float  g_h1 [2*BSZ*HH];
__device__ float4 g_dWhhQ [2*KK4*GG];
__device__ float4 g_dWih1Q[KK4*GG];
__device__ float4 g_qWQ   [KK4*HH];
__device__ float  g_dWih0T[EMBD*GG];

__device__ __forceinline__ float sigf(float v){ return 1.0f/(1.0f+expf(-v)); }

// ---------------- weight packing (decoder only) ----------------
__global__ void prep_kernel(const float* __restrict__ dWhh,  const float* __restrict__ dWih1,
                            const float* __restrict__ qW,    const float* __restrict__ dWih0)
{
    const int NW = 2*KK4*GG;
    const int NI = KK4*GG;
    const int NQ = KK4*HH;
    const int NT = EMBD*GG;
    const int TOT = NW + NI + NQ + NT;
    for (int i = blockIdx.x*blockDim.x + threadIdx.x; i < TOT; i += gridDim.x*blockDim.x){
        int idx = i;
        if (idx < NW){
            int d = idx/(KK4*GG), rem = idx%(KK4*GG);
            int kk = rem/GG, row = rem%GG;
            g_dWhhQ[idx] = *(const float4*)&dWhh[(size_t)(d*GG+row)*HH + 4*kk];
            continue;
        }
        idx -= NW;
        if (idx < NI){
            int kk = idx/GG, row = idx%GG;
            g_dWih1Q[idx] = *(const float4*)&dWih1[(size_t)row*HH + 4*kk];
            continue;
        }
        idx -= NI;
        if (idx < NQ){
            int kk = idx/HH, o = idx%HH;
            g_qWQ[idx] = *(const float4*)&qW[(size_t)o*HH + 4*kk];
            continue;
        }
        idx -= NQ;
        {
            int k = idx/GG, j3 = idx%GG;
            g_dWih0T[idx] = dWih0[(size_t)j3*EMBD + k];
        }
    }
}

// ---------------- clustered encoder layer ----------------
template<int LAYER>
__global__ __cluster_dims__(4,1,1) __launch_bounds__(192,1)
void enc_cluster_kernel(const float* __restrict__ x,   const float* __restrict__ Wih,
                        const float* __restrict__ Whh, const float* __restrict__ bih,
                        const float* __restrict__ bhh, const float* __restrict__ gi_g,
                        float* __restrict__ y_out,     float* __restrict__ h_out)
{
    extern __shared__ float sm[];
    float* Ws   = sm + SM_WS;
    float* hs   = sm + SM_HS;
    float* pa   = sm + SM_PA;
    float* wihs = sm + SM_WIH;
    float* bis  = sm + SM_BIS;
    float* bhs  = sm + SM_BHS;
    float* xs   = sm + SM_XS;

    const int t = threadIdx.x;
    uint32_t rank; asm("mov.u32 %0, %%cluster_ctarank;" : "=r"(rank));
    const int cid = blockIdx.x >> 2;
    const int dir = cid >> 4;
    const int grp = cid & 15;
    const int b0  = grp*8;
    const int g   = t >> 6;
    const int jj  = t & 63;
    const int grow = g*HH + (int)rank*64 + jj;

    const float* __restrict__ GI = (LAYER == 1) ? (gi_g + (size_t)dir*BSZ*TT*GG) : gi_g;

    const float* Wsrc = Whh + (size_t)dir*GG*HH;
    for (int i = t; i < 192*64; i += 192){
        int srow = i >> 6, kk = i & 63;
        int gr = (srow>>6)*HH + (int)rank*64 + (srow&63);
        float4 v = *(const float4*)&Wsrc[(size_t)gr*HH + 4*kk];
        *(float4*)&Ws[(size_t)(kk*192 + srow)*4] = v;
    }
    bhs[t] = bhh[dir*GG + grow];
    if (LAYER == 0){
        bis[t] = bih[dir*GG + grow];
        wihs[t*2+0] = Wih[(size_t)(dir*GG + grow)*2 + 0];
        wihs[t*2+1] = Wih[(size_t)(dir*GG + grow)*2 + 1];
    }
    for (int i = t; i < 8*HH; i += 192) hs[i] = 0.0f;
    __syncthreads();
    CLUSTER_SYNC();

    const uint32_t hs_base = smem_u32(hs);
    int cur = 0;
    for (int s = 0; s < TT; s++){
        const int tt_ = dir ? (TT-1-s) : s;

        float gipre[3][3];
        if (LAYER == 0){
            if (t < 16){ int r = t>>1, c2 = t&1; xs[t] = x[((size_t)(b0+r)*TT + tt_)*2 + c2]; }
        } else {
#pragma unroll
            for (int a = 0; a < 3; a++){
                int task = t + a*192;
                if (task < 512){
                    int j2 = task & 63, r2 = task >> 6;
                    const float* gp = GI + ((size_t)(b0+r2)*TT + tt_)*GG + (int)rank*64 + j2;
                    gipre[a][0] = gp[0]; gipre[a][1] = gp[HH]; gipre[a][2] = gp[2*HH];
                }
            }
        }

        float2 acc[8];
#pragma unroll
        for (int r = 0; r < 8; r++) acc[r] = make_float2(0.f,0.f);
        const float* hb = hs + cur*8*HH;
#pragma unroll 8
        for (int kk = 0; kk < 64; kk++){
            float4 w = *(const float4*)&Ws[(size_t)(kk*192 + t)*4];
#pragma unroll
            for (int r = 0; r < 8; r++){
                float4 h4 = *(const float4*)&hb[r*HH + 4*kk];
                acc[r] = ffma2(make_float2(w.x,w.y), make_float2(h4.x,h4.y), acc[r]);
                acc[r] = ffma2(make_float2(w.z,w.w), make_float2(h4.z,h4.w), acc[r]);
            }
        }
#pragma unroll
        for (int r = 0; r < 8; r++) pa[t*9 + r] = acc[r].x + acc[r].y;
        __syncthreads();

        float* hnxt = hs + (cur^1)*8*HH;
        const uint32_t hnxt_u = hs_base + (uint32_t)((cur^1)*8*HH)*4u;
#pragma unroll
        for (int a = 0; a < 3; a++){
            int task = t + a*192;
            if (task < 512){
                int j2 = task & 63, r2 = task >> 6;
                float aRr = pa[(j2      )*9 + r2];
                float aZz = pa[(64 + j2 )*9 + r2];
                float aNn = pa[(128 + j2)*9 + r2];
                float giR, giZ, giN;
                if (LAYER == 0){
                    float x0 = xs[r2*2], x1 = xs[r2*2+1];
                    giR = bis[j2]      + wihs[(j2      )*2]*x0 + wihs[(j2      )*2+1]*x1;
                    giZ = bis[64+j2]   + wihs[(64+j2   )*2]*x0 + wihs[(64+j2   )*2+1]*x1;
                    giN = bis[128+j2]  + wihs[(128+j2  )*2]*x0 + wihs[(128+j2  )*2+1]*x1;
                } else {
                    giR = gipre[a][0]; giZ = gipre[a][1]; giN = gipre[a][2];
                }
                float rg = sigf(giR + bhs[j2]      + aRr);
                float zg = sigf(giZ + bhs[64+j2]   + aZz);
                float ng = tanhf(giN + rg*(bhs[128+j2] + aNn));
                int off = r2*HH + (int)rank*64 + j2;
                float hold = hb[off];
                float hn = (1.0f - zg)*ng + zg*hold;
                hnxt[off] = hn;
                uint32_t laddr = hnxt_u + (uint32_t)off*4u;
#pragma unroll
                for (uint32_t p = 0; p < 4; p++){
                    if (p != rank) st_cluster_f32(laddr, p, hn);
                }
                y_out[((size_t)(b0+r2)*TT + tt_)*(2*HH) + dir*HH + (int)rank*64 + j2] = hn;
            }
        }
        CLUSTER_SYNC();
        cur ^= 1;
    }

    const float* hf = hs + cur*8*HH;
#pragma unroll
    for (int a = 0; a < 3; a++){
        int task = t + a*192;
        if (task < 512){
            int j2 = task & 63, r2 = task >> 6;
            h_out[dir*BSZ*HH + (b0+r2)*HH + (int)rank*64 + j2] = hf[r2*HH + (int)rank*64 + j2];
        }
    }
}

// ---------------- double-buffered tiled SGEMM (f32x2, strided microtile) ----------------
// gridDim.z selects an offset set (for merged per-direction GEMMs).
#define BM 128
#define BN 128
#define BK 16
__global__ __launch_bounds__(256,2) void gemm_bt(const float* __restrict__ A, const float* __restrict__ Bm,
        const float* __restrict__ bias, float* __restrict__ C, int M, int N, int K,
        size_t bStride, size_t biasStride, size_t cStride)
{
    const int z = blockIdx.z;
    Bm   += (size_t)z * bStride;
    bias += (size_t)z * biasStride;
    C    += (size_t)z * cStride;

    __shared__ __align__(16) float  As[2][BK][BM];
    __shared__ __align__(16) float2 Bs[2][BK][BN];
    const int bm  = blockIdx.x * BM;
    const int bn  = blockIdx.y * BN;
    const int tid = threadIdx.x;
    const int lr  = tid >> 2;
    const int lc  = (tid & 3) * 4;
    const int ty  = tid >> 4;
    const int tx  = tid & 15;

    float2 acc[4][8];
#pragma unroll
    for (int p = 0; p < 4; p++)
#pragma unroll
        for (int q = 0; q < 8; q++) acc[p][q] = make_float2(0.f,0.f);

#pragma unroll
    for (int i = 0; i < 2; i++){
        int r = lr + i*64;
        float4 av = *(const float4*)&A[(size_t)(bm+r)*K + lc];
        As[0][lc+0][r] = av.x; As[0][lc+1][r] = av.y; As[0][lc+2][r] = av.z; As[0][lc+3][r] = av.w;
        float4 bv = *(const float4*)&Bm[(size_t)(bn+r)*K + lc];
        Bs[0][lc+0][r] = make_float2(bv.x,bv.x);
        Bs[0][lc+1][r] = make_float2(bv.y,bv.y);
        Bs[0][lc+2][r] = make_float2(bv.z,bv.z);
        Bs[0][lc+3][r] = make_float2(bv.w,bv.w);
    }
    __syncthreads();

    const int NTILE = K / BK;
    for (int kt = 0; kt < NTILE; kt++){
        const int cur = kt & 1, nxt = cur ^ 1;

        float4 avn[2], bvn[2];
        const bool has_next = (kt + 1 < NTILE);
        if (has_next){
            int k0 = (kt + 1) * BK;
#pragma unroll
            for (int i = 0; i < 2; i++){
                int r = lr + i*64;
                avn[i] = *(const float4*)&A[(size_t)(bm+r)*K + k0 + lc];
                bvn[i] = *(const float4*)&Bm[(size_t)(bn+r)*K + k0 + lc];
            }
        }

#pragma unroll
        for (int k = 0; k < BK; k++){
            float2 a2[4], b2[8];
#pragma unroll
            for (int p = 0; p < 4; p++)
                a2[p] = *(const float2*)&As[cur][k][2*(ty + p*16)];
#pragma unroll
            for (int q = 0; q < 8; q++)
                b2[q] = Bs[cur][k][q*16 + tx];
#pragma unroll
            for (int p = 0; p < 4; p++)
#pragma unroll
                for (int q = 0; q < 8; q++) acc[p][q] = ffma2(a2[p], b2[q], acc[p][q]);
        }

        if (has_next){
#pragma unroll
            for (int i = 0; i < 2; i++){
                int r = lr + i*64;
                As[nxt][lc+0][r] = avn[i].x; As[nxt][lc+1][r] = avn[i].y;
                As[nxt][lc+2][r] = avn[i].z; As[nxt][lc+3][r] = avn[i].w;
                Bs[nxt][lc+0][r] = make_float2(bvn[i].x,bvn[i].x);
                Bs[nxt][lc+1][r] = make_float2(bvn[i].y,bvn[i].y);
                Bs[nxt][lc+2][r] = make_float2(bvn[i].z,bvn[i].z);
                Bs[nxt][lc+3][r] = make_float2(bvn[i].w,bvn[i].w);
            }
        }
        __syncthreads();
    }

#pragma unroll
    for (int p = 0; p < 4; p++){
        int m0 = bm + 2*(ty + p*16);
#pragma unroll
        for (int q = 0; q < 8; q++){
            int n = bn + q*16 + tx;
            float bv = bias[n];
            C[(size_t)m0*N + n]     = acc[p][q].x + bv;
            C[(size_t)(m0+1)*N + n] = acc[p][q].y + bv;
        }
    }
}

// ---------------- decoder: 128 blocks x 1 row ----------------
__global__ __launch_bounds__(256) void dec_kernel(
        const int*   __restrict__ tseq, const float* __restrict__ dbih, const float* __restrict__ dbhh,
        const float* __restrict__ qb,   const float* __restrict__ outb, const float* __restrict__ emb,
        const float* __restrict__ outW, float* __restrict__ out)
{
    const int j  = threadIdx.x;
    const int b  = blockIdx.x;
    const int warp = j >> 5, lane = j & 31;

    __shared__ __align__(16) float h0s[HH];
    __shared__ __align__(16) float h1s[HH];
    __shared__ __align__(16) float qs[HH];
    __shared__ float cx[HH];
    __shared__ float ws[TT];
    __shared__ float es[EMBD];
    __shared__ float ls[32];
    __shared__ float buf[256];
    __shared__ float mred, invs;
    __shared__ int   tok;

    h0s[j] = g_h0[b*HH + j] + g_h0[BSZ*HH + b*HH + j];
    h1s[j] = g_h1[b*HH + j] + g_h1[BSZ*HH + b*HH + j];
    if (j == 0) tok = tseq[(size_t)b*64];
    __syncthreads();

    float bi0[3], bh0[3], bi1[3], bh1[3];
#pragma unroll
    for (int g = 0; g < 3; g++){
        bi0[g] = dbih[g*HH + j];        bh0[g] = dbhh[g*HH + j];
        bi1[g] = dbih[GG + g*HH + j];   bh1[g] = dbhh[GG + g*HH + j];
    }
    const float qbias = qb[j];

    for (int s = 0; s < DECS; s++){
        if (j < EMBD) es[j] = emb[(size_t)tok*EMBD + j];
        __syncthreads();

        // ---- GRU cell 0 ----
        float giR = bi0[0], giZ = bi0[1], giN = bi0[2];
        float2 aR2 = make_float2(0.f,0.f), aZ2 = make_float2(0.f,0.f), aN2 = make_float2(0.f,0.f);
#pragma unroll
        for (int k = 0; k < EMBD; k++){
            float e = es[k];
            giR += g_dWih0T[k*GG + j]*e;
            giZ += g_dWih0T[k*GG + HH + j]*e;
            giN += g_dWih0T[k*GG + 2*HH + j]*e;
        }
#pragma unroll 4
        for (int kk = 0; kk < KK4; kk++){
            float4 w0 = g_dWhhQ[kk*GG + j];
            float4 w1 = g_dWhhQ[kk*GG + HH + j];
            float4 w2 = g_dWhhQ[kk*GG + 2*HH + j];
            float4 h4 = *(const float4*)&h0s[4*kk];
            aR2 = ffma2(make_float2(w0.x,w0.y), make_float2(h4.x,h4.y), aR2);
            aR2 = ffma2(make_float2(w0.z,w0.w), make_float2(h4.z,h4.w), aR2);
            aZ2 = ffma2(make_float2(w1.x,w1.y), make_float2(h4.x,h4.y), aZ2);
            aZ2 = ffma2(make_float2(w1.z,w1.w), make_float2(h4.z,h4.w), aZ2);
            aN2 = ffma2(make_float2(w2.x,w2.y), make_float2(h4.x,h4.y), aN2);
            aN2 = ffma2(make_float2(w2.z,w2.w), make_float2(h4.z,h4.w), aN2);
        }
        float h0n;
        {
            float hold = h0s[j];
            float rg = sigf(giR + bh0[0] + aR2.x + aR2.y);
            float zg = sigf(giZ + bh0[1] + aZ2.x + aZ2.y);
            float ng = tanhf(giN + rg*(bh0[2] + aN2.x + aN2.y));
            h0n = (1.0f - zg)*ng + zg*hold;
        }
        __syncthreads();
        h0s[j] = h0n;
        __syncthreads();

        // ---- GRU cell 1 (input = h0) ----
        float2 gR2 = make_float2(0.f,0.f), gZ2 = make_float2(0.f,0.f), gN2 = make_float2(0.f,0.f);
        aR2 = make_float2(0.f,0.f); aZ2 = make_float2(0.f,0.f); aN2 = make_float2(0.f,0.f);
#pragma unroll 4
        for (int kk = 0; kk < KK4; kk++){
            float4 u0 = g_dWih1Q[kk*GG + j];
            float4 u1 = g_dWih1Q[kk*GG + HH + j];
            float4 u2 = g_dWih1Q[kk*GG + 2*HH + j];
            float4 w0 = g_dWhhQ[KK4*GG + kk*GG + j];
            float4 w1 = g_dWhhQ[KK4*GG + kk*GG + HH + j];
            float4 w2 = g_dWhhQ[KK4*GG + kk*GG + 2*HH + j];
            float4 x4 = *(const float4*)&h0s[4*kk];
            float4 h4 = *(const float4*)&h1s[4*kk];
            gR2 = ffma2(make_float2(u0.x,u0.y), make_float2(x4.x,x4.y), gR2);
            gR2 = ffma2(make_float2(u0.z,u0.w), make_float2(x4.z,x4.w), gR2);
            gZ2 = ffma2(make_float2(u1.x,u1.y), make_float2(x4.x,x4.y), gZ2);
            gZ2 = ffma2(make_float2(u1.z,u1.w), make_float2(x4.z,x4.w), gZ2);
            gN2 = ffma2(make_float2(u2.x,u2.y), make_float2(x4.x,x4.y), gN2);
            gN2 = ffma2(make_float2(u2.z,u2.w), make_float2(x4.z,x4.w), gN2);
            aR2 = ffma2(make_float2(w0.x,w0.y), make_float2(h4.x,h4.y), aR2);
            aR2 = ffma2(make_float2(w0.z,w0.w), make_float2(h4.z,h4.w), aR2);
            aZ2 = ffma2(make_float2(w1.x,w1.y), make_float2(h4.x,h4.y), aZ2);
            aZ2 = ffma2(make_float2(w1.z,w1.w), make_float2(h4.z,h4.w), aZ2);
            aN2 = ffma2(make_float2(w2.x,w2.y), make_float2(h4.x,h4.y), aN2);
            aN2 = ffma2(make_float2(w2.z,w2.w), make_float2(h4.z,h4.w), aN2);
        }
        float h1n;
        {
            float hold = h1s[j];
            float rg = sigf(bi1[0] + gR2.x + gR2.y + bh1[0] + aR2.x + aR2.y);
            float zg = sigf(bi1[1] + gZ2.x + gZ2.y + bh1[1] + aZ2.x + aZ2.y);
            float ng = tanhf(bi1[2] + gN2.x + gN2.y + rg*(bh1[2] + aN2.x + aN2.y));
            h1n = (1.0f - zg)*ng + zg*hold;
        }
        __syncthreads();
        h1s[j] = h1n;
        __syncthreads();

        // ---- q = h1 @ qW^T + qb ----
        {
            float2 q2 = make_float2(0.f,0.f);
#pragma unroll 4
            for (int kk = 0; kk < KK4; kk++){
                float4 w = g_qWQ[kk*HH + j];
                float4 a = *(const float4*)&h1s[4*kk];
                q2 = ffma2(make_float2(w.x,w.y), make_float2(a.x,a.y), q2);
                q2 = ffma2(make_float2(w.z,w.w), make_float2(a.z,a.w), q2);
            }
            qs[j] = qbias + q2.x + q2.y;
        }
        __syncthreads();

        // ---- scores ----
        for (int tt = warp; tt < TT/2; tt += 8){
#pragma unroll
            for (int half = 0; half < 2; half++){
                int t = tt + half*(TT/2);
                const float* ep = g_enc + ((size_t)b*TT + t)*HH + lane*8;
                float4 e0 = *(const float4*)(ep);
                float4 e1 = *(const float4*)(ep+4);
                const float* qp = &qs[lane*8];
                float2 qa = *(const float2*)(qp);
                float2 qb2 = *(const float2*)(qp+2);
                float2 qc = *(const float2*)(qp+4);
                float2 qd = *(const float2*)(qp+6);
                float2 acc2 = make_float2(0.f,0.f);
                acc2 = ffma2(make_float2(e0.x,e0.y), qa, acc2);
                acc2 = ffma2(make_float2(e0.z,e0.w), qb2, acc2);
                acc2 = ffma2(make_float2(e1.x,e1.y), qc, acc2);
                acc2 = ffma2(make_float2(e1.z,e1.w), qd, acc2);
                float acc = acc2.x + acc2.y;
#pragma unroll
                for (int o = 16; o > 0; o >>= 1) acc += __shfl_xor_sync(0xffffffffu, acc, o);
                if (lane == 0) ws[t] = acc;
            }
        }
        __syncthreads();

        // ---- softmax ----
        {
            buf[j] = fmaxf(ws[j], ws[j+256]);
            __syncthreads();
            for (int o = 128; o > 0; o >>= 1){
                if (j < o) buf[j] = fmaxf(buf[j], buf[j+o]);
                __syncthreads();
            }
            if (j == 0) mred = buf[0];
            __syncthreads();
            float m = mred;
            float e0 = expf(ws[j] - m), e1 = expf(ws[j+256] - m);
            ws[j] = e0; ws[j+256] = e1;
            buf[j] = e0 + e1;
            __syncthreads();
            for (int o = 128; o > 0; o >>= 1){
                if (j < o) buf[j] += buf[j+o];
                __syncthreads();
            }
            if (j == 0) invs = 1.0f/buf[0];
            __syncthreads();
        }

        // ---- ctx ----
        {
            float c0a=0.f,c0b=0.f,c0c=0.f,c0d=0.f;
            const float* e0p = g_enc + (size_t)b*TT*HH + j;
#pragma unroll 4
            for (int t = 0; t < TT; t += 4){
                c0a += ws[t  ]*e0p[(size_t)(t  )*HH];
                c0b += ws[t+1]*e0p[(size_t)(t+1)*HH];
                c0c += ws[t+2]*e0p[(size_t)(t+2)*HH];
                c0d += ws[t+3]*e0p[(size_t)(t+3)*HH];
            }
            cx[j] = ((c0a+c0b)+(c0c+c0d))*invs + h1s[j];
        }
        __syncthreads();

        // ---- logits + write ----
        for (int v = warp; v < VOC; v += 8){
            const float* wp = outW + (size_t)v*HH + lane*8;
            float4 w0 = *(const float4*)(wp);
            float4 w1 = *(const float4*)(wp+4);
            const float* hp = &cx[lane*8];
            float acc = w0.x*hp[0] + w0.y*hp[1] + w0.z*hp[2] + w0.w*hp[3]
                      + w1.x*hp[4] + w1.y*hp[5] + w1.z*hp[6] + w1.w*hp[7];
#pragma unroll
            for (int o = 16; o > 0; o >>= 1) acc += __shfl_xor_sync(0xffffffffu, acc, o);
            if (lane == 0){
                float lv = acc + outb[v];
                ls[v] = lv;
                out[((size_t)b*DECS + s)*VOC + v] = lv;
            }
        }
        __syncthreads();

        // ---- argmax feedback ----
        if (j == 0){
            float best = ls[0]; int bi = 0;
#pragma unroll
            for (int v = 1; v < VOC; v++){
                float lv = ls[v];
                if (lv > best){ best = lv; bi = v; }
            }
            tok = bi;
        }
        __syncthreads();
    }

    // ---- final hidden ----
    out[LOGITS_SZ + (size_t)b*HH + j]                 = h0s[j];
    out[LOGITS_SZ + (size_t)BSZ*HH + (size_t)b*HH + j] = h1s[j];
}

// ---------------- launch ----------------
extern "C" void kernel_launch(void* const* d_in, const int* in_sizes, int n_in,
                              void* d_out, int out_size)
{
    const float* x      = (const float*)d_in[0];
    const int*   tseq   = (const int*)  d_in[1];
    const float* eWih0  = (const float*)d_in[2];
    const float* eWhh0  = (const float*)d_in[3];
    const float* ebih0  = (const float*)d_in[4];
    const float* ebhh0  = (const float*)d_in[5];
    const float* eWih1  = (const float*)d_in[6];
    const float* eWhh1  = (const float*)d_in[7];
    const float* ebih1  = (const float*)d_in[8];
    const float* ebhh1  = (const float*)d_in[9];
    const float* e2d_W  = (const float*)d_in[10];
    const float* e2d_b  = (const float*)d_in[11];
    const float* dWih0  = (const float*)d_in[12];
    const float* dWih1  = (const float*)d_in[13];
    const float* dWhh   = (const float*)d_in[14];
    const float* dbih   = (const float*)d_in[15];
    const float* dbhh   = (const float*)d_in[16];
    const float* q_W    = (const float*)d_in[17];
    const float* q_b    = (const float*)d_in[18];
    const float* out_W  = (const float*)d_in[19];
    const float* out_b  = (const float*)d_in[20];
    const float* emb    = (const float*)d_in[21];
    float* out = (float*)d_out;

    static int smem_set = 0;
    if (!smem_set){
        cudaFuncSetAttribute(enc_cluster_kernel<0>, cudaFuncAttributeMaxDynamicSharedMemorySize, SMEM_ENC);
        cudaFuncSetAttribute(enc_cluster_kernel<1>, cudaFuncAttributeMaxDynamicSharedMemorySize, SMEM_ENC);
        smem_set = 1;
    }

    float* gy0 = nullptr; cudaGetSymbolAddress((void**)&gy0, g_y0);
    float* gy1 = nullptr; cudaGetSymbolAddress((void**)&gy1, g_y1);
    float* ggi = nullptr; cudaGetSymbolAddress((void**)&ggi, g_gi1);
    float* gen = nullptr; cudaGetSymbolAddress((void**)&gen, g_enc);
    float* gh0 = nullptr; cudaGetSymbolAddress((void**)&gh0, g_h0);
    float* gh1 = nullptr; cudaGetSymbolAddress((void**)&gh1, g_h1);

    prep_kernel<<<148, 256>>>(dWhh, dWih1, q_W, dWih0);

    enc_cluster_kernel<0><<<128, 192, SMEM_ENC>>>(x, eWih0, eWhh0, ebih0, ebhh0, nullptr, gy0, gh0);

    // merged gi GEMM: z = direction
    dim3 gGI(BSZ*TT/BM, GG/BN, 2);
    gemm_bt<<<gGI, 256>>>(gy0, eWih1, ebih1, ggi, BSZ*TT, GG, 2*HH,
                          (size_t)GG*2*HH, (size_t)GG, (size_t)BSZ*TT*GG);

    enc_cluster_kernel<1><<<128, 192, SMEM_ENC>>>(nullptr, nullptr, eWhh1, ebih1, ebhh1, ggi, gy1, gh1);

    dim3 gED(BSZ*TT/BM, HH/BN, 1);
    gemm_bt<<<gED, 256>>>(gy1, e2d_W, e2d_b, gen, BSZ*TT, HH, 2*HH, 0, 0, 0);

    dec_kernel<<<128, 256>>>(tseq, dbih, dbhh, q_b, out_b, emb, out_W, out);
}